// round 12
// baseline (speedup 1.0000x reference)
#include <cuda_runtime.h>
#include <cuda_bf16.h>
#include <math.h>
#include <stdint.h>

#define NTOK   8192
#define DMODEL 512
#define HEADS  8
#define HD     64
#define SEQ    1024
#define FFDIM  2048
#define NSLOTS 512
#define OUTD   32
#define QKVN   1536
#define HEADN  16896
#define NEGF   (-3.4028234663852886e38f)

// ---------------- static scratch ----------------
__device__ float g_dec [NTOK * DMODEL];
__device__ float g_tmp2[NTOK * DMODEL];
__device__ float g_ctx [NTOK * 1024];
__device__ float g_vs  [(size_t)NTOK * NSLOTS * OUTD];
__device__ float g_bcomb[HEADN];
__device__ unsigned long long g_best[NTOK];
__device__ __nv_bfloat16 g_dech[NTOK * DMODEL], g_decl[NTOK * DMODEL];
__device__ __nv_bfloat16 g_qkvh[NTOK * QKVN],  g_qkvl[NTOK * QKVN];
__device__ __nv_bfloat16 g_obh [NTOK * DMODEL], g_obl [NTOK * DMODEL];
__device__ __nv_bfloat16 g_th  [NTOK * DMODEL], g_tl  [NTOK * DMODEL];
__device__ __nv_bfloat16 g_ffh [NTOK * FFDIM],  g_ffl [NTOK * FFDIM];
__device__ __nv_bfloat16 g_keysh[NTOK * DMODEL], g_keysl[NTOK * DMODEL];
__device__ __nv_bfloat16 g_vthi[64 * HD * SEQ], g_vtlo[64 * HD * SEQ];
__device__ __nv_bfloat16 g_bthi[(size_t)DMODEL * HEADN], g_btlo[(size_t)DMODEL * HEADN];
__device__ __nv_bfloat16 g_xbth[1024 * DMODEL], g_xbtl[1024 * DMODEL];
__device__ __nv_bfloat16 g_cvh[2 * DMODEL * DMODEL], g_cvl[2 * DMODEL * DMODEL];

__device__ __forceinline__ uint32_t smem_u32(const void* p) {
    uint32_t a;
    asm("{ .reg .u64 t; cvta.to.shared.u64 t, %1; cvt.u32.u64 %0, t; }" : "=r"(a) : "l"(p));
    return a;
}
__device__ __forceinline__ uint32_t pack2(__nv_bfloat16 a, __nv_bfloat16 b) {
    return (uint32_t)__bfloat16_as_ushort(a) | ((uint32_t)__bfloat16_as_ushort(b) << 16);
}
__device__ __forceinline__ void cp16(uint32_t dst, const void* src) {
    asm volatile("cp.async.cg.shared.global [%0], [%1], 16;" :: "r"(dst), "l"(src) : "memory");
}
__device__ __forceinline__ void cp_commit() {
    asm volatile("cp.async.commit_group;" ::: "memory");
}
__device__ __forceinline__ void cp_wait0() {
    asm volatile("cp.async.wait_group 0;" ::: "memory");
}
__device__ __forceinline__ void split4(float4 v, uint2& hi, uint2& lo) {
    __nv_bfloat16 hx = __float2bfloat16(v.x), hy = __float2bfloat16(v.y);
    __nv_bfloat16 hz = __float2bfloat16(v.z), hw = __float2bfloat16(v.w);
    __nv_bfloat16 lx = __float2bfloat16(v.x - __bfloat162float(hx));
    __nv_bfloat16 ly = __float2bfloat16(v.y - __bfloat162float(hy));
    __nv_bfloat16 lz = __float2bfloat16(v.z - __bfloat162float(hz));
    __nv_bfloat16 lw = __float2bfloat16(v.w - __bfloat162float(hw));
    hi = make_uint2(pack2(hx, hy), pack2(hz, hw));
    lo = make_uint2(pack2(lx, ly), pack2(lz, lw));
}
__device__ __forceinline__ unsigned long long score_key(float s, int slot) {
    unsigned int u = __float_as_uint(s);
    u = (u & 0x80000000u) ? ~u : (u | 0x80000000u);
    return ((unsigned long long)u << 32) | (unsigned int)(~slot);
}

#define LDMX4(r0, r1, r2, r3, addr) \
    asm volatile("ldmatrix.sync.aligned.m8n8.x4.shared.b16 {%0,%1,%2,%3}, [%4];" \
        : "=r"(r0), "=r"(r1), "=r"(r2), "=r"(r3) : "r"(addr))

#define MMA_BF16(c, a, b) \
    asm volatile("mma.sync.aligned.m16n8k16.row.col.f32.bf16.bf16.f32 " \
        "{%0,%1,%2,%3}, {%4,%5,%6,%7}, {%8,%9}, {%0,%1,%2,%3};" \
        : "+f"((c)[0]), "+f"((c)[1]), "+f"((c)[2]), "+f"((c)[3]) \
        : "r"((a)[0]), "r"((a)[1]), "r"((a)[2]), "r"((a)[3]), "r"((b)[0]), "r"((b)[1]))

#define LDP 72
#define T128 (128 * LDP * 2)
#define T256 (256 * LDP * 2)
#define GB_STAGE (2 * T128 + 2 * T256)
#define GEMM_SMEM (2 * GB_STAGE)
#define FA_LDPV 136
#define FA_VT (64 * FA_LDPV * 2)
#define FA_STAGE (2 * T128 + 2 * FA_VT)
#define FA_SMEM (2 * T128 + 2 * FA_STAGE)

// ============ split-bf16 HMMA GEMM: CTA 128x256, 8 warps of 64x64 =============
// Crossbar-optimized: per ks a warp loads 8 KB of fragments for 96 mmas (85 B/mma).
__global__ __launch_bounds__(256, 1)
void gemm_bb_kernel(const __nv_bfloat16* __restrict__ Ahi, const __nv_bfloat16* __restrict__ Alo,
                    const __nv_bfloat16* __restrict__ Bhi, const __nv_bfloat16* __restrict__ Blo,
                    const float* __restrict__ bias,
                    float* __restrict__ Cf, __nv_bfloat16* __restrict__ Chi,
                    __nv_bfloat16* __restrict__ Clo,
                    int M, int N, int K, int relu,
                    const float* __restrict__ xsc, unsigned long long* __restrict__ best,
                    float* __restrict__ Cf2, int split)
{
    extern __shared__ char smem[];
    const int tid  = threadIdx.x;
    const int lane = tid & 31, wid = tid >> 5;
    const int wm = wid >> 2;             // 0..1 -> 64-row warp tile
    const int wn = wid & 3;              // 0..3 -> 64-col warp tile
    const size_t brow = (size_t)blockIdx.y * 128;
    const size_t bcol = (size_t)blockIdx.x * 256;
    const int seg = tid & 7, r0 = tid >> 3;   // r0: 0..31

    const int NP = K >> 6;

    auto load_panel = [&](int p, int s) {
        char* base = smem + s * GB_STAGE;
        const size_t ka = (size_t)p * 64 + seg * 8;
#pragma unroll
        for (int it = 0; it < 4; it++) {             // A: 128 rows hi/lo
            const int r = r0 + it * 32;
            const uint32_t dst = smem_u32(base + (r * LDP + seg * 8) * 2);
            cp16(dst,        Ahi + (brow + r) * K + ka);
            cp16(dst + T128, Alo + (brow + r) * K + ka);
        }
#pragma unroll
        for (int it = 0; it < 8; it++) {             // B: 256 rows hi/lo
            const int r = r0 + it * 32;
            const uint32_t dst = smem_u32(base + 2 * T128 + (r * LDP + seg * 8) * 2);
            cp16(dst,        Bhi + (bcol + r) * K + ka);
            cp16(dst + T256, Blo + (bcol + r) * K + ka);
        }
        cp_commit();
    };

    load_panel(0, 0);

    float acc[4][8][4];
#pragma unroll
    for (int i = 0; i < 4; i++)
#pragma unroll
        for (int j = 0; j < 8; j++)
#pragma unroll
            for (int c = 0; c < 4; c++) acc[i][j][c] = 0.f;

    const int lm_r = (lane & 7) + ((lane >> 3) & 1) * 8;
    const int lm_c = ((lane >> 4) & 1) * 8;
    const int lb_r = (lane & 7) + ((lane >> 4) & 1) * 8;
    const int lb_c = ((lane >> 3) & 1) * 8;

    for (int p = 0; p < NP; p++) {
        const int s = p & 1;
        cp_wait0();
        __syncthreads();
        if (p + 1 < NP) load_panel(p + 1, s ^ 1);

        const __nv_bfloat16* sAh = (const __nv_bfloat16*)(smem + s * GB_STAGE);
        const __nv_bfloat16* sAl = (const __nv_bfloat16*)((char*)sAh + T128);
        const __nv_bfloat16* sBh = (const __nv_bfloat16*)((char*)sAh + 2 * T128);
        const __nv_bfloat16* sBl = (const __nv_bfloat16*)((char*)sAh + 2 * T128 + T256);

#pragma unroll
        for (int ks = 0; ks < 4; ks++) {
            const int k0 = ks * 16;
            uint32_t Ah[4][4], Al[4][4];
#pragma unroll
            for (int mi = 0; mi < 4; mi++) {
                const int r = wm * 64 + mi * 16 + lm_r;
                LDMX4(Ah[mi][0], Ah[mi][1], Ah[mi][2], Ah[mi][3], smem_u32(sAh + r * LDP + k0 + lm_c));
                LDMX4(Al[mi][0], Al[mi][1], Al[mi][2], Al[mi][3], smem_u32(sAl + r * LDP + k0 + lm_c));
            }
            // two 32-col halves keep live B fragments small
#pragma unroll
            for (int half = 0; half < 2; half++) {
                uint32_t Bh[4][2], Bl[4][2];
#pragma unroll
                for (int nio = 0; nio < 2; nio++) {
                    const int r = wn * 64 + (half * 2 + nio) * 16 + lb_r;
                    LDMX4(Bh[2*nio][0], Bh[2*nio][1], Bh[2*nio+1][0], Bh[2*nio+1][1],
                          smem_u32(sBh + r * LDP + k0 + lb_c));
                    LDMX4(Bl[2*nio][0], Bl[2*nio][1], Bl[2*nio+1][0], Bl[2*nio+1][1],
                          smem_u32(sBl + r * LDP + k0 + lb_c));
                }
                // pass-major: 16 independent accumulators between same-acc reuses
#pragma unroll
                for (int mi = 0; mi < 4; mi++)
#pragma unroll
                    for (int ni = 0; ni < 4; ni++)
                        MMA_BF16(acc[mi][half*4+ni], Ah[mi], Bh[ni]);
#pragma unroll
                for (int mi = 0; mi < 4; mi++)
#pragma unroll
                    for (int ni = 0; ni < 4; ni++)
                        MMA_BF16(acc[mi][half*4+ni], Ah[mi], Bl[ni]);
#pragma unroll
                for (int mi = 0; mi < 4; mi++)
#pragma unroll
                    for (int ni = 0; ni < 4; ni++)
                        MMA_BF16(acc[mi][half*4+ni], Al[mi], Bh[ni]);
            }
        }
    }

    // epilogue
    const int g = lane >> 2, t = lane & 3;
    const int tile_col = (int)bcol + wn * 64;                 // 64-aligned
    const bool lo_region = (split > 0) && (tile_col < split); // split 64-aligned
    const int ldv = (split > 0) ? (N - split) : N;
#pragma unroll
    for (int mi = 0; mi < 4; mi++) {
        const size_t rm = brow + wm * 64 + mi * 16 + g;
#pragma unroll
        for (int half = 0; half < 2; half++) {
            float dA = 0.f, sA2 = 0.f, dB = 0.f, sB2 = 0.f;
#pragma unroll
            for (int ni2 = 0; ni2 < 4; ni2++) {
                const int ni = half * 4 + ni2;
                const size_t cn = tile_col + ni * 8 + 2 * t;
                float b0 = 0.f, b1 = 0.f;
                if (bias) { b0 = bias[cn]; b1 = bias[cn + 1]; }
                float v00 = acc[mi][ni][0] + b0, v01 = acc[mi][ni][1] + b1;
                float v10 = acc[mi][ni][2] + b0, v11 = acc[mi][ni][3] + b1;
                if (relu) {
                    v00 = fmaxf(v00, 0.f); v01 = fmaxf(v01, 0.f);
                    v10 = fmaxf(v10, 0.f); v11 = fmaxf(v11, 0.f);
                }
                if (lo_region) {
                    *(float2*)(Cf2 + rm * split + cn)       = make_float2(v00, v01);
                    *(float2*)(Cf2 + (rm + 8) * split + cn) = make_float2(v10, v11);
                } else if (Cf) {
                    const size_t cv = cn - split;
                    *(float2*)(Cf + rm * ldv + cv)       = make_float2(v00, v01);
                    *(float2*)(Cf + (rm + 8) * ldv + cv) = make_float2(v10, v11);
                }
                if (Chi) {
                    __nv_bfloat16 h00 = __float2bfloat16(v00), h01 = __float2bfloat16(v01);
                    __nv_bfloat16 h10 = __float2bfloat16(v10), h11 = __float2bfloat16(v11);
                    *(uint32_t*)(Chi + rm * N + cn)       = pack2(h00, h01);
                    *(uint32_t*)(Chi + (rm + 8) * N + cn) = pack2(h10, h11);
                    *(uint32_t*)(Clo + rm * N + cn)       =
                        pack2(__float2bfloat16(v00 - __bfloat162float(h00)),
                              __float2bfloat16(v01 - __bfloat162float(h01)));
                    *(uint32_t*)(Clo + (rm + 8) * N + cn) =
                        pack2(__float2bfloat16(v10 - __bfloat162float(h10)),
                              __float2bfloat16(v11 - __bfloat162float(h11)));
                }
                if (xsc && !lo_region) {
                    const int o = ni2 * 8 + 2 * t;        // col within 32-wide slot
                    float xa0 = xsc[rm * OUTD + o],       xa1 = xsc[rm * OUTD + o + 1];
                    float xb0 = xsc[(rm + 8) * OUTD + o], xb1 = xsc[(rm + 8) * OUTD + o + 1];
                    dA += v00 * xa0 + v01 * xa1;  sA2 += v00 * v00 + v01 * v01;
                    dB += v10 * xb0 + v11 * xb1;  sB2 += v10 * v10 + v11 * v11;
                }
            }
            if (xsc && !lo_region) {
#pragma unroll
                for (int m = 1; m <= 2; m <<= 1) {
                    dA  += __shfl_xor_sync(~0u, dA,  m);
                    sA2 += __shfl_xor_sync(~0u, sA2, m);
                    dB  += __shfl_xor_sync(~0u, dB,  m);
                    sB2 += __shfl_xor_sync(~0u, sB2, m);
                }
                if (t == 0) {
                    const int slot = (tile_col + half * 32 - split) >> 5;
                    atomicMax(&best[rm],     score_key(dA * rsqrtf(sA2), slot));
                    atomicMax(&best[rm + 8], score_key(dB * rsqrtf(sB2), slot));
                }
            }
        }
    }
}

// ============ fused flash attention ===========================================
__global__ __launch_bounds__(256, 1)
void flash_attn(const __nv_bfloat16* __restrict__ Qh_, const __nv_bfloat16* __restrict__ Ql_,
                const __nv_bfloat16* __restrict__ Kh_, const __nv_bfloat16* __restrict__ Kl_,
                int ld,
                const __nv_bfloat16* __restrict__ Vth, const __nv_bfloat16* __restrict__ Vtl,
                __nv_bfloat16* __restrict__ Oh, __nv_bfloat16* __restrict__ Ol)
{
    extern __shared__ char smem[];
    const int qt = 7 - blockIdx.x;
    const int bh = blockIdx.y;
    const int b = bh >> 3, h = bh & 7;
    const int tid = threadIdx.x;
    const int lane = tid & 31, wid = tid >> 5;
    const int g = lane >> 2, t = lane & 3;

    auto load_chunk = [&](int kc, int s) {
        char* base = smem + 2 * T128 + s * FA_STAGE;
        {
            const int seg = tid & 7, r0 = tid >> 3;
#pragma unroll
            for (int it = 0; it < 4; it++) {
                const int r = r0 + it * 32;
                const uint32_t dst = smem_u32(base + (r * LDP + seg * 8) * 2);
                const size_t off = ((size_t)(b * SEQ + kc * 128 + r) * ld) + h * HD + seg * 8;
                cp16(dst,        Kh_ + off);
                cp16(dst + T128, Kl_ + off);
            }
        }
        {
            const int seg = tid & 15, r0 = tid >> 4;
#pragma unroll
            for (int it = 0; it < 4; it++) {
                const int r = r0 + it * 16;
                const uint32_t dst = smem_u32(base + 2 * T128 + (r * FA_LDPV + seg * 8) * 2);
                const size_t off = ((size_t)bh * HD + r) * SEQ + kc * 128 + seg * 8;
                cp16(dst,         Vth + off);
                cp16(dst + FA_VT, Vtl + off);
            }
        }
        cp_commit();
    };

    {
        const int seg = tid & 7, r0 = tid >> 3;
#pragma unroll
        for (int it = 0; it < 4; it++) {
            const int r = r0 + it * 32;
            const uint32_t dst = smem_u32(smem + (r * LDP + seg * 8) * 2);
            const size_t off = ((size_t)(b * SEQ + qt * 128 + r) * ld) + h * HD + seg * 8;
            cp16(dst,        Qh_ + off);
            cp16(dst + T128, Ql_ + off);
        }
    }
    load_chunk(0, 0);

    const int lm_r = (lane & 7) + ((lane >> 3) & 1) * 8;
    const int lm_c = ((lane >> 4) & 1) * 8;
    const int lb_r = (lane & 7) + ((lane >> 4) & 1) * 8;
    const int lb_c = ((lane >> 3) & 1) * 8;

    uint32_t Qh[4][4], Ql[4][4];
    float o[8][4];
#pragma unroll
    for (int i = 0; i < 8; i++)
#pragma unroll
        for (int c = 0; c < 4; c++) o[i][c] = 0.f;
    float m0 = -INFINITY, m1 = -INFINITY, l0 = 0.f, l1 = 0.f;
    const int row0 = qt * 128 + wid * 16 + g;
    const int row1 = row0 + 8;

    for (int kc = 0; kc <= qt; kc++) {
        const int s = kc & 1;
        cp_wait0();
        __syncthreads();
        if (kc == 0) {
            const __nv_bfloat16* sQh = (const __nv_bfloat16*)smem;
            const __nv_bfloat16* sQl = (const __nv_bfloat16*)(smem + T128);
#pragma unroll
            for (int kf = 0; kf < 4; kf++) {
                LDMX4(Qh[kf][0], Qh[kf][1], Qh[kf][2], Qh[kf][3],
                      smem_u32(sQh + (wid * 16 + lm_r) * LDP + kf * 16 + lm_c));
                LDMX4(Ql[kf][0], Ql[kf][1], Ql[kf][2], Ql[kf][3],
                      smem_u32(sQl + (wid * 16 + lm_r) * LDP + kf * 16 + lm_c));
            }
        }
        if (kc < qt) load_chunk(kc + 1, s ^ 1);

        const char* base = smem + 2 * T128 + s * FA_STAGE;
        const __nv_bfloat16* sKh = (const __nv_bfloat16*)base;
        const __nv_bfloat16* sKl = (const __nv_bfloat16*)(base + T128);
        const __nv_bfloat16* sVh = (const __nv_bfloat16*)(base + 2 * T128);
        const __nv_bfloat16* sVl = (const __nv_bfloat16*)(base + 2 * T128 + FA_VT);

        float sacc[16][4];
#pragma unroll
        for (int j = 0; j < 16; j++)
#pragma unroll
            for (int c = 0; c < 4; c++) sacc[j][c] = 0.f;

#pragma unroll
        for (int ks = 0; ks < 4; ks++) {
#pragma unroll
            for (int grp = 0; grp < 2; grp++) {
                uint32_t Bh[8][2], Bl[8][2];
#pragma unroll
                for (int i = 0; i < 4; i++) {
                    const int nt = grp * 4 + i;
                    LDMX4(Bh[2*i][0], Bh[2*i][1], Bh[2*i+1][0], Bh[2*i+1][1],
                          smem_u32(sKh + (nt * 16 + lb_r) * LDP + ks * 16 + lb_c));
                    LDMX4(Bl[2*i][0], Bl[2*i][1], Bl[2*i+1][0], Bl[2*i+1][1],
                          smem_u32(sKl + (nt * 16 + lb_r) * LDP + ks * 16 + lb_c));
                }
#pragma unroll
                for (int i = 0; i < 8; i++) MMA_BF16(sacc[grp*8+i], Qh[ks], Bh[i]);
#pragma unroll
                for (int i = 0; i < 8; i++) MMA_BF16(sacc[grp*8+i], Qh[ks], Bl[i]);
#pragma unroll
                for (int i = 0; i < 8; i++) MMA_BF16(sacc[grp*8+i], Ql[ks], Bh[i]);
            }
        }

        const bool diag = (kc == qt);
        float mx0 = -INFINITY, mx1 = -INFINITY;
#pragma unroll
        for (int j = 0; j < 16; j++) {
            const int col = kc * 128 + 8 * j + 2 * t;
            float s0 = sacc[j][0] * 0.125f;
            float s1 = sacc[j][1] * 0.125f;
            float s2 = sacc[j][2] * 0.125f;
            float s3 = sacc[j][3] * 0.125f;
            if (diag) {
                if (col     > row0) s0 = NEGF;
                if (col + 1 > row0) s1 = NEGF;
                if (col     > row1) s2 = NEGF;
                if (col + 1 > row1) s3 = NEGF;
            }
            sacc[j][0] = s0; sacc[j][1] = s1; sacc[j][2] = s2; sacc[j][3] = s3;
            mx0 = fmaxf(mx0, fmaxf(s0, s1));
            mx1 = fmaxf(mx1, fmaxf(s2, s3));
        }
        mx0 = fmaxf(mx0, __shfl_xor_sync(~0u, mx0, 1));
        mx0 = fmaxf(mx0, __shfl_xor_sync(~0u, mx0, 2));
        mx1 = fmaxf(mx1, __shfl_xor_sync(~0u, mx1, 1));
        mx1 = fmaxf(mx1, __shfl_xor_sync(~0u, mx1, 2));
        const float mn0 = fmaxf(m0, mx0), mn1 = fmaxf(m1, mx1);
        const float f0 = expf(m0 - mn0), f1 = expf(m1 - mn1);
        float rs0 = 0.f, rs1 = 0.f;
#pragma unroll
        for (int j = 0; j < 16; j++) {
            float p0 = expf(sacc[j][0] - mn0);
            float p1 = expf(sacc[j][1] - mn0);
            float p2 = expf(sacc[j][2] - mn1);
            float p3 = expf(sacc[j][3] - mn1);
            sacc[j][0] = p0; sacc[j][1] = p1; sacc[j][2] = p2; sacc[j][3] = p3;
            rs0 += p0 + p1; rs1 += p2 + p3;
        }
        rs0 += __shfl_xor_sync(~0u, rs0, 1);
        rs0 += __shfl_xor_sync(~0u, rs0, 2);
        rs1 += __shfl_xor_sync(~0u, rs1, 1);
        rs1 += __shfl_xor_sync(~0u, rs1, 2);
        l0 = l0 * f0 + rs0;
        l1 = l1 * f1 + rs1;
        m0 = mn0; m1 = mn1;
#pragma unroll
        for (int ni = 0; ni < 8; ni++) {
            o[ni][0] *= f0; o[ni][1] *= f0; o[ni][2] *= f1; o[ni][3] *= f1;
        }

#pragma unroll
        for (int kf = 0; kf < 8; kf++) {
            const int j0 = 2 * kf, j1 = 2 * kf + 1;
            uint32_t Pfh[4], Pfl[4];
            {
                __nv_bfloat16 a0 = __float2bfloat16(sacc[j0][0]);
                __nv_bfloat16 a1 = __float2bfloat16(sacc[j0][1]);
                __nv_bfloat16 a2 = __float2bfloat16(sacc[j0][2]);
                __nv_bfloat16 a3 = __float2bfloat16(sacc[j0][3]);
                __nv_bfloat16 a4 = __float2bfloat16(sacc[j1][0]);
                __nv_bfloat16 a5 = __float2bfloat16(sacc[j1][1]);
                __nv_bfloat16 a6 = __float2bfloat16(sacc[j1][2]);
                __nv_bfloat16 a7 = __float2bfloat16(sacc[j1][3]);
                Pfh[0] = pack2(a0, a1); Pfh[1] = pack2(a2, a3);
                Pfh[2] = pack2(a4, a5); Pfh[3] = pack2(a6, a7);
                Pfl[0] = pack2(__float2bfloat16(sacc[j0][0] - __bfloat162float(a0)),
                               __float2bfloat16(sacc[j0][1] - __bfloat162float(a1)));
                Pfl[1] = pack2(__float2bfloat16(sacc[j0][2] - __bfloat162float(a2)),
                               __float2bfloat16(sacc[j0][3] - __bfloat162float(a3)));
                Pfl[2] = pack2(__float2bfloat16(sacc[j1][0] - __bfloat162float(a4)),
                               __float2bfloat16(sacc[j1][1] - __bfloat162float(a5)));
                Pfl[3] = pack2(__float2bfloat16(sacc[j1][2] - __bfloat162float(a6)),
                               __float2bfloat16(sacc[j1][3] - __bfloat162float(a7)));
            }
            uint32_t Vh[8][2], Vl[8][2];
#pragma unroll
            for (int i = 0; i < 4; i++) {
                LDMX4(Vh[2*i][0], Vh[2*i][1], Vh[2*i+1][0], Vh[2*i+1][1],
                      smem_u32(sVh + (i * 16 + lb_r) * FA_LDPV + kf * 16 + lb_c));
                LDMX4(Vl[2*i][0], Vl[2*i][1], Vl[2*i+1][0], Vl[2*i+1][1],
                      smem_u32(sVl + (i * 16 + lb_r) * FA_LDPV + kf * 16 + lb_c));
            }
#pragma unroll
            for (int ni = 0; ni < 8; ni++) MMA_BF16(o[ni], Pfh, Vh[ni]);
#pragma unroll
            for (int ni = 0; ni < 8; ni++) MMA_BF16(o[ni], Pfh, Vl[ni]);
#pragma unroll
            for (int ni = 0; ni < 8; ni++) MMA_BF16(o[ni], Pfl, Vh[ni]);
        }
    }

    const float inv0 = 1.f / l0, inv1 = 1.f / l1;
#pragma unroll
    for (int ni = 0; ni < 8; ni++) {
        const int d = h * HD + 8 * ni + 2 * t;
        const size_t off0 = (size_t)(b * SEQ + row0) * DMODEL + d;
        const size_t off1 = (size_t)(b * SEQ + row1) * DMODEL + d;
        float v00 = o[ni][0] * inv0, v01 = o[ni][1] * inv0;
        float v10 = o[ni][2] * inv1, v11 = o[ni][3] * inv1;
        __nv_bfloat16 h00 = __float2bfloat16(v00), h01 = __float2bfloat16(v01);
        __nv_bfloat16 h10 = __float2bfloat16(v10), h11 = __float2bfloat16(v11);
        *(uint32_t*)(Oh + off0) = pack2(h00, h01);
        *(uint32_t*)(Oh + off1) = pack2(h10, h11);
        *(uint32_t*)(Ol + off0) = pack2(__float2bfloat16(v00 - __bfloat162float(h00)),
                                        __float2bfloat16(v01 - __bfloat162float(h01)));
        *(uint32_t*)(Ol + off1) = pack2(__float2bfloat16(v10 - __bfloat162float(h10)),
                                        __float2bfloat16(v11 - __bfloat162float(h11)));
    }
}

// ============ keys softmax -> hi/lo ===========================================
__global__ __launch_bounds__(256, 1)
void softmax_keys_kernel(const float* __restrict__ src,
                         __nv_bfloat16* __restrict__ Kh, __nv_bfloat16* __restrict__ Kl)
{
    const int row = blockIdx.x;
    const int tid = threadIdx.x, warp = tid >> 5, lane = tid & 31;
    const float* p = src + (size_t)row * DMODEL;
    float v[2];
    float m = -INFINITY;
#pragma unroll
    for (int i = 0; i < 2; i++) { v[i] = p[tid + i * 256]; m = fmaxf(m, v[i]); }
#pragma unroll
    for (int o = 16; o > 0; o >>= 1) m = fmaxf(m, __shfl_xor_sync(~0u, m, o));
    __shared__ float smax[8], ssum[8];
    if (lane == 0) smax[warp] = m;
    __syncthreads();
    m = smax[0];
#pragma unroll
    for (int w = 1; w < 8; w++) m = fmaxf(m, smax[w]);
    float sum = 0.f;
#pragma unroll
    for (int i = 0; i < 2; i++) { v[i] = expf(v[i] - m); sum += v[i]; }
#pragma unroll
    for (int o = 16; o > 0; o >>= 1) sum += __shfl_xor_sync(~0u, sum, o);
    if (lane == 0) ssum[warp] = sum;
    __syncthreads();
    sum = ssum[0];
#pragma unroll
    for (int w = 1; w < 8; w++) sum += ssum[w];
    const float inv = 1.f / sum;
#pragma unroll
    for (int i = 0; i < 2; i++) {
        float pv = v[i] * inv;
        __nv_bfloat16 h = __float2bfloat16(pv);
        Kh[(size_t)row * DMODEL + tid + i * 256] = h;
        Kl[(size_t)row * DMODEL + tid + i * 256] = __float2bfloat16(pv - __bfloat162float(h));
    }
}

// ============ V^T from bf16 hi/lo =============================================
__global__ void vt_convert_bf(const __nv_bfloat16* __restrict__ Vh,
                              const __nv_bfloat16* __restrict__ Vl, int ld,
                              __nv_bfloat16* __restrict__ Hi, __nv_bfloat16* __restrict__ Lo)
{
    __shared__ __nv_bfloat16 th[32][33], tl[32][33];
    const int k0 = blockIdx.x * 32, d0 = blockIdx.y * 32, bh = blockIdx.z;
    const int b = bh >> 3, h = bh & 7;
    const int tx = threadIdx.x & 31, ty = threadIdx.x >> 5;
#pragma unroll
    for (int j = 0; j < 32; j += 8) {
        const size_t src = (size_t)(b * SEQ + k0 + ty + j) * ld + h * HD + d0 + tx;
        th[ty + j][tx] = Vh[src];
        tl[ty + j][tx] = Vl[src];
    }
    __syncthreads();
#pragma unroll
    for (int j = 0; j < 32; j += 8) {
        const size_t o = ((size_t)bh * HD + d0 + ty + j) * SEQ + k0 + tx;
        Hi[o] = th[tx][ty + j];
        Lo[o] = tl[tx][ty + j];
    }
}

// ============ weight transpose + split ========================================
__global__ void transpose_convert_kernel(const float* __restrict__ W,
                                         __nv_bfloat16* __restrict__ Hi,
                                         __nv_bfloat16* __restrict__ Lo, int K, int N)
{
    __shared__ float t[32][33];
    const int k0 = blockIdx.y * 32, n0 = blockIdx.x * 32;
    const int tx = threadIdx.x & 31, ty = threadIdx.x >> 5;
#pragma unroll
    for (int j = 0; j < 32; j += 8)
        t[ty + j][tx] = W[(size_t)(k0 + ty + j) * N + n0 + tx];
    __syncthreads();
#pragma unroll
    for (int j = 0; j < 32; j += 8) {
        float v = t[tx][ty + j];
        __nv_bfloat16 h = __float2bfloat16(v);
        Hi[(size_t)(n0 + ty + j) * K + k0 + tx] = h;
        Lo[(size_t)(n0 + ty + j) * K + k0 + tx] = __float2bfloat16(v - __bfloat162float(h));
    }
}

__global__ void transpose_convert3_kernel(const float* __restrict__ W0,
                                          const float* __restrict__ W1,
                                          const float* __restrict__ W2,
                                          __nv_bfloat16* __restrict__ Hi,
                                          __nv_bfloat16* __restrict__ Lo, int K, int N)
{
    __shared__ float t[32][33];
    const int k0 = blockIdx.y * 32, n0 = blockIdx.x * 32, z = blockIdx.z;
    const float* W = (z == 0) ? W0 : (z == 1) ? W1 : W2;
    const int tx = threadIdx.x & 31, ty = threadIdx.x >> 5;
#pragma unroll
    for (int j = 0; j < 32; j += 8)
        t[ty + j][tx] = W[(size_t)(k0 + ty + j) * N + n0 + tx];
    __syncthreads();
#pragma unroll
    for (int j = 0; j < 32; j += 8) {
        float v = t[tx][ty + j];
        __nv_bfloat16 h = __float2bfloat16(v);
        const size_t o = (size_t)(z * N + n0 + ty + j) * K + k0 + tx;
        Hi[o] = h;
        Lo[o] = __float2bfloat16(v - __bfloat162float(h));
    }
}

// ============ elementwise split ===============================================
__global__ void split_kernel(const float* __restrict__ in,
                             __nv_bfloat16* __restrict__ hi, __nv_bfloat16* __restrict__ lo)
{
    const int i = blockIdx.x * 256 + threadIdx.x;
    float4 v = ((const float4*)in)[i];
    uint2 h, l;
    split4(v, h, l);
    ((uint2*)hi)[i] = h;
    ((uint2*)lo)[i] = l;
}

// ============ residual + LayerNorm ============================================
__global__ void ln_kernel(const float* __restrict__ xin, const float* __restrict__ res,
                          int res_ld,
                          const float* __restrict__ scale, const float* __restrict__ bias,
                          float* __restrict__ outf,
                          __nv_bfloat16* __restrict__ outh, __nv_bfloat16* __restrict__ outl)
{
    const int row = blockIdx.x;
    const int tid = threadIdx.x;
    float4 v = ((const float4*)(xin + (size_t)row * DMODEL))[tid];
    if (res) {
        float4 r = ((const float4*)(res + (size_t)row * res_ld))[tid];
        v.x += r.x; v.y += r.y; v.z += r.z; v.w += r.w;
    }
    float s  = v.x + v.y + v.z + v.w;
    float sq = v.x * v.x + v.y * v.y + v.z * v.z + v.w * v.w;
#pragma unroll
    for (int o = 16; o > 0; o >>= 1) {
        s  += __shfl_xor_sync(~0u, s,  o);
        sq += __shfl_xor_sync(~0u, sq, o);
    }
    __shared__ float ss[4], sqs[4];
    const int warp = tid >> 5, lane = tid & 31;
    if (lane == 0) { ss[warp] = s; sqs[warp] = sq; }
    __syncthreads();
    float S  = ss[0]  + ss[1]  + ss[2]  + ss[3];
    float SQ = sqs[0] + sqs[1] + sqs[2] + sqs[3];
    float mean = S * (1.f / DMODEL);
    float var  = SQ * (1.f / DMODEL) - mean * mean;
    float rs   = rsqrtf(var + 1e-6f);
    float4 sc4 = ((const float4*)scale)[tid];
    float4 bi4 = ((const float4*)bias)[tid];
    float4 o;
    o.x = (v.x - mean) * rs * sc4.x + bi4.x;
    o.y = (v.y - mean) * rs * sc4.y + bi4.y;
    o.z = (v.z - mean) * rs * sc4.z + bi4.z;
    o.w = (v.w - mean) * rs * sc4.w + bi4.w;
    if (outf) ((float4*)(outf + (size_t)row * DMODEL))[tid] = o;
    uint2 h, l;
    split4(o, h, l);
    ((uint2*)(outh + (size_t)row * DMODEL))[tid] = h;
    ((uint2*)(outl + (size_t)row * DMODEL))[tid] = l;
}

// ============ fused double LayerNorm: LN2(LN1(x + a) + c) =====================
__global__ void ln2x_kernel(const float* __restrict__ xin, const float* __restrict__ add1,
                            const float* __restrict__ ctx, int ctx_ld,
                            const float* __restrict__ s1, const float* __restrict__ b1,
                            const float* __restrict__ s2, const float* __restrict__ b2,
                            float* __restrict__ outf,
                            __nv_bfloat16* __restrict__ outh, __nv_bfloat16* __restrict__ outl)
{
    const int row = blockIdx.x;
    const int tid = threadIdx.x;
    const int warp = tid >> 5, lane = tid & 31;
    __shared__ float ss[4], sqs[4];

    float4 v = ((const float4*)(xin + (size_t)row * DMODEL))[tid];
    float4 a = ((const float4*)(add1 + (size_t)row * DMODEL))[tid];
    v.x += a.x; v.y += a.y; v.z += a.z; v.w += a.w;

    {
        float s  = v.x + v.y + v.z + v.w;
        float sq = v.x * v.x + v.y * v.y + v.z * v.z + v.w * v.w;
#pragma unroll
        for (int o = 16; o > 0; o >>= 1) {
            s  += __shfl_xor_sync(~0u, s,  o);
            sq += __shfl_xor_sync(~0u, sq, o);
        }
        if (lane == 0) { ss[warp] = s; sqs[warp] = sq; }
        __syncthreads();
        float S  = ss[0]  + ss[1]  + ss[2]  + ss[3];
        float SQ = sqs[0] + sqs[1] + sqs[2] + sqs[3];
        float mean = S * (1.f / DMODEL);
        float var  = SQ * (1.f / DMODEL) - mean * mean;
        float rs   = rsqrtf(var + 1e-6f);
        float4 sc4 = ((const float4*)s1)[tid];
        float4 bi4 = ((const float4*)b1)[tid];
        v.x = (v.x - mean) * rs * sc4.x + bi4.x;
        v.y = (v.y - mean) * rs * sc4.y + bi4.y;
        v.z = (v.z - mean) * rs * sc4.z + bi4.z;
        v.w = (v.w - mean) * rs * sc4.w + bi4.w;
        __syncthreads();
    }
    {
        float4 c = ((const float4*)(ctx + (size_t)row * ctx_ld))[tid];
        v.x += c.x; v.y += c.y; v.z += c.z; v.w += c.w;
        float s  = v.x + v.y + v.z + v.w;
        float sq = v.x * v.x + v.y * v.y + v.z * v.z + v.w * v.w;
#pragma unroll
        for (int o = 16; o > 0; o >>= 1) {
            s  += __shfl_xor_sync(~0u, s,  o);
            sq += __shfl_xor_sync(~0u, sq, o);
        }
        if (lane == 0) { ss[warp] = s; sqs[warp] = sq; }
        __syncthreads();
        float S  = ss[0]  + ss[1]  + ss[2]  + ss[3];
        float SQ = sqs[0] + sqs[1] + sqs[2] + sqs[3];
        float mean = S * (1.f / DMODEL);
        float var  = SQ * (1.f / DMODEL) - mean * mean;
        float rs   = rsqrtf(var + 1e-6f);
        float4 sc4 = ((const float4*)s2)[tid];
        float4 bi4 = ((const float4*)b2)[tid];
        v.x = (v.x - mean) * rs * sc4.x + bi4.x;
        v.y = (v.y - mean) * rs * sc4.y + bi4.y;
        v.z = (v.z - mean) * rs * sc4.z + bi4.z;
        v.w = (v.w - mean) * rs * sc4.w + bi4.w;
    }
    ((float4*)(outf + (size_t)row * DMODEL))[tid] = v;
    uint2 h, l;
    split4(v, h, l);
    ((uint2*)(outh + (size_t)row * DMODEL))[tid] = h;
    ((uint2*)(outl + (size_t)row * DMODEL))[tid] = l;
}

// ============ winner gather ===================================================
__global__ void gather_kernel(const unsigned long long* __restrict__ best,
                              const float* __restrict__ vs, const float* __restrict__ ss,
                              float* __restrict__ vout, float* __restrict__ sout)
{
    const int n = blockIdx.x;
    const int lane = threadIdx.x;
    const unsigned long long key = best[n];
    const int idx = (int)(~(unsigned int)(key & 0xFFFFFFFFull));
    vout[(size_t)n * OUTD + lane] = vs[(size_t)n * (NSLOTS * OUTD) + (size_t)idx * OUTD + lane];
    if (lane == 0) sout[n] = ss[(size_t)n * NSLOTS + idx];
}

// ---------------- host-side wrapper ----------------
struct Bufs {
    __nv_bfloat16 *bthi, *btlo;
};
static void tc_gemm(const __nv_bfloat16* Ah, const __nv_bfloat16* Al,
                    const float* W, const float* bias,
                    float* Cf, __nv_bfloat16* Chi, __nv_bfloat16* Clo,
                    int M, int N, int K, int relu, const Bufs& bf)
{
    transpose_convert_kernel<<<dim3(N / 32, K / 32), 256>>>(W, bf.bthi, bf.btlo, K, N);
    gemm_bb_kernel<<<dim3(N / 256, M / 128), 256, GEMM_SMEM>>>(
        Ah, Al, bf.bthi, bf.btlo, bias, Cf, Chi, Clo, M, N, K, relu,
        nullptr, nullptr, nullptr, 0);
}

extern "C" void kernel_launch(void* const* d_in, const int* in_sizes, int n_in,
                              void* d_out, int out_size)
{
    const float* s_in  = (const float*)d_in[0];
    const float* x_in  = (const float*)d_in[1];
    const float* t_in  = (const float*)d_in[2];
    const float* Wq    = (const float*)d_in[3];
    const float* Wk    = (const float*)d_in[4];
    const float* Wv    = (const float*)d_in[5];
    const float* Wo    = (const float*)d_in[6];
    const float* cWv   = (const float*)d_in[9];
    const float* cWo   = (const float*)d_in[10];
    const float* ln1_s = (const float*)d_in[11];
    const float* ln1_b = (const float*)d_in[12];
    const float* ln2_s = (const float*)d_in[13];
    const float* ln2_b = (const float*)d_in[14];
    const float* ln3_s = (const float*)d_in[15];
    const float* ln3_b = (const float*)d_in[16];
    const float* W1    = (const float*)d_in[17];
    const float* b1    = (const float*)d_in[18];
    const float* W2    = (const float*)d_in[19];
    const float* b2    = (const float*)d_in[20];
    const float* lnf_s = (const float*)d_in[21];
    const float* lnf_b = (const float*)d_in[22];
    const float* Wout  = (const float*)d_in[23];
    const float* bout  = (const float*)d_in[24];
    const float* W_vs  = (const float*)d_in[25];
    const float* b_vs  = (const float*)d_in[26];
    const float* W_ss  = (const float*)d_in[27];
    const float* b_ss  = (const float*)d_in[28];
    float* out = (float*)d_out;

    float *dec, *tmp2, *ctx, *vs, *bcomb;
    unsigned long long* best;
    __nv_bfloat16 *dech, *decl, *qkvh, *qkvl, *obh, *obl, *th, *tl;
    __nv_bfloat16 *ffh, *ffl, *keysh, *keysl, *vthi, *vtlo;
    __nv_bfloat16 *xbth, *xbtl, *cvh, *cvl;
    Bufs bf;
    cudaGetSymbolAddress((void**)&dec,  g_dec);
    cudaGetSymbolAddress((void**)&tmp2, g_tmp2);
    cudaGetSymbolAddress((void**)&ctx,  g_ctx);
    cudaGetSymbolAddress((void**)&vs,   g_vs);
    cudaGetSymbolAddress((void**)&bcomb,g_bcomb);
    cudaGetSymbolAddress((void**)&best, g_best);
    cudaGetSymbolAddress((void**)&dech, g_dech);
    cudaGetSymbolAddress((void**)&decl, g_decl);
    cudaGetSymbolAddress((void**)&qkvh, g_qkvh);
    cudaGetSymbolAddress((void**)&qkvl, g_qkvl);
    cudaGetSymbolAddress((void**)&obh,  g_obh);
    cudaGetSymbolAddress((void**)&obl,  g_obl);
    cudaGetSymbolAddress((void**)&th,   g_th);
    cudaGetSymbolAddress((void**)&tl,   g_tl);
    cudaGetSymbolAddress((void**)&ffh,  g_ffh);
    cudaGetSymbolAddress((void**)&ffl,  g_ffl);
    cudaGetSymbolAddress((void**)&keysh,g_keysh);
    cudaGetSymbolAddress((void**)&keysl,g_keysl);
    cudaGetSymbolAddress((void**)&vthi, g_vthi);
    cudaGetSymbolAddress((void**)&vtlo, g_vtlo);
    cudaGetSymbolAddress((void**)&xbth, g_xbth);
    cudaGetSymbolAddress((void**)&xbtl, g_xbtl);
    cudaGetSymbolAddress((void**)&cvh,  g_cvh);
    cudaGetSymbolAddress((void**)&cvl,  g_cvl);
    cudaGetSymbolAddress((void**)&bf.bthi, g_bthi);
    cudaGetSymbolAddress((void**)&bf.btlo, g_btlo);

    cudaFuncSetAttribute(gemm_bb_kernel, cudaFuncAttributeMaxDynamicSharedMemorySize, GEMM_SMEM);
    cudaFuncSetAttribute(flash_attn,     cudaFuncAttributeMaxDynamicSharedMemorySize, FA_SMEM);

    cudaMemcpyAsync(dec, s_in, sizeof(float) * NTOK * DMODEL, cudaMemcpyDeviceToDevice);
    cudaMemsetAsync(best, 0, NTOK * sizeof(unsigned long long));
    split_kernel<<<NTOK * DMODEL / 1024, 256>>>(s_in, dech, decl);
    split_kernel<<<NTOK * DMODEL / 1024, 256>>>(t_in, th, tl);
    split_kernel<<<2 * DMODEL * DMODEL / 1024, 256>>>(cWv, cvh, cvl);

    // ---- hoisted cross-attention: ctx = t @ [Mx0 | Mx1] ----
    for (int l = 0; l < 2; l++) {
        const size_t wo = (size_t)l * DMODEL * DMODEL;
        tc_gemm(cvh + wo, cvl + wo, cWo + wo, nullptr, tmp2, nullptr, nullptr,
                DMODEL, DMODEL, DMODEL, 0, bf);
        transpose_convert_kernel<<<dim3(16, 16), 256>>>(
            tmp2, xbth + (size_t)l * DMODEL * DMODEL, xbtl + (size_t)l * DMODEL * DMODEL,
            DMODEL, DMODEL);
    }
    gemm_bb_kernel<<<dim3(1024 / 256, NTOK / 128), 256, GEMM_SMEM>>>(
        th, tl, xbth, xbtl, nullptr, ctx, nullptr, nullptr,
        NTOK, 1024, DMODEL, 0, nullptr, nullptr, nullptr, 0);

    for (int l = 0; l < 2; l++) {
        const size_t wo = (size_t)l * DMODEL * DMODEL;
        // ---- fused QKV projection (N=1536) ----
        transpose_convert3_kernel<<<dim3(16, 16, 3), 256>>>(
            Wq + wo, Wk + wo, Wv + wo, bf.bthi, bf.btlo, DMODEL, DMODEL);
        gemm_bb_kernel<<<dim3(QKVN / 256, NTOK / 128), 256, GEMM_SMEM>>>(
            dech, decl, bf.bthi, bf.btlo, nullptr, nullptr, qkvh, qkvl,
            NTOK, QKVN, DMODEL, 0, nullptr, nullptr, nullptr, 0);
        // ---- fused flash attention ----
        vt_convert_bf<<<dim3(32, 2, 64), 256>>>(qkvh + 1024, qkvl + 1024, QKVN, vthi, vtlo);
        flash_attn<<<dim3(8, 64), 256, FA_SMEM>>>(
            qkvh, qkvl, qkvh + 512, qkvl + 512, QKVN, vthi, vtlo, obh, obl);
        tc_gemm(obh, obl, Wo + wo, nullptr, tmp2, nullptr, nullptr, NTOK, DMODEL, DMODEL, 0, bf);
        // ---- fused ln1 + cross-residual + ln2 ----
        ln2x_kernel<<<NTOK, 128>>>(dec, tmp2, ctx + (size_t)l * 512, 1024,
                                   ln1_s + l * DMODEL, ln1_b + l * DMODEL,
                                   ln2_s + l * DMODEL, ln2_b + l * DMODEL,
                                   dec, dech, decl);
        // ---- FFN ----
        tc_gemm(dech, decl, W1 + (size_t)l * DMODEL * FFDIM, b1 + (size_t)l * FFDIM,
                nullptr, ffh, ffl, NTOK, FFDIM, DMODEL, 1, bf);
        tc_gemm(ffh, ffl, W2 + (size_t)l * FFDIM * DMODEL, b2 + (size_t)l * DMODEL,
                tmp2, nullptr, nullptr, NTOK, DMODEL, FFDIM, 0, bf);
        ln_kernel<<<NTOK, 128>>>(dec, tmp2, DMODEL,
                                 ln3_s + l * DMODEL, ln3_b + l * DMODEL, dec, dech, decl);
    }

    // ---- final head ----
    ln_kernel<<<NTOK, 128>>>(dec, nullptr, 0, lnf_s, lnf_b, nullptr, obh, obl);
    tc_gemm(obh, obl, Wout, bout, tmp2, nullptr, nullptr, NTOK, DMODEL, DMODEL, 0, bf);
    softmax_keys_kernel<<<NTOK, 256>>>(tmp2, keysh, keysl);

    float* out_v  = out;
    float* out_s  = out + 262144;
    float* out_ss = out + 262144 + 8192;

    // ---- merged scoring head: [W_ss | W_vs], N = 16896, split epilogue ----
    cudaMemcpyAsync(bcomb, b_ss, NSLOTS * sizeof(float), cudaMemcpyDeviceToDevice);
    cudaMemcpyAsync(bcomb + NSLOTS, b_vs, NSLOTS * OUTD * sizeof(float), cudaMemcpyDeviceToDevice);
    transpose_convert_kernel<<<dim3(NSLOTS / 32, DMODEL / 32), 256>>>(
        W_ss, bf.bthi, bf.btlo, DMODEL, NSLOTS);
    transpose_convert_kernel<<<dim3(NSLOTS * OUTD / 32, DMODEL / 32), 256>>>(
        W_vs, bf.bthi + (size_t)NSLOTS * DMODEL, bf.btlo + (size_t)NSLOTS * DMODEL,
        DMODEL, NSLOTS * OUTD);
    gemm_bb_kernel<<<dim3(HEADN / 256, NTOK / 128), 256, GEMM_SMEM>>>(
        keysh, keysl, bf.bthi, bf.btlo, bcomb, vs, nullptr, nullptr,
        NTOK, HEADN, DMODEL, 0, x_in, best, out_ss, NSLOTS);
    gather_kernel<<<NTOK, 32>>>(best, vs, out_ss, out_v, out_s);
}

// round 13
// speedup vs baseline: 1.0439x; 1.0439x over previous
#include <cuda_runtime.h>
#include <cuda_bf16.h>
#include <math.h>
#include <stdint.h>

#define NTOK   8192
#define DMODEL 512
#define HEADS  8
#define HD     64
#define SEQ    1024
#define FFDIM  2048
#define NSLOTS 512
#define OUTD   32
#define QKVN   1536
#define HEADN  16896
#define NEGF   (-3.4028234663852886e38f)

// ---------------- static scratch ----------------
__device__ float g_dec [NTOK * DMODEL];
__device__ float g_tmp2[NTOK * DMODEL];
__device__ float g_ctx [NTOK * 1024];
__device__ float g_vs  [(size_t)NTOK * NSLOTS * OUTD];
__device__ float g_bcomb[HEADN];
__device__ unsigned long long g_best[NTOK];
__device__ __nv_bfloat16 g_dech[NTOK * DMODEL], g_decl[NTOK * DMODEL];
__device__ __nv_bfloat16 g_qkvh[NTOK * QKVN],  g_qkvl[NTOK * QKVN];
__device__ __nv_bfloat16 g_obh [NTOK * DMODEL], g_obl [NTOK * DMODEL];
__device__ __nv_bfloat16 g_th  [NTOK * DMODEL], g_tl  [NTOK * DMODEL];
__device__ __nv_bfloat16 g_ffh [NTOK * FFDIM],  g_ffl [NTOK * FFDIM];
__device__ __nv_bfloat16 g_keysh[NTOK * DMODEL], g_keysl[NTOK * DMODEL];
__device__ __nv_bfloat16 g_vthi[64 * HD * SEQ], g_vtlo[64 * HD * SEQ];
__device__ __nv_bfloat16 g_bthi[(size_t)DMODEL * HEADN], g_btlo[(size_t)DMODEL * HEADN];
__device__ __nv_bfloat16 g_xbth[1024 * DMODEL], g_xbtl[1024 * DMODEL];
__device__ __nv_bfloat16 g_cvh[2 * DMODEL * DMODEL], g_cvl[2 * DMODEL * DMODEL];

__device__ __forceinline__ uint32_t smem_u32(const void* p) {
    uint32_t a;
    asm("{ .reg .u64 t; cvta.to.shared.u64 t, %1; cvt.u32.u64 %0, t; }" : "=r"(a) : "l"(p));
    return a;
}
__device__ __forceinline__ uint32_t pack2(__nv_bfloat16 a, __nv_bfloat16 b) {
    return (uint32_t)__bfloat16_as_ushort(a) | ((uint32_t)__bfloat16_as_ushort(b) << 16);
}
__device__ __forceinline__ void cp16(uint32_t dst, const void* src) {
    asm volatile("cp.async.cg.shared.global [%0], [%1], 16;" :: "r"(dst), "l"(src) : "memory");
}
__device__ __forceinline__ void cp_commit() {
    asm volatile("cp.async.commit_group;" ::: "memory");
}
__device__ __forceinline__ void cp_wait0() {
    asm volatile("cp.async.wait_group 0;" ::: "memory");
}
__device__ __forceinline__ void split4(float4 v, uint2& hi, uint2& lo) {
    __nv_bfloat16 hx = __float2bfloat16(v.x), hy = __float2bfloat16(v.y);
    __nv_bfloat16 hz = __float2bfloat16(v.z), hw = __float2bfloat16(v.w);
    __nv_bfloat16 lx = __float2bfloat16(v.x - __bfloat162float(hx));
    __nv_bfloat16 ly = __float2bfloat16(v.y - __bfloat162float(hy));
    __nv_bfloat16 lz = __float2bfloat16(v.z - __bfloat162float(hz));
    __nv_bfloat16 lw = __float2bfloat16(v.w - __bfloat162float(hw));
    hi = make_uint2(pack2(hx, hy), pack2(hz, hw));
    lo = make_uint2(pack2(lx, ly), pack2(lz, lw));
}
__device__ __forceinline__ unsigned long long score_key(float s, int slot) {
    unsigned int u = __float_as_uint(s);
    u = (u & 0x80000000u) ? ~u : (u | 0x80000000u);
    return ((unsigned long long)u << 32) | (unsigned int)(~slot);
}

#define LDMX4(r0, r1, r2, r3, addr) \
    asm volatile("ldmatrix.sync.aligned.m8n8.x4.shared.b16 {%0,%1,%2,%3}, [%4];" \
        : "=r"(r0), "=r"(r1), "=r"(r2), "=r"(r3) : "r"(addr))

#define MMA_BF16(c, a, b) \
    asm volatile("mma.sync.aligned.m16n8k16.row.col.f32.bf16.bf16.f32 " \
        "{%0,%1,%2,%3}, {%4,%5,%6,%7}, {%8,%9}, {%0,%1,%2,%3};" \
        : "+f"((c)[0]), "+f"((c)[1]), "+f"((c)[2]), "+f"((c)[3]) \
        : "r"((a)[0]), "r"((a)[1]), "r"((a)[2]), "r"((a)[3]), "r"((b)[0]), "r"((b)[1]))

#define LDP 72
#define T128 (128 * LDP * 2)
#define T256 (256 * LDP * 2)
#define GB_STAGE (2 * T128 + 2 * T256)
#define GEMM_SMEM (2 * GB_STAGE)
#define FA_LDPV 136
#define FA_VT (64 * FA_LDPV * 2)
#define FA_STAGE (2 * T128 + 2 * FA_VT)
#define FA_SMEM (2 * T128 + 2 * FA_STAGE)

// ============ split-bf16 HMMA GEMM: CTA 128x256, 16 warps of 64x32 (R11 champ) =
__global__ __launch_bounds__(512, 1)
void gemm_bb_kernel(const __nv_bfloat16* __restrict__ Ahi, const __nv_bfloat16* __restrict__ Alo,
                    const __nv_bfloat16* __restrict__ Bhi, const __nv_bfloat16* __restrict__ Blo,
                    const float* __restrict__ bias,
                    float* __restrict__ Cf, __nv_bfloat16* __restrict__ Chi,
                    __nv_bfloat16* __restrict__ Clo,
                    int M, int N, int K, int relu,
                    const float* __restrict__ xsc, unsigned long long* __restrict__ best,
                    float* __restrict__ Cf2, int split)
{
    extern __shared__ char smem[];
    const int tid  = threadIdx.x;
    const int lane = tid & 31, wid = tid >> 5;
    const int wm = wid >> 3;
    const int wn = wid & 7;
    const size_t brow = (size_t)blockIdx.y * 128;
    const size_t bcol = (size_t)blockIdx.x * 256;
    const int seg = tid & 7, r0 = tid >> 3;

    const int NP = K >> 6;

    auto load_panel = [&](int p, int s) {
        char* base = smem + s * GB_STAGE;
        const size_t ka = (size_t)p * 64 + seg * 8;
#pragma unroll
        for (int hf = 0; hf < 2; hf++) {
            const int r = r0 + hf * 64;
            const uint32_t dst = smem_u32(base + (r * LDP + seg * 8) * 2);
            cp16(dst,        Ahi + (brow + r) * K + ka);
            cp16(dst + T128, Alo + (brow + r) * K + ka);
        }
#pragma unroll
        for (int i = 0; i < 4; i++) {
            const int r = r0 + i * 64;
            const uint32_t dst = smem_u32(base + 2 * T128 + (r * LDP + seg * 8) * 2);
            cp16(dst,        Bhi + (bcol + r) * K + ka);
            cp16(dst + T256, Blo + (bcol + r) * K + ka);
        }
        cp_commit();
    };

    load_panel(0, 0);

    float acc[4][4][4];
#pragma unroll
    for (int i = 0; i < 4; i++)
#pragma unroll
        for (int j = 0; j < 4; j++)
#pragma unroll
            for (int c = 0; c < 4; c++) acc[i][j][c] = 0.f;

    const int lm_r = (lane & 7) + ((lane >> 3) & 1) * 8;
    const int lm_c = ((lane >> 4) & 1) * 8;
    const int lb_r = (lane & 7) + ((lane >> 4) & 1) * 8;
    const int lb_c = ((lane >> 3) & 1) * 8;

    for (int p = 0; p < NP; p++) {
        const int s = p & 1;
        cp_wait0();
        __syncthreads();
        if (p + 1 < NP) load_panel(p + 1, s ^ 1);

        const __nv_bfloat16* sAh = (const __nv_bfloat16*)(smem + s * GB_STAGE);
        const __nv_bfloat16* sAl = (const __nv_bfloat16*)((char*)sAh + T128);
        const __nv_bfloat16* sBh = (const __nv_bfloat16*)((char*)sAh + 2 * T128);
        const __nv_bfloat16* sBl = (const __nv_bfloat16*)((char*)sAh + 2 * T128 + T256);

#pragma unroll
        for (int ks = 0; ks < 4; ks++) {
            const int k0 = ks * 16;
            uint32_t Ah[4][4], Al[4][4], Bh[4][2], Bl[4][2];
#pragma unroll
            for (int mi = 0; mi < 4; mi++) {
                const int r = wm * 64 + mi * 16 + lm_r;
                LDMX4(Ah[mi][0], Ah[mi][1], Ah[mi][2], Ah[mi][3], smem_u32(sAh + r * LDP + k0 + lm_c));
                LDMX4(Al[mi][0], Al[mi][1], Al[mi][2], Al[mi][3], smem_u32(sAl + r * LDP + k0 + lm_c));
            }
#pragma unroll
            for (int nio = 0; nio < 2; nio++) {
                const int r = wn * 32 + nio * 16 + lb_r;
                LDMX4(Bh[2*nio][0], Bh[2*nio][1], Bh[2*nio+1][0], Bh[2*nio+1][1],
                      smem_u32(sBh + r * LDP + k0 + lb_c));
                LDMX4(Bl[2*nio][0], Bl[2*nio][1], Bl[2*nio+1][0], Bl[2*nio+1][1],
                      smem_u32(sBl + r * LDP + k0 + lb_c));
            }
#pragma unroll
            for (int mi = 0; mi < 4; mi++)
#pragma unroll
                for (int ni = 0; ni < 4; ni++) MMA_BF16(acc[mi][ni], Ah[mi], Bh[ni]);
#pragma unroll
            for (int mi = 0; mi < 4; mi++)
#pragma unroll
                for (int ni = 0; ni < 4; ni++) MMA_BF16(acc[mi][ni], Ah[mi], Bl[ni]);
#pragma unroll
            for (int mi = 0; mi < 4; mi++)
#pragma unroll
                for (int ni = 0; ni < 4; ni++) MMA_BF16(acc[mi][ni], Al[mi], Bh[ni]);
        }
    }

    const int g = lane >> 2, t = lane & 3;
    const int tile_col = (int)bcol + wn * 32;
    const bool lo_region = (split > 0) && (tile_col < split);
    const int ldv = (split > 0) ? (N - split) : N;
#pragma unroll
    for (int mi = 0; mi < 4; mi++) {
        const size_t rm = brow + wm * 64 + mi * 16 + g;
        float dA = 0.f, sA2 = 0.f, dB = 0.f, sB2 = 0.f;
#pragma unroll
        for (int ni = 0; ni < 4; ni++) {
            const size_t cn = bcol + wn * 32 + ni * 8 + 2 * t;
            float b0 = 0.f, b1 = 0.f;
            if (bias) { b0 = bias[cn]; b1 = bias[cn + 1]; }
            float v00 = acc[mi][ni][0] + b0, v01 = acc[mi][ni][1] + b1;
            float v10 = acc[mi][ni][2] + b0, v11 = acc[mi][ni][3] + b1;
            if (relu) {
                v00 = fmaxf(v00, 0.f); v01 = fmaxf(v01, 0.f);
                v10 = fmaxf(v10, 0.f); v11 = fmaxf(v11, 0.f);
            }
            if (lo_region) {
                *(float2*)(Cf2 + rm * split + cn)       = make_float2(v00, v01);
                *(float2*)(Cf2 + (rm + 8) * split + cn) = make_float2(v10, v11);
            } else if (Cf) {
                const size_t cv = cn - split;
                *(float2*)(Cf + rm * ldv + cv)       = make_float2(v00, v01);
                *(float2*)(Cf + (rm + 8) * ldv + cv) = make_float2(v10, v11);
            }
            if (Chi) {
                __nv_bfloat16 h00 = __float2bfloat16(v00), h01 = __float2bfloat16(v01);
                __nv_bfloat16 h10 = __float2bfloat16(v10), h11 = __float2bfloat16(v11);
                *(uint32_t*)(Chi + rm * N + cn)       = pack2(h00, h01);
                *(uint32_t*)(Chi + (rm + 8) * N + cn) = pack2(h10, h11);
                *(uint32_t*)(Clo + rm * N + cn)       =
                    pack2(__float2bfloat16(v00 - __bfloat162float(h00)),
                          __float2bfloat16(v01 - __bfloat162float(h01)));
                *(uint32_t*)(Clo + (rm + 8) * N + cn) =
                    pack2(__float2bfloat16(v10 - __bfloat162float(h10)),
                          __float2bfloat16(v11 - __bfloat162float(h11)));
            }
            if (xsc && !lo_region) {
                const int o = ni * 8 + 2 * t;
                float xa0 = xsc[rm * OUTD + o],       xa1 = xsc[rm * OUTD + o + 1];
                float xb0 = xsc[(rm + 8) * OUTD + o], xb1 = xsc[(rm + 8) * OUTD + o + 1];
                dA += v00 * xa0 + v01 * xa1;  sA2 += v00 * v00 + v01 * v01;
                dB += v10 * xb0 + v11 * xb1;  sB2 += v10 * v10 + v11 * v11;
            }
        }
        if (xsc && !lo_region) {
#pragma unroll
            for (int m = 1; m <= 2; m <<= 1) {
                dA  += __shfl_xor_sync(~0u, dA,  m);
                sA2 += __shfl_xor_sync(~0u, sA2, m);
                dB  += __shfl_xor_sync(~0u, dB,  m);
                sB2 += __shfl_xor_sync(~0u, sB2, m);
            }
            if (t == 0) {
                const int slot = (tile_col - split) >> 5;
                atomicMax(&best[rm],     score_key(dA * rsqrtf(sA2), slot));
                atomicMax(&best[rm + 8], score_key(dB * rsqrtf(sB2), slot));
            }
        }
    }
}

// ============ fused flash attention ===========================================
__global__ __launch_bounds__(256, 1)
void flash_attn(const __nv_bfloat16* __restrict__ Qh_, const __nv_bfloat16* __restrict__ Ql_,
                const __nv_bfloat16* __restrict__ Kh_, const __nv_bfloat16* __restrict__ Kl_,
                int ld,
                const __nv_bfloat16* __restrict__ Vth, const __nv_bfloat16* __restrict__ Vtl,
                __nv_bfloat16* __restrict__ Oh, __nv_bfloat16* __restrict__ Ol)
{
    extern __shared__ char smem[];
    const int qt = 7 - blockIdx.x;
    const int bh = blockIdx.y;
    const int b = bh >> 3, h = bh & 7;
    const int tid = threadIdx.x;
    const int lane = tid & 31, wid = tid >> 5;
    const int g = lane >> 2, t = lane & 3;

    auto load_chunk = [&](int kc, int s) {
        char* base = smem + 2 * T128 + s * FA_STAGE;
        {
            const int seg = tid & 7, r0 = tid >> 3;
#pragma unroll
            for (int it = 0; it < 4; it++) {
                const int r = r0 + it * 32;
                const uint32_t dst = smem_u32(base + (r * LDP + seg * 8) * 2);
                const size_t off = ((size_t)(b * SEQ + kc * 128 + r) * ld) + h * HD + seg * 8;
                cp16(dst,        Kh_ + off);
                cp16(dst + T128, Kl_ + off);
            }
        }
        {
            const int seg = tid & 15, r0 = tid >> 4;
#pragma unroll
            for (int it = 0; it < 4; it++) {
                const int r = r0 + it * 16;
                const uint32_t dst = smem_u32(base + 2 * T128 + (r * FA_LDPV + seg * 8) * 2);
                const size_t off = ((size_t)bh * HD + r) * SEQ + kc * 128 + seg * 8;
                cp16(dst,         Vth + off);
                cp16(dst + FA_VT, Vtl + off);
            }
        }
        cp_commit();
    };

    {
        const int seg = tid & 7, r0 = tid >> 3;
#pragma unroll
        for (int it = 0; it < 4; it++) {
            const int r = r0 + it * 32;
            const uint32_t dst = smem_u32(smem + (r * LDP + seg * 8) * 2);
            const size_t off = ((size_t)(b * SEQ + qt * 128 + r) * ld) + h * HD + seg * 8;
            cp16(dst,        Qh_ + off);
            cp16(dst + T128, Ql_ + off);
        }
    }
    load_chunk(0, 0);

    const int lm_r = (lane & 7) + ((lane >> 3) & 1) * 8;
    const int lm_c = ((lane >> 4) & 1) * 8;
    const int lb_r = (lane & 7) + ((lane >> 4) & 1) * 8;
    const int lb_c = ((lane >> 3) & 1) * 8;

    uint32_t Qh[4][4], Ql[4][4];
    float o[8][4];
#pragma unroll
    for (int i = 0; i < 8; i++)
#pragma unroll
        for (int c = 0; c < 4; c++) o[i][c] = 0.f;
    float m0 = -INFINITY, m1 = -INFINITY, l0 = 0.f, l1 = 0.f;
    const int row0 = qt * 128 + wid * 16 + g;
    const int row1 = row0 + 8;

    for (int kc = 0; kc <= qt; kc++) {
        const int s = kc & 1;
        cp_wait0();
        __syncthreads();
        if (kc == 0) {
            const __nv_bfloat16* sQh = (const __nv_bfloat16*)smem;
            const __nv_bfloat16* sQl = (const __nv_bfloat16*)(smem + T128);
#pragma unroll
            for (int kf = 0; kf < 4; kf++) {
                LDMX4(Qh[kf][0], Qh[kf][1], Qh[kf][2], Qh[kf][3],
                      smem_u32(sQh + (wid * 16 + lm_r) * LDP + kf * 16 + lm_c));
                LDMX4(Ql[kf][0], Ql[kf][1], Ql[kf][2], Ql[kf][3],
                      smem_u32(sQl + (wid * 16 + lm_r) * LDP + kf * 16 + lm_c));
            }
        }
        if (kc < qt) load_chunk(kc + 1, s ^ 1);

        const char* base = smem + 2 * T128 + s * FA_STAGE;
        const __nv_bfloat16* sKh = (const __nv_bfloat16*)base;
        const __nv_bfloat16* sKl = (const __nv_bfloat16*)(base + T128);
        const __nv_bfloat16* sVh = (const __nv_bfloat16*)(base + 2 * T128);
        const __nv_bfloat16* sVl = (const __nv_bfloat16*)(base + 2 * T128 + FA_VT);

        float sacc[16][4];
#pragma unroll
        for (int j = 0; j < 16; j++)
#pragma unroll
            for (int c = 0; c < 4; c++) sacc[j][c] = 0.f;

#pragma unroll
        for (int ks = 0; ks < 4; ks++) {
#pragma unroll
            for (int grp = 0; grp < 2; grp++) {
                uint32_t Bh[8][2], Bl[8][2];
#pragma unroll
                for (int i = 0; i < 4; i++) {
                    const int nt = grp * 4 + i;
                    LDMX4(Bh[2*i][0], Bh[2*i][1], Bh[2*i+1][0], Bh[2*i+1][1],
                          smem_u32(sKh + (nt * 16 + lb_r) * LDP + ks * 16 + lb_c));
                    LDMX4(Bl[2*i][0], Bl[2*i][1], Bl[2*i+1][0], Bl[2*i+1][1],
                          smem_u32(sKl + (nt * 16 + lb_r) * LDP + ks * 16 + lb_c));
                }
#pragma unroll
                for (int i = 0; i < 8; i++) MMA_BF16(sacc[grp*8+i], Qh[ks], Bh[i]);
#pragma unroll
                for (int i = 0; i < 8; i++) MMA_BF16(sacc[grp*8+i], Qh[ks], Bl[i]);
#pragma unroll
                for (int i = 0; i < 8; i++) MMA_BF16(sacc[grp*8+i], Ql[ks], Bh[i]);
            }
        }

        const bool diag = (kc == qt);
        float mx0 = -INFINITY, mx1 = -INFINITY;
#pragma unroll
        for (int j = 0; j < 16; j++) {
            const int col = kc * 128 + 8 * j + 2 * t;
            float s0 = sacc[j][0] * 0.125f;
            float s1 = sacc[j][1] * 0.125f;
            float s2 = sacc[j][2] * 0.125f;
            float s3 = sacc[j][3] * 0.125f;
            if (diag) {
                if (col     > row0) s0 = NEGF;
                if (col + 1 > row0) s1 = NEGF;
                if (col     > row1) s2 = NEGF;
                if (col + 1 > row1) s3 = NEGF;
            }
            sacc[j][0] = s0; sacc[j][1] = s1; sacc[j][2] = s2; sacc[j][3] = s3;
            mx0 = fmaxf(mx0, fmaxf(s0, s1));
            mx1 = fmaxf(mx1, fmaxf(s2, s3));
        }
        mx0 = fmaxf(mx0, __shfl_xor_sync(~0u, mx0, 1));
        mx0 = fmaxf(mx0, __shfl_xor_sync(~0u, mx0, 2));
        mx1 = fmaxf(mx1, __shfl_xor_sync(~0u, mx1, 1));
        mx1 = fmaxf(mx1, __shfl_xor_sync(~0u, mx1, 2));
        const float mn0 = fmaxf(m0, mx0), mn1 = fmaxf(m1, mx1);
        const float f0 = expf(m0 - mn0), f1 = expf(m1 - mn1);
        float rs0 = 0.f, rs1 = 0.f;
#pragma unroll
        for (int j = 0; j < 16; j++) {
            float p0 = expf(sacc[j][0] - mn0);
            float p1 = expf(sacc[j][1] - mn0);
            float p2 = expf(sacc[j][2] - mn1);
            float p3 = expf(sacc[j][3] - mn1);
            sacc[j][0] = p0; sacc[j][1] = p1; sacc[j][2] = p2; sacc[j][3] = p3;
            rs0 += p0 + p1; rs1 += p2 + p3;
        }
        rs0 += __shfl_xor_sync(~0u, rs0, 1);
        rs0 += __shfl_xor_sync(~0u, rs0, 2);
        rs1 += __shfl_xor_sync(~0u, rs1, 1);
        rs1 += __shfl_xor_sync(~0u, rs1, 2);
        l0 = l0 * f0 + rs0;
        l1 = l1 * f1 + rs1;
        m0 = mn0; m1 = mn1;
#pragma unroll
        for (int ni = 0; ni < 8; ni++) {
            o[ni][0] *= f0; o[ni][1] *= f0; o[ni][2] *= f1; o[ni][3] *= f1;
        }

#pragma unroll
        for (int kf = 0; kf < 8; kf++) {
            const int j0 = 2 * kf, j1 = 2 * kf + 1;
            uint32_t Pfh[4], Pfl[4];
            {
                __nv_bfloat16 a0 = __float2bfloat16(sacc[j0][0]);
                __nv_bfloat16 a1 = __float2bfloat16(sacc[j0][1]);
                __nv_bfloat16 a2 = __float2bfloat16(sacc[j0][2]);
                __nv_bfloat16 a3 = __float2bfloat16(sacc[j0][3]);
                __nv_bfloat16 a4 = __float2bfloat16(sacc[j1][0]);
                __nv_bfloat16 a5 = __float2bfloat16(sacc[j1][1]);
                __nv_bfloat16 a6 = __float2bfloat16(sacc[j1][2]);
                __nv_bfloat16 a7 = __float2bfloat16(sacc[j1][3]);
                Pfh[0] = pack2(a0, a1); Pfh[1] = pack2(a2, a3);
                Pfh[2] = pack2(a4, a5); Pfh[3] = pack2(a6, a7);
                Pfl[0] = pack2(__float2bfloat16(sacc[j0][0] - __bfloat162float(a0)),
                               __float2bfloat16(sacc[j0][1] - __bfloat162float(a1)));
                Pfl[1] = pack2(__float2bfloat16(sacc[j0][2] - __bfloat162float(a2)),
                               __float2bfloat16(sacc[j0][3] - __bfloat162float(a3)));
                Pfl[2] = pack2(__float2bfloat16(sacc[j1][0] - __bfloat162float(a4)),
                               __float2bfloat16(sacc[j1][1] - __bfloat162float(a5)));
                Pfl[3] = pack2(__float2bfloat16(sacc[j1][2] - __bfloat162float(a6)),
                               __float2bfloat16(sacc[j1][3] - __bfloat162float(a7)));
            }
            uint32_t Vh[8][2], Vl[8][2];
#pragma unroll
            for (int i = 0; i < 4; i++) {
                LDMX4(Vh[2*i][0], Vh[2*i][1], Vh[2*i+1][0], Vh[2*i+1][1],
                      smem_u32(sVh + (i * 16 + lb_r) * FA_LDPV + kf * 16 + lb_c));
                LDMX4(Vl[2*i][0], Vl[2*i][1], Vl[2*i+1][0], Vl[2*i+1][1],
                      smem_u32(sVl + (i * 16 + lb_r) * FA_LDPV + kf * 16 + lb_c));
            }
#pragma unroll
            for (int ni = 0; ni < 8; ni++) MMA_BF16(o[ni], Pfh, Vh[ni]);
#pragma unroll
            for (int ni = 0; ni < 8; ni++) MMA_BF16(o[ni], Pfh, Vl[ni]);
#pragma unroll
            for (int ni = 0; ni < 8; ni++) MMA_BF16(o[ni], Pfl, Vh[ni]);
        }
    }

    const float inv0 = 1.f / l0, inv1 = 1.f / l1;
#pragma unroll
    for (int ni = 0; ni < 8; ni++) {
        const int d = h * HD + 8 * ni + 2 * t;
        const size_t off0 = (size_t)(b * SEQ + row0) * DMODEL + d;
        const size_t off1 = (size_t)(b * SEQ + row1) * DMODEL + d;
        float v00 = o[ni][0] * inv0, v01 = o[ni][1] * inv0;
        float v10 = o[ni][2] * inv1, v11 = o[ni][3] * inv1;
        __nv_bfloat16 h00 = __float2bfloat16(v00), h01 = __float2bfloat16(v01);
        __nv_bfloat16 h10 = __float2bfloat16(v10), h11 = __float2bfloat16(v11);
        *(uint32_t*)(Oh + off0) = pack2(h00, h01);
        *(uint32_t*)(Oh + off1) = pack2(h10, h11);
        *(uint32_t*)(Ol + off0) = pack2(__float2bfloat16(v00 - __bfloat162float(h00)),
                                        __float2bfloat16(v01 - __bfloat162float(h01)));
        *(uint32_t*)(Ol + off1) = pack2(__float2bfloat16(v10 - __bfloat162float(h10)),
                                        __float2bfloat16(v11 - __bfloat162float(h11)));
    }
}

// ============ keys softmax -> hi/lo ===========================================
__global__ __launch_bounds__(256, 1)
void softmax_keys_kernel(const float* __restrict__ src,
                         __nv_bfloat16* __restrict__ Kh, __nv_bfloat16* __restrict__ Kl)
{
    const int row = blockIdx.x;
    const int tid = threadIdx.x, warp = tid >> 5, lane = tid & 31;
    const float* p = src + (size_t)row * DMODEL;
    float v[2];
    float m = -INFINITY;
#pragma unroll
    for (int i = 0; i < 2; i++) { v[i] = p[tid + i * 256]; m = fmaxf(m, v[i]); }
#pragma unroll
    for (int o = 16; o > 0; o >>= 1) m = fmaxf(m, __shfl_xor_sync(~0u, m, o));
    __shared__ float smax[8], ssum[8];
    if (lane == 0) smax[warp] = m;
    __syncthreads();
    m = smax[0];
#pragma unroll
    for (int w = 1; w < 8; w++) m = fmaxf(m, smax[w]);
    float sum = 0.f;
#pragma unroll
    for (int i = 0; i < 2; i++) { v[i] = expf(v[i] - m); sum += v[i]; }
#pragma unroll
    for (int o = 16; o > 0; o >>= 1) sum += __shfl_xor_sync(~0u, sum, o);
    if (lane == 0) ssum[warp] = sum;
    __syncthreads();
    sum = ssum[0];
#pragma unroll
    for (int w = 1; w < 8; w++) sum += ssum[w];
    const float inv = 1.f / sum;
#pragma unroll
    for (int i = 0; i < 2; i++) {
        float pv = v[i] * inv;
        __nv_bfloat16 h = __float2bfloat16(pv);
        Kh[(size_t)row * DMODEL + tid + i * 256] = h;
        Kl[(size_t)row * DMODEL + tid + i * 256] = __float2bfloat16(pv - __bfloat162float(h));
    }
}

// ============ V^T from bf16 hi/lo =============================================
__global__ void vt_convert_bf(const __nv_bfloat16* __restrict__ Vh,
                              const __nv_bfloat16* __restrict__ Vl, int ld,
                              __nv_bfloat16* __restrict__ Hi, __nv_bfloat16* __restrict__ Lo)
{
    __shared__ __nv_bfloat16 th[32][33], tl[32][33];
    const int k0 = blockIdx.x * 32, d0 = blockIdx.y * 32, bh = blockIdx.z;
    const int b = bh >> 3, h = bh & 7;
    const int tx = threadIdx.x & 31, ty = threadIdx.x >> 5;
#pragma unroll
    for (int j = 0; j < 32; j += 8) {
        const size_t src = (size_t)(b * SEQ + k0 + ty + j) * ld + h * HD + d0 + tx;
        th[ty + j][tx] = Vh[src];
        tl[ty + j][tx] = Vl[src];
    }
    __syncthreads();
#pragma unroll
    for (int j = 0; j < 32; j += 8) {
        const size_t o = ((size_t)bh * HD + d0 + ty + j) * SEQ + k0 + tx;
        Hi[o] = th[tx][ty + j];
        Lo[o] = tl[tx][ty + j];
    }
}

// ============ weight transpose + split ========================================
__global__ void transpose_convert_kernel(const float* __restrict__ W,
                                         __nv_bfloat16* __restrict__ Hi,
                                         __nv_bfloat16* __restrict__ Lo, int K, int N)
{
    __shared__ float t[32][33];
    const int k0 = blockIdx.y * 32, n0 = blockIdx.x * 32;
    const int tx = threadIdx.x & 31, ty = threadIdx.x >> 5;
#pragma unroll
    for (int j = 0; j < 32; j += 8)
        t[ty + j][tx] = W[(size_t)(k0 + ty + j) * N + n0 + tx];
    __syncthreads();
#pragma unroll
    for (int j = 0; j < 32; j += 8) {
        float v = t[tx][ty + j];
        __nv_bfloat16 h = __float2bfloat16(v);
        Hi[(size_t)(n0 + ty + j) * K + k0 + tx] = h;
        Lo[(size_t)(n0 + ty + j) * K + k0 + tx] = __float2bfloat16(v - __bfloat162float(h));
    }
}

__global__ void transpose_convert3_kernel(const float* __restrict__ W0,
                                          const float* __restrict__ W1,
                                          const float* __restrict__ W2,
                                          __nv_bfloat16* __restrict__ Hi,
                                          __nv_bfloat16* __restrict__ Lo, int K, int N)
{
    __shared__ float t[32][33];
    const int k0 = blockIdx.y * 32, n0 = blockIdx.x * 32, z = blockIdx.z;
    const float* W = (z == 0) ? W0 : (z == 1) ? W1 : W2;
    const int tx = threadIdx.x & 31, ty = threadIdx.x >> 5;
#pragma unroll
    for (int j = 0; j < 32; j += 8)
        t[ty + j][tx] = W[(size_t)(k0 + ty + j) * N + n0 + tx];
    __syncthreads();
#pragma unroll
    for (int j = 0; j < 32; j += 8) {
        float v = t[tx][ty + j];
        __nv_bfloat16 h = __float2bfloat16(v);
        const size_t o = (size_t)(z * N + n0 + ty + j) * K + k0 + tx;
        Hi[o] = h;
        Lo[o] = __float2bfloat16(v - __bfloat162float(h));
    }
}

// ============ elementwise split (optionally also copies fp32) =================
__global__ void split_kernel(const float* __restrict__ in,
                             __nv_bfloat16* __restrict__ hi, __nv_bfloat16* __restrict__ lo)
{
    const int i = blockIdx.x * 256 + threadIdx.x;
    float4 v = ((const float4*)in)[i];
    uint2 h, l;
    split4(v, h, l);
    ((uint2*)hi)[i] = h;
    ((uint2*)lo)[i] = l;
}

__global__ void split_copy_kernel(const float* __restrict__ in, float* __restrict__ outf,
                                  __nv_bfloat16* __restrict__ hi, __nv_bfloat16* __restrict__ lo)
{
    const int i = blockIdx.x * 256 + threadIdx.x;
    float4 v = ((const float4*)in)[i];
    ((float4*)outf)[i] = v;
    uint2 h, l;
    split4(v, h, l);
    ((uint2*)hi)[i] = h;
    ((uint2*)lo)[i] = l;
}

// ============ residual + LayerNorm ============================================
__global__ void ln_kernel(const float* __restrict__ xin, const float* __restrict__ res,
                          int res_ld,
                          const float* __restrict__ scale, const float* __restrict__ bias,
                          float* __restrict__ outf,
                          __nv_bfloat16* __restrict__ outh, __nv_bfloat16* __restrict__ outl)
{
    const int row = blockIdx.x;
    const int tid = threadIdx.x;
    float4 v = ((const float4*)(xin + (size_t)row * DMODEL))[tid];
    if (res) {
        float4 r = ((const float4*)(res + (size_t)row * res_ld))[tid];
        v.x += r.x; v.y += r.y; v.z += r.z; v.w += r.w;
    }
    float s  = v.x + v.y + v.z + v.w;
    float sq = v.x * v.x + v.y * v.y + v.z * v.z + v.w * v.w;
#pragma unroll
    for (int o = 16; o > 0; o >>= 1) {
        s  += __shfl_xor_sync(~0u, s,  o);
        sq += __shfl_xor_sync(~0u, sq, o);
    }
    __shared__ float ss[4], sqs[4];
    const int warp = tid >> 5, lane = tid & 31;
    if (lane == 0) { ss[warp] = s; sqs[warp] = sq; }
    __syncthreads();
    float S  = ss[0]  + ss[1]  + ss[2]  + ss[3];
    float SQ = sqs[0] + sqs[1] + sqs[2] + sqs[3];
    float mean = S * (1.f / DMODEL);
    float var  = SQ * (1.f / DMODEL) - mean * mean;
    float rs   = rsqrtf(var + 1e-6f);
    float4 sc4 = ((const float4*)scale)[tid];
    float4 bi4 = ((const float4*)bias)[tid];
    float4 o;
    o.x = (v.x - mean) * rs * sc4.x + bi4.x;
    o.y = (v.y - mean) * rs * sc4.y + bi4.y;
    o.z = (v.z - mean) * rs * sc4.z + bi4.z;
    o.w = (v.w - mean) * rs * sc4.w + bi4.w;
    if (outf) ((float4*)(outf + (size_t)row * DMODEL))[tid] = o;
    uint2 h, l;
    split4(o, h, l);
    ((uint2*)(outh + (size_t)row * DMODEL))[tid] = h;
    ((uint2*)(outl + (size_t)row * DMODEL))[tid] = l;
}

// ============ fused double LayerNorm: LN2(LN1(x + a) + c) =====================
__global__ void ln2x_kernel(const float* __restrict__ xin, const float* __restrict__ add1,
                            const float* __restrict__ ctx, int ctx_ld,
                            const float* __restrict__ s1, const float* __restrict__ b1,
                            const float* __restrict__ s2, const float* __restrict__ b2,
                            float* __restrict__ outf,
                            __nv_bfloat16* __restrict__ outh, __nv_bfloat16* __restrict__ outl)
{
    const int row = blockIdx.x;
    const int tid = threadIdx.x;
    const int warp = tid >> 5, lane = tid & 31;
    __shared__ float ss[4], sqs[4];

    float4 v = ((const float4*)(xin + (size_t)row * DMODEL))[tid];
    float4 a = ((const float4*)(add1 + (size_t)row * DMODEL))[tid];
    v.x += a.x; v.y += a.y; v.z += a.z; v.w += a.w;

    {
        float s  = v.x + v.y + v.z + v.w;
        float sq = v.x * v.x + v.y * v.y + v.z * v.z + v.w * v.w;
#pragma unroll
        for (int o = 16; o > 0; o >>= 1) {
            s  += __shfl_xor_sync(~0u, s,  o);
            sq += __shfl_xor_sync(~0u, sq, o);
        }
        if (lane == 0) { ss[warp] = s; sqs[warp] = sq; }
        __syncthreads();
        float S  = ss[0]  + ss[1]  + ss[2]  + ss[3];
        float SQ = sqs[0] + sqs[1] + sqs[2] + sqs[3];
        float mean = S * (1.f / DMODEL);
        float var  = SQ * (1.f / DMODEL) - mean * mean;
        float rs   = rsqrtf(var + 1e-6f);
        float4 sc4 = ((const float4*)s1)[tid];
        float4 bi4 = ((const float4*)b1)[tid];
        v.x = (v.x - mean) * rs * sc4.x + bi4.x;
        v.y = (v.y - mean) * rs * sc4.y + bi4.y;
        v.z = (v.z - mean) * rs * sc4.z + bi4.z;
        v.w = (v.w - mean) * rs * sc4.w + bi4.w;
        __syncthreads();
    }
    {
        float4 c = ((const float4*)(ctx + (size_t)row * ctx_ld))[tid];
        v.x += c.x; v.y += c.y; v.z += c.z; v.w += c.w;
        float s  = v.x + v.y + v.z + v.w;
        float sq = v.x * v.x + v.y * v.y + v.z * v.z + v.w * v.w;
#pragma unroll
        for (int o = 16; o > 0; o >>= 1) {
            s  += __shfl_xor_sync(~0u, s,  o);
            sq += __shfl_xor_sync(~0u, sq, o);
        }
        if (lane == 0) { ss[warp] = s; sqs[warp] = sq; }
        __syncthreads();
        float S  = ss[0]  + ss[1]  + ss[2]  + ss[3];
        float SQ = sqs[0] + sqs[1] + sqs[2] + sqs[3];
        float mean = S * (1.f / DMODEL);
        float var  = SQ * (1.f / DMODEL) - mean * mean;
        float rs   = rsqrtf(var + 1e-6f);
        float4 sc4 = ((const float4*)s2)[tid];
        float4 bi4 = ((const float4*)b2)[tid];
        v.x = (v.x - mean) * rs * sc4.x + bi4.x;
        v.y = (v.y - mean) * rs * sc4.y + bi4.y;
        v.z = (v.z - mean) * rs * sc4.z + bi4.z;
        v.w = (v.w - mean) * rs * sc4.w + bi4.w;
    }
    ((float4*)(outf + (size_t)row * DMODEL))[tid] = v;
    uint2 h, l;
    split4(v, h, l);
    ((uint2*)(outh + (size_t)row * DMODEL))[tid] = h;
    ((uint2*)(outl + (size_t)row * DMODEL))[tid] = l;
}

// ============ winner gather ===================================================
__global__ void gather_kernel(const unsigned long long* __restrict__ best,
                              const float* __restrict__ vs, const float* __restrict__ ss,
                              float* __restrict__ vout, float* __restrict__ sout)
{
    const int n = blockIdx.x;
    const int lane = threadIdx.x;
    const unsigned long long key = best[n];
    const int idx = (int)(~(unsigned int)(key & 0xFFFFFFFFull));
    vout[(size_t)n * OUTD + lane] = vs[(size_t)n * (NSLOTS * OUTD) + (size_t)idx * OUTD + lane];
    if (lane == 0) sout[n] = ss[(size_t)n * NSLOTS + idx];
}

// ---------------- host-side wrapper ----------------
struct Bufs {
    __nv_bfloat16 *bthi, *btlo;
};
static void tc_gemm(const __nv_bfloat16* Ah, const __nv_bfloat16* Al,
                    const float* W, const float* bias,
                    float* Cf, __nv_bfloat16* Chi, __nv_bfloat16* Clo,
                    int M, int N, int K, int relu, const Bufs& bf)
{
    transpose_convert_kernel<<<dim3(N / 32, K / 32), 256>>>(W, bf.bthi, bf.btlo, K, N);
    gemm_bb_kernel<<<dim3(N / 256, M / 128), 512, GEMM_SMEM>>>(
        Ah, Al, bf.bthi, bf.btlo, bias, Cf, Chi, Clo, M, N, K, relu,
        nullptr, nullptr, nullptr, 0);
}

extern "C" void kernel_launch(void* const* d_in, const int* in_sizes, int n_in,
                              void* d_out, int out_size)
{
    const float* s_in  = (const float*)d_in[0];
    const float* x_in  = (const float*)d_in[1];
    const float* t_in  = (const float*)d_in[2];
    const float* Wq    = (const float*)d_in[3];
    const float* Wk    = (const float*)d_in[4];
    const float* Wv    = (const float*)d_in[5];
    const float* Wo    = (const float*)d_in[6];
    const float* cWv   = (const float*)d_in[9];
    const float* cWo   = (const float*)d_in[10];
    const float* ln1_s = (const float*)d_in[11];
    const float* ln1_b = (const float*)d_in[12];
    const float* ln2_s = (const float*)d_in[13];
    const float* ln2_b = (const float*)d_in[14];
    const float* ln3_s = (const float*)d_in[15];
    const float* ln3_b = (const float*)d_in[16];
    const float* W1    = (const float*)d_in[17];
    const float* b1    = (const float*)d_in[18];
    const float* W2    = (const float*)d_in[19];
    const float* b2    = (const float*)d_in[20];
    const float* lnf_s = (const float*)d_in[21];
    const float* lnf_b = (const float*)d_in[22];
    const float* Wout  = (const float*)d_in[23];
    const float* bout  = (const float*)d_in[24];
    const float* W_vs  = (const float*)d_in[25];
    const float* b_vs  = (const float*)d_in[26];
    const float* W_ss  = (const float*)d_in[27];
    const float* b_ss  = (const float*)d_in[28];
    float* out = (float*)d_out;

    float *dec, *tmp2, *ctx, *vs, *bcomb;
    unsigned long long* best;
    __nv_bfloat16 *dech, *decl, *qkvh, *qkvl, *obh, *obl, *th, *tl;
    __nv_bfloat16 *ffh, *ffl, *keysh, *keysl, *vthi, *vtlo;
    __nv_bfloat16 *xbth, *xbtl, *cvh, *cvl;
    Bufs bf;
    cudaGetSymbolAddress((void**)&dec,  g_dec);
    cudaGetSymbolAddress((void**)&tmp2, g_tmp2);
    cudaGetSymbolAddress((void**)&ctx,  g_ctx);
    cudaGetSymbolAddress((void**)&vs,   g_vs);
    cudaGetSymbolAddress((void**)&bcomb,g_bcomb);
    cudaGetSymbolAddress((void**)&best, g_best);
    cudaGetSymbolAddress((void**)&dech, g_dech);
    cudaGetSymbolAddress((void**)&decl, g_decl);
    cudaGetSymbolAddress((void**)&qkvh, g_qkvh);
    cudaGetSymbolAddress((void**)&qkvl, g_qkvl);
    cudaGetSymbolAddress((void**)&obh,  g_obh);
    cudaGetSymbolAddress((void**)&obl,  g_obl);
    cudaGetSymbolAddress((void**)&th,   g_th);
    cudaGetSymbolAddress((void**)&tl,   g_tl);
    cudaGetSymbolAddress((void**)&ffh,  g_ffh);
    cudaGetSymbolAddress((void**)&ffl,  g_ffl);
    cudaGetSymbolAddress((void**)&keysh,g_keysh);
    cudaGetSymbolAddress((void**)&keysl,g_keysl);
    cudaGetSymbolAddress((void**)&vthi, g_vthi);
    cudaGetSymbolAddress((void**)&vtlo, g_vtlo);
    cudaGetSymbolAddress((void**)&xbth, g_xbth);
    cudaGetSymbolAddress((void**)&xbtl, g_xbtl);
    cudaGetSymbolAddress((void**)&cvh,  g_cvh);
    cudaGetSymbolAddress((void**)&cvl,  g_cvl);
    cudaGetSymbolAddress((void**)&bf.bthi, g_bthi);
    cudaGetSymbolAddress((void**)&bf.btlo, g_btlo);

    cudaFuncSetAttribute(gemm_bb_kernel, cudaFuncAttributeMaxDynamicSharedMemorySize, GEMM_SMEM);
    cudaFuncSetAttribute(flash_attn,     cudaFuncAttributeMaxDynamicSharedMemorySize, FA_SMEM);

    cudaMemsetAsync(best, 0, NTOK * sizeof(unsigned long long));
    split_copy_kernel<<<NTOK * DMODEL / 1024, 256>>>(s_in, dec, dech, decl);
    split_kernel<<<NTOK * DMODEL / 1024, 256>>>(t_in, th, tl);
    split_kernel<<<2 * DMODEL * DMODEL / 1024, 256>>>(cWv, cvh, cvl);

    // ---- hoisted cross-attention: ctx = t @ [Mx0 | Mx1] ----
    for (int l = 0; l < 2; l++) {
        const size_t wo = (size_t)l * DMODEL * DMODEL;
        tc_gemm(cvh + wo, cvl + wo, cWo + wo, nullptr, tmp2, nullptr, nullptr,
                DMODEL, DMODEL, DMODEL, 0, bf);
        transpose_convert_kernel<<<dim3(16, 16), 256>>>(
            tmp2, xbth + (size_t)l * DMODEL * DMODEL, xbtl + (size_t)l * DMODEL * DMODEL,
            DMODEL, DMODEL);
    }
    gemm_bb_kernel<<<dim3(1024 / 256, NTOK / 128), 512, GEMM_SMEM>>>(
        th, tl, xbth, xbtl, nullptr, ctx, nullptr, nullptr,
        NTOK, 1024, DMODEL, 0, nullptr, nullptr, nullptr, 0);

    for (int l = 0; l < 2; l++) {
        const size_t wo = (size_t)l * DMODEL * DMODEL;
        // ---- fused QKV projection (N=1536) ----
        transpose_convert3_kernel<<<dim3(16, 16, 3), 256>>>(
            Wq + wo, Wk + wo, Wv + wo, bf.bthi, bf.btlo, DMODEL, DMODEL);
        gemm_bb_kernel<<<dim3(QKVN / 256, NTOK / 128), 512, GEMM_SMEM>>>(
            dech, decl, bf.bthi, bf.btlo, nullptr, nullptr, qkvh, qkvl,
            NTOK, QKVN, DMODEL, 0, nullptr, nullptr, nullptr, 0);
        // ---- fused flash attention ----
        vt_convert_bf<<<dim3(32, 2, 64), 256>>>(qkvh + 1024, qkvl + 1024, QKVN, vthi, vtlo);
        flash_attn<<<dim3(8, 64), 256, FA_SMEM>>>(
            qkvh, qkvl, qkvh + 512, qkvl + 512, QKVN, vthi, vtlo, obh, obl);
        tc_gemm(obh, obl, Wo + wo, nullptr, tmp2, nullptr, nullptr, NTOK, DMODEL, DMODEL, 0, bf);
        // ---- fused ln1 + cross-residual + ln2 ----
        ln2x_kernel<<<NTOK, 128>>>(dec, tmp2, ctx + (size_t)l * 512, 1024,
                                   ln1_s + l * DMODEL, ln1_b + l * DMODEL,
                                   ln2_s + l * DMODEL, ln2_b + l * DMODEL,
                                   dec, dech, decl);
        // ---- FFN ----
        tc_gemm(dech, decl, W1 + (size_t)l * DMODEL * FFDIM, b1 + (size_t)l * FFDIM,
                nullptr, ffh, ffl, NTOK, FFDIM, DMODEL, 1, bf);
        tc_gemm(ffh, ffl, W2 + (size_t)l * FFDIM * DMODEL, b2 + (size_t)l * DMODEL,
                tmp2, nullptr, nullptr, NTOK, DMODEL, FFDIM, 0, bf);
        ln_kernel<<<NTOK, 128>>>(dec, tmp2, DMODEL,
                                 ln3_s + l * DMODEL, ln3_b + l * DMODEL, dec, dech, decl);
    }

    // ---- final head ----
    ln_kernel<<<NTOK, 128>>>(dec, nullptr, 0, lnf_s, lnf_b, nullptr, obh, obl);
    tc_gemm(obh, obl, Wout, bout, tmp2, nullptr, nullptr, NTOK, DMODEL, DMODEL, 0, bf);
    softmax_keys_kernel<<<NTOK, 256>>>(tmp2, keysh, keysl);

    float* out_v  = out;
    float* out_s  = out + 262144;
    float* out_ss = out + 262144 + 8192;

    // ---- merged scoring head: [W_ss | W_vs], N = 16896, split epilogue ----
    cudaMemcpyAsync(bcomb, b_ss, NSLOTS * sizeof(float), cudaMemcpyDeviceToDevice);
    cudaMemcpyAsync(bcomb + NSLOTS, b_vs, NSLOTS * OUTD * sizeof(float), cudaMemcpyDeviceToDevice);
    transpose_convert_kernel<<<dim3(NSLOTS / 32, DMODEL / 32), 256>>>(
        W_ss, bf.bthi, bf.btlo, DMODEL, NSLOTS);
    transpose_convert_kernel<<<dim3(NSLOTS * OUTD / 32, DMODEL / 32), 256>>>(
        W_vs, bf.bthi + (size_t)NSLOTS * DMODEL, bf.btlo + (size_t)NSLOTS * DMODEL,
        DMODEL, NSLOTS * OUTD);
    gemm_bb_kernel<<<dim3(HEADN / 256, NTOK / 128), 512, GEMM_SMEM>>>(
        keysh, keysl, bf.bthi, bf.btlo, bcomb, vs, nullptr, nullptr,
        NTOK, HEADN, DMODEL, 0, x_in, best, out_ss, NSLOTS);
    gather_kernel<<<NTOK, 32>>>(best, vs, out_ss, out_v, out_s);
}

// round 14
// speedup vs baseline: 1.0489x; 1.0048x over previous
#include <cuda_runtime.h>
#include <cuda_bf16.h>
#include <math.h>
#include <stdint.h>

#define NTOK   8192
#define DMODEL 512
#define HEADS  8
#define HD     64
#define SEQ    1024
#define FFDIM  2048
#define NSLOTS 512
#define OUTD   32
#define QKVN   1536
#define HEADN  16896
#define NEGF   (-3.4028234663852886e38f)

// ---------------- static scratch ----------------
__device__ float g_dec [NTOK * DMODEL];
__device__ float g_tmp2[NTOK * DMODEL];
__device__ float g_ctx [NTOK * 1024];
__device__ float g_vs  [(size_t)NTOK * NSLOTS * OUTD];
__device__ float g_bcomb[HEADN];
__device__ unsigned long long g_best[NTOK];
__device__ __nv_bfloat16 g_dech[NTOK * DMODEL], g_decl[NTOK * DMODEL];
__device__ __nv_bfloat16 g_qkvh[NTOK * QKVN],  g_qkvl[NTOK * QKVN];
__device__ __nv_bfloat16 g_obh [NTOK * DMODEL], g_obl [NTOK * DMODEL];
__device__ __nv_bfloat16 g_th  [NTOK * DMODEL], g_tl  [NTOK * DMODEL];
__device__ __nv_bfloat16 g_ffh [NTOK * FFDIM],  g_ffl [NTOK * FFDIM];
__device__ __nv_bfloat16 g_keysh[NTOK * DMODEL], g_keysl[NTOK * DMODEL];
__device__ __nv_bfloat16 g_vthi[64 * HD * SEQ], g_vtlo[64 * HD * SEQ];
__device__ __nv_bfloat16 g_bthi[(size_t)DMODEL * HEADN], g_btlo[(size_t)DMODEL * HEADN];
__device__ __nv_bfloat16 g_xbth[1024 * DMODEL], g_xbtl[1024 * DMODEL];
__device__ __nv_bfloat16 g_cvh[2 * DMODEL * DMODEL], g_cvl[2 * DMODEL * DMODEL];

__device__ __forceinline__ uint32_t smem_u32(const void* p) {
    uint32_t a;
    asm("{ .reg .u64 t; cvta.to.shared.u64 t, %1; cvt.u32.u64 %0, t; }" : "=r"(a) : "l"(p));
    return a;
}
__device__ __forceinline__ uint32_t pack2(__nv_bfloat16 a, __nv_bfloat16 b) {
    return (uint32_t)__bfloat16_as_ushort(a) | ((uint32_t)__bfloat16_as_ushort(b) << 16);
}
__device__ __forceinline__ void cp16(uint32_t dst, const void* src) {
    asm volatile("cp.async.cg.shared.global [%0], [%1], 16;" :: "r"(dst), "l"(src) : "memory");
}
__device__ __forceinline__ void cp_commit() {
    asm volatile("cp.async.commit_group;" ::: "memory");
}
__device__ __forceinline__ void cp_wait0() {
    asm volatile("cp.async.wait_group 0;" ::: "memory");
}
__device__ __forceinline__ void split4(float4 v, uint2& hi, uint2& lo) {
    __nv_bfloat16 hx = __float2bfloat16(v.x), hy = __float2bfloat16(v.y);
    __nv_bfloat16 hz = __float2bfloat16(v.z), hw = __float2bfloat16(v.w);
    __nv_bfloat16 lx = __float2bfloat16(v.x - __bfloat162float(hx));
    __nv_bfloat16 ly = __float2bfloat16(v.y - __bfloat162float(hy));
    __nv_bfloat16 lz = __float2bfloat16(v.z - __bfloat162float(hz));
    __nv_bfloat16 lw = __float2bfloat16(v.w - __bfloat162float(hw));
    hi = make_uint2(pack2(hx, hy), pack2(hz, hw));
    lo = make_uint2(pack2(lx, ly), pack2(lz, lw));
}
__device__ __forceinline__ unsigned long long score_key(float s, int slot) {
    unsigned int u = __float_as_uint(s);
    u = (u & 0x80000000u) ? ~u : (u | 0x80000000u);
    return ((unsigned long long)u << 32) | (unsigned int)(~slot);
}

#define LDMX4(r0, r1, r2, r3, addr) \
    asm volatile("ldmatrix.sync.aligned.m8n8.x4.shared.b16 {%0,%1,%2,%3}, [%4];" \
        : "=r"(r0), "=r"(r1), "=r"(r2), "=r"(r3) : "r"(addr))

#define MMA_BF16(c, a, b) \
    asm volatile("mma.sync.aligned.m16n8k16.row.col.f32.bf16.bf16.f32 " \
        "{%0,%1,%2,%3}, {%4,%5,%6,%7}, {%8,%9}, {%0,%1,%2,%3};" \
        : "+f"((c)[0]), "+f"((c)[1]), "+f"((c)[2]), "+f"((c)[3]) \
        : "r"((a)[0]), "r"((a)[1]), "r"((a)[2]), "r"((a)[3]), "r"((b)[0]), "r"((b)[1]))

#define LDP 72
#define T128 (128 * LDP * 2)
#define T256 (256 * LDP * 2)
#define GB_STAGE (2 * T128 + 2 * T256)
#define GEMM_SMEM (2 * GB_STAGE)
#define FA_LDPV 136
#define FA_VT (64 * FA_LDPV * 2)
#define FA_STAGE (2 * T128 + 2 * FA_VT)
#define FA_SMEM (2 * T128 + 2 * FA_STAGE)

// ============ split-bf16 HMMA GEMM: CTA 128x256, 16 warps of 64x32 (champion) ==
__global__ __launch_bounds__(512, 1)
void gemm_bb_kernel(const __nv_bfloat16* __restrict__ Ahi, const __nv_bfloat16* __restrict__ Alo,
                    const __nv_bfloat16* __restrict__ Bhi, const __nv_bfloat16* __restrict__ Blo,
                    const float* __restrict__ bias,
                    float* __restrict__ Cf, __nv_bfloat16* __restrict__ Chi,
                    __nv_bfloat16* __restrict__ Clo,
                    int M, int N, int K, int relu,
                    const float* __restrict__ xsc, unsigned long long* __restrict__ best,
                    float* __restrict__ Cf2, int split)
{
    extern __shared__ char smem[];
    const int tid  = threadIdx.x;
    const int lane = tid & 31, wid = tid >> 5;
    const int wm = wid >> 3;
    const int wn = wid & 7;
    const size_t brow = (size_t)blockIdx.y * 128;
    const size_t bcol = (size_t)blockIdx.x * 256;
    const int seg = tid & 7, r0 = tid >> 3;

    const int NP = K >> 6;

    auto load_panel = [&](int p, int s) {
        char* base = smem + s * GB_STAGE;
        const size_t ka = (size_t)p * 64 + seg * 8;
#pragma unroll
        for (int hf = 0; hf < 2; hf++) {
            const int r = r0 + hf * 64;
            const uint32_t dst = smem_u32(base + (r * LDP + seg * 8) * 2);
            cp16(dst,        Ahi + (brow + r) * K + ka);
            cp16(dst + T128, Alo + (brow + r) * K + ka);
        }
#pragma unroll
        for (int i = 0; i < 4; i++) {
            const int r = r0 + i * 64;
            const uint32_t dst = smem_u32(base + 2 * T128 + (r * LDP + seg * 8) * 2);
            cp16(dst,        Bhi + (bcol + r) * K + ka);
            cp16(dst + T256, Blo + (bcol + r) * K + ka);
        }
        cp_commit();
    };

    load_panel(0, 0);

    float acc[4][4][4];
#pragma unroll
    for (int i = 0; i < 4; i++)
#pragma unroll
        for (int j = 0; j < 4; j++)
#pragma unroll
            for (int c = 0; c < 4; c++) acc[i][j][c] = 0.f;

    const int lm_r = (lane & 7) + ((lane >> 3) & 1) * 8;
    const int lm_c = ((lane >> 4) & 1) * 8;
    const int lb_r = (lane & 7) + ((lane >> 4) & 1) * 8;
    const int lb_c = ((lane >> 3) & 1) * 8;

    for (int p = 0; p < NP; p++) {
        const int s = p & 1;
        cp_wait0();
        __syncthreads();
        if (p + 1 < NP) load_panel(p + 1, s ^ 1);

        const __nv_bfloat16* sAh = (const __nv_bfloat16*)(smem + s * GB_STAGE);
        const __nv_bfloat16* sAl = (const __nv_bfloat16*)((char*)sAh + T128);
        const __nv_bfloat16* sBh = (const __nv_bfloat16*)((char*)sAh + 2 * T128);
        const __nv_bfloat16* sBl = (const __nv_bfloat16*)((char*)sAh + 2 * T128 + T256);

#pragma unroll
        for (int ks = 0; ks < 4; ks++) {
            const int k0 = ks * 16;
            uint32_t Ah[4][4], Al[4][4], Bh[4][2], Bl[4][2];
#pragma unroll
            for (int mi = 0; mi < 4; mi++) {
                const int r = wm * 64 + mi * 16 + lm_r;
                LDMX4(Ah[mi][0], Ah[mi][1], Ah[mi][2], Ah[mi][3], smem_u32(sAh + r * LDP + k0 + lm_c));
                LDMX4(Al[mi][0], Al[mi][1], Al[mi][2], Al[mi][3], smem_u32(sAl + r * LDP + k0 + lm_c));
            }
#pragma unroll
            for (int nio = 0; nio < 2; nio++) {
                const int r = wn * 32 + nio * 16 + lb_r;
                LDMX4(Bh[2*nio][0], Bh[2*nio][1], Bh[2*nio+1][0], Bh[2*nio+1][1],
                      smem_u32(sBh + r * LDP + k0 + lb_c));
                LDMX4(Bl[2*nio][0], Bl[2*nio][1], Bl[2*nio+1][0], Bl[2*nio+1][1],
                      smem_u32(sBl + r * LDP + k0 + lb_c));
            }
#pragma unroll
            for (int mi = 0; mi < 4; mi++)
#pragma unroll
                for (int ni = 0; ni < 4; ni++) MMA_BF16(acc[mi][ni], Ah[mi], Bh[ni]);
#pragma unroll
            for (int mi = 0; mi < 4; mi++)
#pragma unroll
                for (int ni = 0; ni < 4; ni++) MMA_BF16(acc[mi][ni], Ah[mi], Bl[ni]);
#pragma unroll
            for (int mi = 0; mi < 4; mi++)
#pragma unroll
                for (int ni = 0; ni < 4; ni++) MMA_BF16(acc[mi][ni], Al[mi], Bh[ni]);
        }
    }

    const int g = lane >> 2, t = lane & 3;
    const int tile_col = (int)bcol + wn * 32;
    const bool lo_region = (split > 0) && (tile_col < split);
    const int ldv = (split > 0) ? (N - split) : N;
#pragma unroll
    for (int mi = 0; mi < 4; mi++) {
        const size_t rm = brow + wm * 64 + mi * 16 + g;
        float dA = 0.f, sA2 = 0.f, dB = 0.f, sB2 = 0.f;
#pragma unroll
        for (int ni = 0; ni < 4; ni++) {
            const size_t cn = bcol + wn * 32 + ni * 8 + 2 * t;
            float b0 = 0.f, b1 = 0.f;
            if (bias) { b0 = bias[cn]; b1 = bias[cn + 1]; }
            float v00 = acc[mi][ni][0] + b0, v01 = acc[mi][ni][1] + b1;
            float v10 = acc[mi][ni][2] + b0, v11 = acc[mi][ni][3] + b1;
            if (relu) {
                v00 = fmaxf(v00, 0.f); v01 = fmaxf(v01, 0.f);
                v10 = fmaxf(v10, 0.f); v11 = fmaxf(v11, 0.f);
            }
            if (lo_region) {
                *(float2*)(Cf2 + rm * split + cn)       = make_float2(v00, v01);
                *(float2*)(Cf2 + (rm + 8) * split + cn) = make_float2(v10, v11);
            } else if (Cf) {
                const size_t cv = cn - split;
                *(float2*)(Cf + rm * ldv + cv)       = make_float2(v00, v01);
                *(float2*)(Cf + (rm + 8) * ldv + cv) = make_float2(v10, v11);
            }
            if (Chi) {
                __nv_bfloat16 h00 = __float2bfloat16(v00), h01 = __float2bfloat16(v01);
                __nv_bfloat16 h10 = __float2bfloat16(v10), h11 = __float2bfloat16(v11);
                *(uint32_t*)(Chi + rm * N + cn)       = pack2(h00, h01);
                *(uint32_t*)(Chi + (rm + 8) * N + cn) = pack2(h10, h11);
                *(uint32_t*)(Clo + rm * N + cn)       =
                    pack2(__float2bfloat16(v00 - __bfloat162float(h00)),
                          __float2bfloat16(v01 - __bfloat162float(h01)));
                *(uint32_t*)(Clo + (rm + 8) * N + cn) =
                    pack2(__float2bfloat16(v10 - __bfloat162float(h10)),
                          __float2bfloat16(v11 - __bfloat162float(h11)));
            }
            if (xsc && !lo_region) {
                const int o = ni * 8 + 2 * t;
                float xa0 = xsc[rm * OUTD + o],       xa1 = xsc[rm * OUTD + o + 1];
                float xb0 = xsc[(rm + 8) * OUTD + o], xb1 = xsc[(rm + 8) * OUTD + o + 1];
                dA += v00 * xa0 + v01 * xa1;  sA2 += v00 * v00 + v01 * v01;
                dB += v10 * xb0 + v11 * xb1;  sB2 += v10 * v10 + v11 * v11;
            }
        }
        if (xsc && !lo_region) {
#pragma unroll
            for (int m = 1; m <= 2; m <<= 1) {
                dA  += __shfl_xor_sync(~0u, dA,  m);
                sA2 += __shfl_xor_sync(~0u, sA2, m);
                dB  += __shfl_xor_sync(~0u, dB,  m);
                sB2 += __shfl_xor_sync(~0u, sB2, m);
            }
            if (t == 0) {
                const int slot = (tile_col - split) >> 5;
                atomicMax(&best[rm],     score_key(dA * rsqrtf(sA2), slot));
                atomicMax(&best[rm + 8], score_key(dB * rsqrtf(sB2), slot));
            }
        }
    }
}

// ============ fused flash attention (__expf fast path) ========================
__global__ __launch_bounds__(256, 1)
void flash_attn(const __nv_bfloat16* __restrict__ Qh_, const __nv_bfloat16* __restrict__ Ql_,
                const __nv_bfloat16* __restrict__ Kh_, const __nv_bfloat16* __restrict__ Kl_,
                int ld,
                const __nv_bfloat16* __restrict__ Vth, const __nv_bfloat16* __restrict__ Vtl,
                __nv_bfloat16* __restrict__ Oh, __nv_bfloat16* __restrict__ Ol)
{
    extern __shared__ char smem[];
    const int qt = 7 - blockIdx.x;
    const int bh = blockIdx.y;
    const int b = bh >> 3, h = bh & 7;
    const int tid = threadIdx.x;
    const int lane = tid & 31, wid = tid >> 5;
    const int g = lane >> 2, t = lane & 3;

    auto load_chunk = [&](int kc, int s) {
        char* base = smem + 2 * T128 + s * FA_STAGE;
        {
            const int seg = tid & 7, r0 = tid >> 3;
#pragma unroll
            for (int it = 0; it < 4; it++) {
                const int r = r0 + it * 32;
                const uint32_t dst = smem_u32(base + (r * LDP + seg * 8) * 2);
                const size_t off = ((size_t)(b * SEQ + kc * 128 + r) * ld) + h * HD + seg * 8;
                cp16(dst,        Kh_ + off);
                cp16(dst + T128, Kl_ + off);
            }
        }
        {
            const int seg = tid & 15, r0 = tid >> 4;
#pragma unroll
            for (int it = 0; it < 4; it++) {
                const int r = r0 + it * 16;
                const uint32_t dst = smem_u32(base + 2 * T128 + (r * FA_LDPV + seg * 8) * 2);
                const size_t off = ((size_t)bh * HD + r) * SEQ + kc * 128 + seg * 8;
                cp16(dst,         Vth + off);
                cp16(dst + FA_VT, Vtl + off);
            }
        }
        cp_commit();
    };

    {
        const int seg = tid & 7, r0 = tid >> 3;
#pragma unroll
        for (int it = 0; it < 4; it++) {
            const int r = r0 + it * 32;
            const uint32_t dst = smem_u32(smem + (r * LDP + seg * 8) * 2);
            const size_t off = ((size_t)(b * SEQ + qt * 128 + r) * ld) + h * HD + seg * 8;
            cp16(dst,        Qh_ + off);
            cp16(dst + T128, Ql_ + off);
        }
    }
    load_chunk(0, 0);

    const int lm_r = (lane & 7) + ((lane >> 3) & 1) * 8;
    const int lm_c = ((lane >> 4) & 1) * 8;
    const int lb_r = (lane & 7) + ((lane >> 4) & 1) * 8;
    const int lb_c = ((lane >> 3) & 1) * 8;

    uint32_t Qh[4][4], Ql[4][4];
    float o[8][4];
#pragma unroll
    for (int i = 0; i < 8; i++)
#pragma unroll
        for (int c = 0; c < 4; c++) o[i][c] = 0.f;
    float m0 = -INFINITY, m1 = -INFINITY, l0 = 0.f, l1 = 0.f;
    const int row0 = qt * 128 + wid * 16 + g;
    const int row1 = row0 + 8;

    for (int kc = 0; kc <= qt; kc++) {
        const int s = kc & 1;
        cp_wait0();
        __syncthreads();
        if (kc == 0) {
            const __nv_bfloat16* sQh = (const __nv_bfloat16*)smem;
            const __nv_bfloat16* sQl = (const __nv_bfloat16*)(smem + T128);
#pragma unroll
            for (int kf = 0; kf < 4; kf++) {
                LDMX4(Qh[kf][0], Qh[kf][1], Qh[kf][2], Qh[kf][3],
                      smem_u32(sQh + (wid * 16 + lm_r) * LDP + kf * 16 + lm_c));
                LDMX4(Ql[kf][0], Ql[kf][1], Ql[kf][2], Ql[kf][3],
                      smem_u32(sQl + (wid * 16 + lm_r) * LDP + kf * 16 + lm_c));
            }
        }
        if (kc < qt) load_chunk(kc + 1, s ^ 1);

        const char* base = smem + 2 * T128 + s * FA_STAGE;
        const __nv_bfloat16* sKh = (const __nv_bfloat16*)base;
        const __nv_bfloat16* sKl = (const __nv_bfloat16*)(base + T128);
        const __nv_bfloat16* sVh = (const __nv_bfloat16*)(base + 2 * T128);
        const __nv_bfloat16* sVl = (const __nv_bfloat16*)(base + 2 * T128 + FA_VT);

        float sacc[16][4];
#pragma unroll
        for (int j = 0; j < 16; j++)
#pragma unroll
            for (int c = 0; c < 4; c++) sacc[j][c] = 0.f;

#pragma unroll
        for (int ks = 0; ks < 4; ks++) {
#pragma unroll
            for (int grp = 0; grp < 2; grp++) {
                uint32_t Bh[8][2], Bl[8][2];
#pragma unroll
                for (int i = 0; i < 4; i++) {
                    const int nt = grp * 4 + i;
                    LDMX4(Bh[2*i][0], Bh[2*i][1], Bh[2*i+1][0], Bh[2*i+1][1],
                          smem_u32(sKh + (nt * 16 + lb_r) * LDP + ks * 16 + lb_c));
                    LDMX4(Bl[2*i][0], Bl[2*i][1], Bl[2*i+1][0], Bl[2*i+1][1],
                          smem_u32(sKl + (nt * 16 + lb_r) * LDP + ks * 16 + lb_c));
                }
#pragma unroll
                for (int i = 0; i < 8; i++) MMA_BF16(sacc[grp*8+i], Qh[ks], Bh[i]);
#pragma unroll
                for (int i = 0; i < 8; i++) MMA_BF16(sacc[grp*8+i], Qh[ks], Bl[i]);
#pragma unroll
                for (int i = 0; i < 8; i++) MMA_BF16(sacc[grp*8+i], Ql[ks], Bh[i]);
            }
        }

        const bool diag = (kc == qt);
        float mx0 = -INFINITY, mx1 = -INFINITY;
#pragma unroll
        for (int j = 0; j < 16; j++) {
            const int col = kc * 128 + 8 * j + 2 * t;
            float s0 = sacc[j][0] * 0.125f;
            float s1 = sacc[j][1] * 0.125f;
            float s2 = sacc[j][2] * 0.125f;
            float s3 = sacc[j][3] * 0.125f;
            if (diag) {
                if (col     > row0) s0 = NEGF;
                if (col + 1 > row0) s1 = NEGF;
                if (col     > row1) s2 = NEGF;
                if (col + 1 > row1) s3 = NEGF;
            }
            sacc[j][0] = s0; sacc[j][1] = s1; sacc[j][2] = s2; sacc[j][3] = s3;
            mx0 = fmaxf(mx0, fmaxf(s0, s1));
            mx1 = fmaxf(mx1, fmaxf(s2, s3));
        }
        mx0 = fmaxf(mx0, __shfl_xor_sync(~0u, mx0, 1));
        mx0 = fmaxf(mx0, __shfl_xor_sync(~0u, mx0, 2));
        mx1 = fmaxf(mx1, __shfl_xor_sync(~0u, mx1, 1));
        mx1 = fmaxf(mx1, __shfl_xor_sync(~0u, mx1, 2));
        const float mn0 = fmaxf(m0, mx0), mn1 = fmaxf(m1, mx1);
        const float f0 = __expf(m0 - mn0), f1 = __expf(m1 - mn1);
        float rs0 = 0.f, rs1 = 0.f;
#pragma unroll
        for (int j = 0; j < 16; j++) {
            float p0 = __expf(sacc[j][0] - mn0);
            float p1 = __expf(sacc[j][1] - mn0);
            float p2 = __expf(sacc[j][2] - mn1);
            float p3 = __expf(sacc[j][3] - mn1);
            sacc[j][0] = p0; sacc[j][1] = p1; sacc[j][2] = p2; sacc[j][3] = p3;
            rs0 += p0 + p1; rs1 += p2 + p3;
        }
        rs0 += __shfl_xor_sync(~0u, rs0, 1);
        rs0 += __shfl_xor_sync(~0u, rs0, 2);
        rs1 += __shfl_xor_sync(~0u, rs1, 1);
        rs1 += __shfl_xor_sync(~0u, rs1, 2);
        l0 = l0 * f0 + rs0;
        l1 = l1 * f1 + rs1;
        m0 = mn0; m1 = mn1;
#pragma unroll
        for (int ni = 0; ni < 8; ni++) {
            o[ni][0] *= f0; o[ni][1] *= f0; o[ni][2] *= f1; o[ni][3] *= f1;
        }

#pragma unroll
        for (int kf = 0; kf < 8; kf++) {
            const int j0 = 2 * kf, j1 = 2 * kf + 1;
            uint32_t Pfh[4], Pfl[4];
            {
                __nv_bfloat16 a0 = __float2bfloat16(sacc[j0][0]);
                __nv_bfloat16 a1 = __float2bfloat16(sacc[j0][1]);
                __nv_bfloat16 a2 = __float2bfloat16(sacc[j0][2]);
                __nv_bfloat16 a3 = __float2bfloat16(sacc[j0][3]);
                __nv_bfloat16 a4 = __float2bfloat16(sacc[j1][0]);
                __nv_bfloat16 a5 = __float2bfloat16(sacc[j1][1]);
                __nv_bfloat16 a6 = __float2bfloat16(sacc[j1][2]);
                __nv_bfloat16 a7 = __float2bfloat16(sacc[j1][3]);
                Pfh[0] = pack2(a0, a1); Pfh[1] = pack2(a2, a3);
                Pfh[2] = pack2(a4, a5); Pfh[3] = pack2(a6, a7);
                Pfl[0] = pack2(__float2bfloat16(sacc[j0][0] - __bfloat162float(a0)),
                               __float2bfloat16(sacc[j0][1] - __bfloat162float(a1)));
                Pfl[1] = pack2(__float2bfloat16(sacc[j0][2] - __bfloat162float(a2)),
                               __float2bfloat16(sacc[j0][3] - __bfloat162float(a3)));
                Pfl[2] = pack2(__float2bfloat16(sacc[j1][0] - __bfloat162float(a4)),
                               __float2bfloat16(sacc[j1][1] - __bfloat162float(a5)));
                Pfl[3] = pack2(__float2bfloat16(sacc[j1][2] - __bfloat162float(a6)),
                               __float2bfloat16(sacc[j1][3] - __bfloat162float(a7)));
            }
            uint32_t Vh[8][2], Vl[8][2];
#pragma unroll
            for (int i = 0; i < 4; i++) {
                LDMX4(Vh[2*i][0], Vh[2*i][1], Vh[2*i+1][0], Vh[2*i+1][1],
                      smem_u32(sVh + (i * 16 + lb_r) * FA_LDPV + kf * 16 + lb_c));
                LDMX4(Vl[2*i][0], Vl[2*i][1], Vl[2*i+1][0], Vl[2*i+1][1],
                      smem_u32(sVl + (i * 16 + lb_r) * FA_LDPV + kf * 16 + lb_c));
            }
#pragma unroll
            for (int ni = 0; ni < 8; ni++) MMA_BF16(o[ni], Pfh, Vh[ni]);
#pragma unroll
            for (int ni = 0; ni < 8; ni++) MMA_BF16(o[ni], Pfh, Vl[ni]);
#pragma unroll
            for (int ni = 0; ni < 8; ni++) MMA_BF16(o[ni], Pfl, Vh[ni]);
        }
    }

    const float inv0 = 1.f / l0, inv1 = 1.f / l1;
#pragma unroll
    for (int ni = 0; ni < 8; ni++) {
        const int d = h * HD + 8 * ni + 2 * t;
        const size_t off0 = (size_t)(b * SEQ + row0) * DMODEL + d;
        const size_t off1 = (size_t)(b * SEQ + row1) * DMODEL + d;
        float v00 = o[ni][0] * inv0, v01 = o[ni][1] * inv0;
        float v10 = o[ni][2] * inv1, v11 = o[ni][3] * inv1;
        __nv_bfloat16 h00 = __float2bfloat16(v00), h01 = __float2bfloat16(v01);
        __nv_bfloat16 h10 = __float2bfloat16(v10), h11 = __float2bfloat16(v11);
        *(uint32_t*)(Oh + off0) = pack2(h00, h01);
        *(uint32_t*)(Oh + off1) = pack2(h10, h11);
        *(uint32_t*)(Ol + off0) = pack2(__float2bfloat16(v00 - __bfloat162float(h00)),
                                        __float2bfloat16(v01 - __bfloat162float(h01)));
        *(uint32_t*)(Ol + off1) = pack2(__float2bfloat16(v10 - __bfloat162float(h10)),
                                        __float2bfloat16(v11 - __bfloat162float(h11)));
    }
}

// ============ keys softmax -> hi/lo (__expf fast path) ========================
__global__ __launch_bounds__(256, 1)
void softmax_keys_kernel(const float* __restrict__ src,
                         __nv_bfloat16* __restrict__ Kh, __nv_bfloat16* __restrict__ Kl)
{
    const int row = blockIdx.x;
    const int tid = threadIdx.x, warp = tid >> 5, lane = tid & 31;
    const float* p = src + (size_t)row * DMODEL;
    float v[2];
    float m = -INFINITY;
#pragma unroll
    for (int i = 0; i < 2; i++) { v[i] = p[tid + i * 256]; m = fmaxf(m, v[i]); }
#pragma unroll
    for (int o = 16; o > 0; o >>= 1) m = fmaxf(m, __shfl_xor_sync(~0u, m, o));
    __shared__ float smax[8], ssum[8];
    if (lane == 0) smax[warp] = m;
    __syncthreads();
    m = smax[0];
#pragma unroll
    for (int w = 1; w < 8; w++) m = fmaxf(m, smax[w]);
    float sum = 0.f;
#pragma unroll
    for (int i = 0; i < 2; i++) { v[i] = __expf(v[i] - m); sum += v[i]; }
#pragma unroll
    for (int o = 16; o > 0; o >>= 1) sum += __shfl_xor_sync(~0u, sum, o);
    if (lane == 0) ssum[warp] = sum;
    __syncthreads();
    sum = ssum[0];
#pragma unroll
    for (int w = 1; w < 8; w++) sum += ssum[w];
    const float inv = 1.f / sum;
#pragma unroll
    for (int i = 0; i < 2; i++) {
        float pv = v[i] * inv;
        __nv_bfloat16 h = __float2bfloat16(pv);
        Kh[(size_t)row * DMODEL + tid + i * 256] = h;
        Kl[(size_t)row * DMODEL + tid + i * 256] = __float2bfloat16(pv - __bfloat162float(h));
    }
}

// ============ V^T from bf16 hi/lo =============================================
__global__ void vt_convert_bf(const __nv_bfloat16* __restrict__ Vh,
                              const __nv_bfloat16* __restrict__ Vl, int ld,
                              __nv_bfloat16* __restrict__ Hi, __nv_bfloat16* __restrict__ Lo)
{
    __shared__ __nv_bfloat16 th[32][33], tl[32][33];
    const int k0 = blockIdx.x * 32, d0 = blockIdx.y * 32, bh = blockIdx.z;
    const int b = bh >> 3, h = bh & 7;
    const int tx = threadIdx.x & 31, ty = threadIdx.x >> 5;
#pragma unroll
    for (int j = 0; j < 32; j += 8) {
        const size_t src = (size_t)(b * SEQ + k0 + ty + j) * ld + h * HD + d0 + tx;
        th[ty + j][tx] = Vh[src];
        tl[ty + j][tx] = Vl[src];
    }
    __syncthreads();
#pragma unroll
    for (int j = 0; j < 32; j += 8) {
        const size_t o = ((size_t)bh * HD + d0 + ty + j) * SEQ + k0 + tx;
        Hi[o] = th[tx][ty + j];
        Lo[o] = tl[tx][ty + j];
    }
}

// ============ weight transpose + split ========================================
__global__ void transpose_convert_kernel(const float* __restrict__ W,
                                         __nv_bfloat16* __restrict__ Hi,
                                         __nv_bfloat16* __restrict__ Lo, int K, int N)
{
    __shared__ float t[32][33];
    const int k0 = blockIdx.y * 32, n0 = blockIdx.x * 32;
    const int tx = threadIdx.x & 31, ty = threadIdx.x >> 5;
#pragma unroll
    for (int j = 0; j < 32; j += 8)
        t[ty + j][tx] = W[(size_t)(k0 + ty + j) * N + n0 + tx];
    __syncthreads();
#pragma unroll
    for (int j = 0; j < 32; j += 8) {
        float v = t[tx][ty + j];
        __nv_bfloat16 h = __float2bfloat16(v);
        Hi[(size_t)(n0 + ty + j) * K + k0 + tx] = h;
        Lo[(size_t)(n0 + ty + j) * K + k0 + tx] = __float2bfloat16(v - __bfloat162float(h));
    }
}

__global__ void transpose_convert3_kernel(const float* __restrict__ W0,
                                          const float* __restrict__ W1,
                                          const float* __restrict__ W2,
                                          __nv_bfloat16* __restrict__ Hi,
                                          __nv_bfloat16* __restrict__ Lo, int K, int N)
{
    __shared__ float t[32][33];
    const int k0 = blockIdx.y * 32, n0 = blockIdx.x * 32, z = blockIdx.z;
    const float* W = (z == 0) ? W0 : (z == 1) ? W1 : W2;
    const int tx = threadIdx.x & 31, ty = threadIdx.x >> 5;
#pragma unroll
    for (int j = 0; j < 32; j += 8)
        t[ty + j][tx] = W[(size_t)(k0 + ty + j) * N + n0 + tx];
    __syncthreads();
#pragma unroll
    for (int j = 0; j < 32; j += 8) {
        float v = t[tx][ty + j];
        __nv_bfloat16 h = __float2bfloat16(v);
        const size_t o = (size_t)(z * N + n0 + ty + j) * K + k0 + tx;
        Hi[o] = h;
        Lo[o] = __float2bfloat16(v - __bfloat162float(h));
    }
}

// ============ elementwise split ===============================================
__global__ void split_kernel(const float* __restrict__ in,
                             __nv_bfloat16* __restrict__ hi, __nv_bfloat16* __restrict__ lo)
{
    const int i = blockIdx.x * 256 + threadIdx.x;
    float4 v = ((const float4*)in)[i];
    uint2 h, l;
    split4(v, h, l);
    ((uint2*)hi)[i] = h;
    ((uint2*)lo)[i] = l;
}

__global__ void split_copy_kernel(const float* __restrict__ in, float* __restrict__ outf,
                                  __nv_bfloat16* __restrict__ hi, __nv_bfloat16* __restrict__ lo)
{
    const int i = blockIdx.x * 256 + threadIdx.x;
    float4 v = ((const float4*)in)[i];
    ((float4*)outf)[i] = v;
    uint2 h, l;
    split4(v, h, l);
    ((uint2*)hi)[i] = h;
    ((uint2*)lo)[i] = l;
}

// ============ combined-bias assembly (replaces two memcpy nodes) ==============
__global__ void bias_concat_kernel(const float* __restrict__ b_ss,
                                   const float* __restrict__ b_vs,
                                   float* __restrict__ bcomb)
{
    const int i = blockIdx.x * 256 + threadIdx.x;
    if (i < NSLOTS) bcomb[i] = b_ss[i];
    if (i < NSLOTS * OUTD) bcomb[NSLOTS + i] = b_vs[i];
}

// ============ residual + LayerNorm ============================================
__global__ void ln_kernel(const float* __restrict__ xin, const float* __restrict__ res,
                          int res_ld,
                          const float* __restrict__ scale, const float* __restrict__ bias,
                          float* __restrict__ outf,
                          __nv_bfloat16* __restrict__ outh, __nv_bfloat16* __restrict__ outl)
{
    const int row = blockIdx.x;
    const int tid = threadIdx.x;
    float4 v = ((const float4*)(xin + (size_t)row * DMODEL))[tid];
    if (res) {
        float4 r = ((const float4*)(res + (size_t)row * res_ld))[tid];
        v.x += r.x; v.y += r.y; v.z += r.z; v.w += r.w;
    }
    float s  = v.x + v.y + v.z + v.w;
    float sq = v.x * v.x + v.y * v.y + v.z * v.z + v.w * v.w;
#pragma unroll
    for (int o = 16; o > 0; o >>= 1) {
        s  += __shfl_xor_sync(~0u, s,  o);
        sq += __shfl_xor_sync(~0u, sq, o);
    }
    __shared__ float ss[4], sqs[4];
    const int warp = tid >> 5, lane = tid & 31;
    if (lane == 0) { ss[warp] = s; sqs[warp] = sq; }
    __syncthreads();
    float S  = ss[0]  + ss[1]  + ss[2]  + ss[3];
    float SQ = sqs[0] + sqs[1] + sqs[2] + sqs[3];
    float mean = S * (1.f / DMODEL);
    float var  = SQ * (1.f / DMODEL) - mean * mean;
    float rs   = rsqrtf(var + 1e-6f);
    float4 sc4 = ((const float4*)scale)[tid];
    float4 bi4 = ((const float4*)bias)[tid];
    float4 o;
    o.x = (v.x - mean) * rs * sc4.x + bi4.x;
    o.y = (v.y - mean) * rs * sc4.y + bi4.y;
    o.z = (v.z - mean) * rs * sc4.z + bi4.z;
    o.w = (v.w - mean) * rs * sc4.w + bi4.w;
    if (outf) ((float4*)(outf + (size_t)row * DMODEL))[tid] = o;
    uint2 h, l;
    split4(o, h, l);
    ((uint2*)(outh + (size_t)row * DMODEL))[tid] = h;
    ((uint2*)(outl + (size_t)row * DMODEL))[tid] = l;
}

// ============ fused double LayerNorm: LN2(LN1(x + a) + c) =====================
__global__ void ln2x_kernel(const float* __restrict__ xin, const float* __restrict__ add1,
                            const float* __restrict__ ctx, int ctx_ld,
                            const float* __restrict__ s1, const float* __restrict__ b1,
                            const float* __restrict__ s2, const float* __restrict__ b2,
                            float* __restrict__ outf,
                            __nv_bfloat16* __restrict__ outh, __nv_bfloat16* __restrict__ outl)
{
    const int row = blockIdx.x;
    const int tid = threadIdx.x;
    const int warp = tid >> 5, lane = tid & 31;
    __shared__ float ss[4], sqs[4];

    float4 v = ((const float4*)(xin + (size_t)row * DMODEL))[tid];
    float4 a = ((const float4*)(add1 + (size_t)row * DMODEL))[tid];
    v.x += a.x; v.y += a.y; v.z += a.z; v.w += a.w;

    {
        float s  = v.x + v.y + v.z + v.w;
        float sq = v.x * v.x + v.y * v.y + v.z * v.z + v.w * v.w;
#pragma unroll
        for (int o = 16; o > 0; o >>= 1) {
            s  += __shfl_xor_sync(~0u, s,  o);
            sq += __shfl_xor_sync(~0u, sq, o);
        }
        if (lane == 0) { ss[warp] = s; sqs[warp] = sq; }
        __syncthreads();
        float S  = ss[0]  + ss[1]  + ss[2]  + ss[3];
        float SQ = sqs[0] + sqs[1] + sqs[2] + sqs[3];
        float mean = S * (1.f / DMODEL);
        float var  = SQ * (1.f / DMODEL) - mean * mean;
        float rs   = rsqrtf(var + 1e-6f);
        float4 sc4 = ((const float4*)s1)[tid];
        float4 bi4 = ((const float4*)b1)[tid];
        v.x = (v.x - mean) * rs * sc4.x + bi4.x;
        v.y = (v.y - mean) * rs * sc4.y + bi4.y;
        v.z = (v.z - mean) * rs * sc4.z + bi4.z;
        v.w = (v.w - mean) * rs * sc4.w + bi4.w;
        __syncthreads();
    }
    {
        float4 c = ((const float4*)(ctx + (size_t)row * ctx_ld))[tid];
        v.x += c.x; v.y += c.y; v.z += c.z; v.w += c.w;
        float s  = v.x + v.y + v.z + v.w;
        float sq = v.x * v.x + v.y * v.y + v.z * v.z + v.w * v.w;
#pragma unroll
        for (int o = 16; o > 0; o >>= 1) {
            s  += __shfl_xor_sync(~0u, s,  o);
            sq += __shfl_xor_sync(~0u, sq, o);
        }
        if (lane == 0) { ss[warp] = s; sqs[warp] = sq; }
        __syncthreads();
        float S  = ss[0]  + ss[1]  + ss[2]  + ss[3];
        float SQ = sqs[0] + sqs[1] + sqs[2] + sqs[3];
        float mean = S * (1.f / DMODEL);
        float var  = SQ * (1.f / DMODEL) - mean * mean;
        float rs   = rsqrtf(var + 1e-6f);
        float4 sc4 = ((const float4*)s2)[tid];
        float4 bi4 = ((const float4*)b2)[tid];
        v.x = (v.x - mean) * rs * sc4.x + bi4.x;
        v.y = (v.y - mean) * rs * sc4.y + bi4.y;
        v.z = (v.z - mean) * rs * sc4.z + bi4.z;
        v.w = (v.w - mean) * rs * sc4.w + bi4.w;
    }
    ((float4*)(outf + (size_t)row * DMODEL))[tid] = v;
    uint2 h, l;
    split4(v, h, l);
    ((uint2*)(outh + (size_t)row * DMODEL))[tid] = h;
    ((uint2*)(outl + (size_t)row * DMODEL))[tid] = l;
}

// ============ winner gather ===================================================
__global__ void gather_kernel(const unsigned long long* __restrict__ best,
                              const float* __restrict__ vs, const float* __restrict__ ss,
                              float* __restrict__ vout, float* __restrict__ sout)
{
    const int n = blockIdx.x;
    const int lane = threadIdx.x;
    const unsigned long long key = best[n];
    const int idx = (int)(~(unsigned int)(key & 0xFFFFFFFFull));
    vout[(size_t)n * OUTD + lane] = vs[(size_t)n * (NSLOTS * OUTD) + (size_t)idx * OUTD + lane];
    if (lane == 0) sout[n] = ss[(size_t)n * NSLOTS + idx];
}

// ---------------- host-side wrapper ----------------
struct Bufs {
    __nv_bfloat16 *bthi, *btlo;
};
static void tc_gemm(const __nv_bfloat16* Ah, const __nv_bfloat16* Al,
                    const float* W, const float* bias,
                    float* Cf, __nv_bfloat16* Chi, __nv_bfloat16* Clo,
                    int M, int N, int K, int relu, const Bufs& bf)
{
    transpose_convert_kernel<<<dim3(N / 32, K / 32), 256>>>(W, bf.bthi, bf.btlo, K, N);
    gemm_bb_kernel<<<dim3(N / 256, M / 128), 512, GEMM_SMEM>>>(
        Ah, Al, bf.bthi, bf.btlo, bias, Cf, Chi, Clo, M, N, K, relu,
        nullptr, nullptr, nullptr, 0);
}

extern "C" void kernel_launch(void* const* d_in, const int* in_sizes, int n_in,
                              void* d_out, int out_size)
{
    const float* s_in  = (const float*)d_in[0];
    const float* x_in  = (const float*)d_in[1];
    const float* t_in  = (const float*)d_in[2];
    const float* Wq    = (const float*)d_in[3];
    const float* Wk    = (const float*)d_in[4];
    const float* Wv    = (const float*)d_in[5];
    const float* Wo    = (const float*)d_in[6];
    const float* cWv   = (const float*)d_in[9];
    const float* cWo   = (const float*)d_in[10];
    const float* ln1_s = (const float*)d_in[11];
    const float* ln1_b = (const float*)d_in[12];
    const float* ln2_s = (const float*)d_in[13];
    const float* ln2_b = (const float*)d_in[14];
    const float* ln3_s = (const float*)d_in[15];
    const float* ln3_b = (const float*)d_in[16];
    const float* W1    = (const float*)d_in[17];
    const float* b1    = (const float*)d_in[18];
    const float* W2    = (const float*)d_in[19];
    const float* b2    = (const float*)d_in[20];
    const float* lnf_s = (const float*)d_in[21];
    const float* lnf_b = (const float*)d_in[22];
    const float* Wout  = (const float*)d_in[23];
    const float* bout  = (const float*)d_in[24];
    const float* W_vs  = (const float*)d_in[25];
    const float* b_vs  = (const float*)d_in[26];
    const float* W_ss  = (const float*)d_in[27];
    const float* b_ss  = (const float*)d_in[28];
    float* out = (float*)d_out;

    float *dec, *tmp2, *ctx, *vs, *bcomb;
    unsigned long long* best;
    __nv_bfloat16 *dech, *decl, *qkvh, *qkvl, *obh, *obl, *th, *tl;
    __nv_bfloat16 *ffh, *ffl, *keysh, *keysl, *vthi, *vtlo;
    __nv_bfloat16 *xbth, *xbtl, *cvh, *cvl;
    Bufs bf;
    cudaGetSymbolAddress((void**)&dec,  g_dec);
    cudaGetSymbolAddress((void**)&tmp2, g_tmp2);
    cudaGetSymbolAddress((void**)&ctx,  g_ctx);
    cudaGetSymbolAddress((void**)&vs,   g_vs);
    cudaGetSymbolAddress((void**)&bcomb,g_bcomb);
    cudaGetSymbolAddress((void**)&best, g_best);
    cudaGetSymbolAddress((void**)&dech, g_dech);
    cudaGetSymbolAddress((void**)&decl, g_decl);
    cudaGetSymbolAddress((void**)&qkvh, g_qkvh);
    cudaGetSymbolAddress((void**)&qkvl, g_qkvl);
    cudaGetSymbolAddress((void**)&obh,  g_obh);
    cudaGetSymbolAddress((void**)&obl,  g_obl);
    cudaGetSymbolAddress((void**)&th,   g_th);
    cudaGetSymbolAddress((void**)&tl,   g_tl);
    cudaGetSymbolAddress((void**)&ffh,  g_ffh);
    cudaGetSymbolAddress((void**)&ffl,  g_ffl);
    cudaGetSymbolAddress((void**)&keysh,g_keysh);
    cudaGetSymbolAddress((void**)&keysl,g_keysl);
    cudaGetSymbolAddress((void**)&vthi, g_vthi);
    cudaGetSymbolAddress((void**)&vtlo, g_vtlo);
    cudaGetSymbolAddress((void**)&xbth, g_xbth);
    cudaGetSymbolAddress((void**)&xbtl, g_xbtl);
    cudaGetSymbolAddress((void**)&cvh,  g_cvh);
    cudaGetSymbolAddress((void**)&cvl,  g_cvl);
    cudaGetSymbolAddress((void**)&bf.bthi, g_bthi);
    cudaGetSymbolAddress((void**)&bf.btlo, g_btlo);

    cudaFuncSetAttribute(gemm_bb_kernel, cudaFuncAttributeMaxDynamicSharedMemorySize, GEMM_SMEM);
    cudaFuncSetAttribute(flash_attn,     cudaFuncAttributeMaxDynamicSharedMemorySize, FA_SMEM);

    cudaMemsetAsync(best, 0, NTOK * sizeof(unsigned long long));
    split_copy_kernel<<<NTOK * DMODEL / 1024, 256>>>(s_in, dec, dech, decl);
    split_kernel<<<NTOK * DMODEL / 1024, 256>>>(t_in, th, tl);
    split_kernel<<<2 * DMODEL * DMODEL / 1024, 256>>>(cWv, cvh, cvl);

    // ---- hoisted cross-attention: ctx = t @ [Mx0 | Mx1] ----
    for (int l = 0; l < 2; l++) {
        const size_t wo = (size_t)l * DMODEL * DMODEL;
        tc_gemm(cvh + wo, cvl + wo, cWo + wo, nullptr, tmp2, nullptr, nullptr,
                DMODEL, DMODEL, DMODEL, 0, bf);
        transpose_convert_kernel<<<dim3(16, 16), 256>>>(
            tmp2, xbth + (size_t)l * DMODEL * DMODEL, xbtl + (size_t)l * DMODEL * DMODEL,
            DMODEL, DMODEL);
    }
    gemm_bb_kernel<<<dim3(1024 / 256, NTOK / 128), 512, GEMM_SMEM>>>(
        th, tl, xbth, xbtl, nullptr, ctx, nullptr, nullptr,
        NTOK, 1024, DMODEL, 0, nullptr, nullptr, nullptr, 0);

    for (int l = 0; l < 2; l++) {
        const size_t wo = (size_t)l * DMODEL * DMODEL;
        // ---- fused QKV projection (N=1536) ----
        transpose_convert3_kernel<<<dim3(16, 16, 3), 256>>>(
            Wq + wo, Wk + wo, Wv + wo, bf.bthi, bf.btlo, DMODEL, DMODEL);
        gemm_bb_kernel<<<dim3(QKVN / 256, NTOK / 128), 512, GEMM_SMEM>>>(
            dech, decl, bf.bthi, bf.btlo, nullptr, nullptr, qkvh, qkvl,
            NTOK, QKVN, DMODEL, 0, nullptr, nullptr, nullptr, 0);
        // ---- fused flash attention ----
        vt_convert_bf<<<dim3(32, 2, 64), 256>>>(qkvh + 1024, qkvl + 1024, QKVN, vthi, vtlo);
        flash_attn<<<dim3(8, 64), 256, FA_SMEM>>>(
            qkvh, qkvl, qkvh + 512, qkvl + 512, QKVN, vthi, vtlo, obh, obl);
        tc_gemm(obh, obl, Wo + wo, nullptr, tmp2, nullptr, nullptr, NTOK, DMODEL, DMODEL, 0, bf);
        // ---- fused ln1 + cross-residual + ln2 ----
        ln2x_kernel<<<NTOK, 128>>>(dec, tmp2, ctx + (size_t)l * 512, 1024,
                                   ln1_s + l * DMODEL, ln1_b + l * DMODEL,
                                   ln2_s + l * DMODEL, ln2_b + l * DMODEL,
                                   dec, dech, decl);
        // ---- FFN ----
        tc_gemm(dech, decl, W1 + (size_t)l * DMODEL * FFDIM, b1 + (size_t)l * FFDIM,
                nullptr, ffh, ffl, NTOK, FFDIM, DMODEL, 1, bf);
        tc_gemm(ffh, ffl, W2 + (size_t)l * FFDIM * DMODEL, b2 + (size_t)l * DMODEL,
                tmp2, nullptr, nullptr, NTOK, DMODEL, FFDIM, 0, bf);
        ln_kernel<<<NTOK, 128>>>(dec, tmp2, DMODEL,
                                 ln3_s + l * DMODEL, ln3_b + l * DMODEL, dec, dech, decl);
    }

    // ---- final head ----
    ln_kernel<<<NTOK, 128>>>(dec, nullptr, 0, lnf_s, lnf_b, nullptr, obh, obl);
    tc_gemm(obh, obl, Wout, bout, tmp2, nullptr, nullptr, NTOK, DMODEL, DMODEL, 0, bf);
    softmax_keys_kernel<<<NTOK, 256>>>(tmp2, keysh, keysl);

    float* out_v  = out;
    float* out_s  = out + 262144;
    float* out_ss = out + 262144 + 8192;

    // ---- merged scoring head: [W_ss | W_vs], N = 16896, split epilogue ----
    bias_concat_kernel<<<(NSLOTS * OUTD + 255) / 256, 256>>>(b_ss, b_vs, bcomb);
    transpose_convert_kernel<<<dim3(NSLOTS / 32, DMODEL / 32), 256>>>(
        W_ss, bf.bthi, bf.btlo, DMODEL, NSLOTS);
    transpose_convert_kernel<<<dim3(NSLOTS * OUTD / 32, DMODEL / 32), 256>>>(
        W_vs, bf.bthi + (size_t)NSLOTS * DMODEL, bf.btlo + (size_t)NSLOTS * DMODEL,
        DMODEL, NSLOTS * OUTD);
    gemm_bb_kernel<<<dim3(HEADN / 256, NTOK / 128), 512, GEMM_SMEM>>>(
        keysh, keysl, bf.bthi, bf.btlo, bcomb, vs, nullptr, nullptr,
        NTOK, HEADN, DMODEL, 0, x_in, best, out_ss, NSLOTS);
    gather_kernel<<<NTOK, 32>>>(best, vs, out_ss, out_v, out_s);
}

// round 15
// speedup vs baseline: 1.0558x; 1.0066x over previous
#include <cuda_runtime.h>
#include <cuda_bf16.h>
#include <math.h>
#include <stdint.h>

#define NTOK   8192
#define DMODEL 512
#define HEADS  8
#define HD     64
#define SEQ    1024
#define FFDIM  2048
#define NSLOTS 512
#define OUTD   32
#define QKVN   1536
#define HEADN  16896
#define NEGF   (-3.4028234663852886e38f)

// ---- weight-bank offsets (elements) ----
#define OFF_QKV0  0u
#define OFF_QKV1  786432u
#define OFF_WO0   1572864u
#define OFF_WO1   1835008u
#define OFF_W1_0  2097152u
#define OFF_W1_1  3145728u
#define OFF_W2_0  4194304u
#define OFF_W2_1  5242880u
#define OFF_WOUT  6291456u
#define OFF_HEAD  6553600u
#define OFF_CWO0  15204352u
#define OFF_CWO1  15466496u
#define WBANK_SZ  15728640u

// ---------------- static scratch ----------------
__device__ float g_dec [NTOK * DMODEL];
__device__ float g_tmp2[NTOK * DMODEL];
__device__ float g_ctx [NTOK * 1024];
__device__ float g_vs  [(size_t)NTOK * NSLOTS * OUTD];
__device__ float g_bcomb[HEADN];
__device__ unsigned long long g_best[NTOK];
__device__ __nv_bfloat16 g_dech[NTOK * DMODEL], g_decl[NTOK * DMODEL];
__device__ __nv_bfloat16 g_qkvh[NTOK * QKVN],  g_qkvl[NTOK * QKVN];
__device__ __nv_bfloat16 g_obh [NTOK * DMODEL], g_obl [NTOK * DMODEL];
__device__ __nv_bfloat16 g_th  [NTOK * DMODEL], g_tl  [NTOK * DMODEL];
__device__ __nv_bfloat16 g_ffh [NTOK * FFDIM],  g_ffl [NTOK * FFDIM];
__device__ __nv_bfloat16 g_keysh[NTOK * DMODEL], g_keysl[NTOK * DMODEL];
__device__ __nv_bfloat16 g_vthi[64 * HD * SEQ], g_vtlo[64 * HD * SEQ];
__device__ __nv_bfloat16 g_wbh[WBANK_SZ], g_wbl[WBANK_SZ];
__device__ __nv_bfloat16 g_xbth[1024 * DMODEL], g_xbtl[1024 * DMODEL];
__device__ __nv_bfloat16 g_cvh[2 * DMODEL * DMODEL], g_cvl[2 * DMODEL * DMODEL];

__device__ __forceinline__ uint32_t smem_u32(const void* p) {
    uint32_t a;
    asm("{ .reg .u64 t; cvta.to.shared.u64 t, %1; cvt.u32.u64 %0, t; }" : "=r"(a) : "l"(p));
    return a;
}
__device__ __forceinline__ uint32_t pack2(__nv_bfloat16 a, __nv_bfloat16 b) {
    return (uint32_t)__bfloat16_as_ushort(a) | ((uint32_t)__bfloat16_as_ushort(b) << 16);
}
__device__ __forceinline__ void cp16(uint32_t dst, const void* src) {
    asm volatile("cp.async.cg.shared.global [%0], [%1], 16;" :: "r"(dst), "l"(src) : "memory");
}
__device__ __forceinline__ void cp_commit() {
    asm volatile("cp.async.commit_group;" ::: "memory");
}
__device__ __forceinline__ void cp_wait0() {
    asm volatile("cp.async.wait_group 0;" ::: "memory");
}
__device__ __forceinline__ void split4(float4 v, uint2& hi, uint2& lo) {
    __nv_bfloat16 hx = __float2bfloat16(v.x), hy = __float2bfloat16(v.y);
    __nv_bfloat16 hz = __float2bfloat16(v.z), hw = __float2bfloat16(v.w);
    __nv_bfloat16 lx = __float2bfloat16(v.x - __bfloat162float(hx));
    __nv_bfloat16 ly = __float2bfloat16(v.y - __bfloat162float(hy));
    __nv_bfloat16 lz = __float2bfloat16(v.z - __bfloat162float(hz));
    __nv_bfloat16 lw = __float2bfloat16(v.w - __bfloat162float(hw));
    hi = make_uint2(pack2(hx, hy), pack2(hz, hw));
    lo = make_uint2(pack2(lx, ly), pack2(lz, lw));
}
__device__ __forceinline__ unsigned long long score_key(float s, int slot) {
    unsigned int u = __float_as_uint(s);
    u = (u & 0x80000000u) ? ~u : (u | 0x80000000u);
    return ((unsigned long long)u << 32) | (unsigned int)(~slot);
}

#define LDMX4(r0, r1, r2, r3, addr) \
    asm volatile("ldmatrix.sync.aligned.m8n8.x4.shared.b16 {%0,%1,%2,%3}, [%4];" \
        : "=r"(r0), "=r"(r1), "=r"(r2), "=r"(r3) : "r"(addr))

#define MMA_BF16(c, a, b) \
    asm volatile("mma.sync.aligned.m16n8k16.row.col.f32.bf16.bf16.f32 " \
        "{%0,%1,%2,%3}, {%4,%5,%6,%7}, {%8,%9}, {%0,%1,%2,%3};" \
        : "+f"((c)[0]), "+f"((c)[1]), "+f"((c)[2]), "+f"((c)[3]) \
        : "r"((a)[0]), "r"((a)[1]), "r"((a)[2]), "r"((a)[3]), "r"((b)[0]), "r"((b)[1]))

#define LDP 72
#define T128 (128 * LDP * 2)
#define T256 (256 * LDP * 2)
#define GB_STAGE (2 * T128 + 2 * T256)
#define GEMM_SMEM (2 * GB_STAGE)
#define FA_LDPV 136
#define FA_VT (64 * FA_LDPV * 2)
#define FA_STAGE (2 * T128 + 2 * FA_VT)
#define FA_SMEM (2 * T128 + 2 * FA_STAGE)

// ============ split-bf16 HMMA GEMM: CTA 128x256, 16 warps of 64x32 (champion) ==
__global__ __launch_bounds__(512, 1)
void gemm_bb_kernel(const __nv_bfloat16* __restrict__ Ahi, const __nv_bfloat16* __restrict__ Alo,
                    const __nv_bfloat16* __restrict__ Bhi, const __nv_bfloat16* __restrict__ Blo,
                    const float* __restrict__ bias,
                    float* __restrict__ Cf, __nv_bfloat16* __restrict__ Chi,
                    __nv_bfloat16* __restrict__ Clo,
                    int M, int N, int K, int relu,
                    const float* __restrict__ xsc, unsigned long long* __restrict__ best,
                    float* __restrict__ Cf2, int split)
{
    extern __shared__ char smem[];
    const int tid  = threadIdx.x;
    const int lane = tid & 31, wid = tid >> 5;
    const int wm = wid >> 3;
    const int wn = wid & 7;
    const size_t brow = (size_t)blockIdx.y * 128;
    const size_t bcol = (size_t)blockIdx.x * 256;
    const int seg = tid & 7, r0 = tid >> 3;

    const int NP = K >> 6;

    auto load_panel = [&](int p, int s) {
        char* base = smem + s * GB_STAGE;
        const size_t ka = (size_t)p * 64 + seg * 8;
#pragma unroll
        for (int hf = 0; hf < 2; hf++) {
            const int r = r0 + hf * 64;
            const uint32_t dst = smem_u32(base + (r * LDP + seg * 8) * 2);
            cp16(dst,        Ahi + (brow + r) * K + ka);
            cp16(dst + T128, Alo + (brow + r) * K + ka);
        }
#pragma unroll
        for (int i = 0; i < 4; i++) {
            const int r = r0 + i * 64;
            const uint32_t dst = smem_u32(base + 2 * T128 + (r * LDP + seg * 8) * 2);
            cp16(dst,        Bhi + (bcol + r) * K + ka);
            cp16(dst + T256, Blo + (bcol + r) * K + ka);
        }
        cp_commit();
    };

    load_panel(0, 0);

    float acc[4][4][4];
#pragma unroll
    for (int i = 0; i < 4; i++)
#pragma unroll
        for (int j = 0; j < 4; j++)
#pragma unroll
            for (int c = 0; c < 4; c++) acc[i][j][c] = 0.f;

    const int lm_r = (lane & 7) + ((lane >> 3) & 1) * 8;
    const int lm_c = ((lane >> 4) & 1) * 8;
    const int lb_r = (lane & 7) + ((lane >> 4) & 1) * 8;
    const int lb_c = ((lane >> 3) & 1) * 8;

    for (int p = 0; p < NP; p++) {
        const int s = p & 1;
        cp_wait0();
        __syncthreads();
        if (p + 1 < NP) load_panel(p + 1, s ^ 1);

        const __nv_bfloat16* sAh = (const __nv_bfloat16*)(smem + s * GB_STAGE);
        const __nv_bfloat16* sAl = (const __nv_bfloat16*)((char*)sAh + T128);
        const __nv_bfloat16* sBh = (const __nv_bfloat16*)((char*)sAh + 2 * T128);
        const __nv_bfloat16* sBl = (const __nv_bfloat16*)((char*)sAh + 2 * T128 + T256);

#pragma unroll
        for (int ks = 0; ks < 4; ks++) {
            const int k0 = ks * 16;
            uint32_t Ah[4][4], Al[4][4], Bh[4][2], Bl[4][2];
#pragma unroll
            for (int mi = 0; mi < 4; mi++) {
                const int r = wm * 64 + mi * 16 + lm_r;
                LDMX4(Ah[mi][0], Ah[mi][1], Ah[mi][2], Ah[mi][3], smem_u32(sAh + r * LDP + k0 + lm_c));
                LDMX4(Al[mi][0], Al[mi][1], Al[mi][2], Al[mi][3], smem_u32(sAl + r * LDP + k0 + lm_c));
            }
#pragma unroll
            for (int nio = 0; nio < 2; nio++) {
                const int r = wn * 32 + nio * 16 + lb_r;
                LDMX4(Bh[2*nio][0], Bh[2*nio][1], Bh[2*nio+1][0], Bh[2*nio+1][1],
                      smem_u32(sBh + r * LDP + k0 + lb_c));
                LDMX4(Bl[2*nio][0], Bl[2*nio][1], Bl[2*nio+1][0], Bl[2*nio+1][1],
                      smem_u32(sBl + r * LDP + k0 + lb_c));
            }
#pragma unroll
            for (int mi = 0; mi < 4; mi++)
#pragma unroll
                for (int ni = 0; ni < 4; ni++) MMA_BF16(acc[mi][ni], Ah[mi], Bh[ni]);
#pragma unroll
            for (int mi = 0; mi < 4; mi++)
#pragma unroll
                for (int ni = 0; ni < 4; ni++) MMA_BF16(acc[mi][ni], Ah[mi], Bl[ni]);
#pragma unroll
            for (int mi = 0; mi < 4; mi++)
#pragma unroll
                for (int ni = 0; ni < 4; ni++) MMA_BF16(acc[mi][ni], Al[mi], Bh[ni]);
        }
    }

    const int g = lane >> 2, t = lane & 3;
    const int tile_col = (int)bcol + wn * 32;
    const bool lo_region = (split > 0) && (tile_col < split);
    const int ldv = (split > 0) ? (N - split) : N;
#pragma unroll
    for (int mi = 0; mi < 4; mi++) {
        const size_t rm = brow + wm * 64 + mi * 16 + g;
        float dA = 0.f, sA2 = 0.f, dB = 0.f, sB2 = 0.f;
#pragma unroll
        for (int ni = 0; ni < 4; ni++) {
            const size_t cn = bcol + wn * 32 + ni * 8 + 2 * t;
            float b0 = 0.f, b1 = 0.f;
            if (bias) { b0 = bias[cn]; b1 = bias[cn + 1]; }
            float v00 = acc[mi][ni][0] + b0, v01 = acc[mi][ni][1] + b1;
            float v10 = acc[mi][ni][2] + b0, v11 = acc[mi][ni][3] + b1;
            if (relu) {
                v00 = fmaxf(v00, 0.f); v01 = fmaxf(v01, 0.f);
                v10 = fmaxf(v10, 0.f); v11 = fmaxf(v11, 0.f);
            }
            if (lo_region) {
                *(float2*)(Cf2 + rm * split + cn)       = make_float2(v00, v01);
                *(float2*)(Cf2 + (rm + 8) * split + cn) = make_float2(v10, v11);
            } else if (Cf) {
                const size_t cv = cn - split;
                *(float2*)(Cf + rm * ldv + cv)       = make_float2(v00, v01);
                *(float2*)(Cf + (rm + 8) * ldv + cv) = make_float2(v10, v11);
            }
            if (Chi) {
                __nv_bfloat16 h00 = __float2bfloat16(v00), h01 = __float2bfloat16(v01);
                __nv_bfloat16 h10 = __float2bfloat16(v10), h11 = __float2bfloat16(v11);
                *(uint32_t*)(Chi + rm * N + cn)       = pack2(h00, h01);
                *(uint32_t*)(Chi + (rm + 8) * N + cn) = pack2(h10, h11);
                *(uint32_t*)(Clo + rm * N + cn)       =
                    pack2(__float2bfloat16(v00 - __bfloat162float(h00)),
                          __float2bfloat16(v01 - __bfloat162float(h01)));
                *(uint32_t*)(Clo + (rm + 8) * N + cn) =
                    pack2(__float2bfloat16(v10 - __bfloat162float(h10)),
                          __float2bfloat16(v11 - __bfloat162float(h11)));
            }
            if (xsc && !lo_region) {
                const int o = ni * 8 + 2 * t;
                float xa0 = xsc[rm * OUTD + o],       xa1 = xsc[rm * OUTD + o + 1];
                float xb0 = xsc[(rm + 8) * OUTD + o], xb1 = xsc[(rm + 8) * OUTD + o + 1];
                dA += v00 * xa0 + v01 * xa1;  sA2 += v00 * v00 + v01 * v01;
                dB += v10 * xb0 + v11 * xb1;  sB2 += v10 * v10 + v11 * v11;
            }
        }
        if (xsc && !lo_region) {
#pragma unroll
            for (int m = 1; m <= 2; m <<= 1) {
                dA  += __shfl_xor_sync(~0u, dA,  m);
                sA2 += __shfl_xor_sync(~0u, sA2, m);
                dB  += __shfl_xor_sync(~0u, dB,  m);
                sB2 += __shfl_xor_sync(~0u, sB2, m);
            }
            if (t == 0) {
                const int slot = (tile_col - split) >> 5;
                atomicMax(&best[rm],     score_key(dA * rsqrtf(sA2), slot));
                atomicMax(&best[rm + 8], score_key(dB * rsqrtf(sB2), slot));
            }
        }
    }
}

// ============ fused flash attention (__expf fast path) ========================
__global__ __launch_bounds__(256, 1)
void flash_attn(const __nv_bfloat16* __restrict__ Qh_, const __nv_bfloat16* __restrict__ Ql_,
                const __nv_bfloat16* __restrict__ Kh_, const __nv_bfloat16* __restrict__ Kl_,
                int ld,
                const __nv_bfloat16* __restrict__ Vth, const __nv_bfloat16* __restrict__ Vtl,
                __nv_bfloat16* __restrict__ Oh, __nv_bfloat16* __restrict__ Ol)
{
    extern __shared__ char smem[];
    const int qt = 7 - blockIdx.x;
    const int bh = blockIdx.y;
    const int b = bh >> 3, h = bh & 7;
    const int tid = threadIdx.x;
    const int lane = tid & 31, wid = tid >> 5;
    const int g = lane >> 2, t = lane & 3;

    auto load_chunk = [&](int kc, int s) {
        char* base = smem + 2 * T128 + s * FA_STAGE;
        {
            const int seg = tid & 7, r0 = tid >> 3;
#pragma unroll
            for (int it = 0; it < 4; it++) {
                const int r = r0 + it * 32;
                const uint32_t dst = smem_u32(base + (r * LDP + seg * 8) * 2);
                const size_t off = ((size_t)(b * SEQ + kc * 128 + r) * ld) + h * HD + seg * 8;
                cp16(dst,        Kh_ + off);
                cp16(dst + T128, Kl_ + off);
            }
        }
        {
            const int seg = tid & 15, r0 = tid >> 4;
#pragma unroll
            for (int it = 0; it < 4; it++) {
                const int r = r0 + it * 16;
                const uint32_t dst = smem_u32(base + 2 * T128 + (r * FA_LDPV + seg * 8) * 2);
                const size_t off = ((size_t)bh * HD + r) * SEQ + kc * 128 + seg * 8;
                cp16(dst,         Vth + off);
                cp16(dst + FA_VT, Vtl + off);
            }
        }
        cp_commit();
    };

    {
        const int seg = tid & 7, r0 = tid >> 3;
#pragma unroll
        for (int it = 0; it < 4; it++) {
            const int r = r0 + it * 32;
            const uint32_t dst = smem_u32(smem + (r * LDP + seg * 8) * 2);
            const size_t off = ((size_t)(b * SEQ + qt * 128 + r) * ld) + h * HD + seg * 8;
            cp16(dst,        Qh_ + off);
            cp16(dst + T128, Ql_ + off);
        }
    }
    load_chunk(0, 0);

    const int lm_r = (lane & 7) + ((lane >> 3) & 1) * 8;
    const int lm_c = ((lane >> 4) & 1) * 8;
    const int lb_r = (lane & 7) + ((lane >> 4) & 1) * 8;
    const int lb_c = ((lane >> 3) & 1) * 8;

    uint32_t Qh[4][4], Ql[4][4];
    float o[8][4];
#pragma unroll
    for (int i = 0; i < 8; i++)
#pragma unroll
        for (int c = 0; c < 4; c++) o[i][c] = 0.f;
    float m0 = -INFINITY, m1 = -INFINITY, l0 = 0.f, l1 = 0.f;
    const int row0 = qt * 128 + wid * 16 + g;
    const int row1 = row0 + 8;

    for (int kc = 0; kc <= qt; kc++) {
        const int s = kc & 1;
        cp_wait0();
        __syncthreads();
        if (kc == 0) {
            const __nv_bfloat16* sQh = (const __nv_bfloat16*)smem;
            const __nv_bfloat16* sQl = (const __nv_bfloat16*)(smem + T128);
#pragma unroll
            for (int kf = 0; kf < 4; kf++) {
                LDMX4(Qh[kf][0], Qh[kf][1], Qh[kf][2], Qh[kf][3],
                      smem_u32(sQh + (wid * 16 + lm_r) * LDP + kf * 16 + lm_c));
                LDMX4(Ql[kf][0], Ql[kf][1], Ql[kf][2], Ql[kf][3],
                      smem_u32(sQl + (wid * 16 + lm_r) * LDP + kf * 16 + lm_c));
            }
        }
        if (kc < qt) load_chunk(kc + 1, s ^ 1);

        const char* base = smem + 2 * T128 + s * FA_STAGE;
        const __nv_bfloat16* sKh = (const __nv_bfloat16*)base;
        const __nv_bfloat16* sKl = (const __nv_bfloat16*)(base + T128);
        const __nv_bfloat16* sVh = (const __nv_bfloat16*)(base + 2 * T128);
        const __nv_bfloat16* sVl = (const __nv_bfloat16*)(base + 2 * T128 + FA_VT);

        float sacc[16][4];
#pragma unroll
        for (int j = 0; j < 16; j++)
#pragma unroll
            for (int c = 0; c < 4; c++) sacc[j][c] = 0.f;

#pragma unroll
        for (int ks = 0; ks < 4; ks++) {
#pragma unroll
            for (int grp = 0; grp < 2; grp++) {
                uint32_t Bh[8][2], Bl[8][2];
#pragma unroll
                for (int i = 0; i < 4; i++) {
                    const int nt = grp * 4 + i;
                    LDMX4(Bh[2*i][0], Bh[2*i][1], Bh[2*i+1][0], Bh[2*i+1][1],
                          smem_u32(sKh + (nt * 16 + lb_r) * LDP + ks * 16 + lb_c));
                    LDMX4(Bl[2*i][0], Bl[2*i][1], Bl[2*i+1][0], Bl[2*i+1][1],
                          smem_u32(sKl + (nt * 16 + lb_r) * LDP + ks * 16 + lb_c));
                }
#pragma unroll
                for (int i = 0; i < 8; i++) MMA_BF16(sacc[grp*8+i], Qh[ks], Bh[i]);
#pragma unroll
                for (int i = 0; i < 8; i++) MMA_BF16(sacc[grp*8+i], Qh[ks], Bl[i]);
#pragma unroll
                for (int i = 0; i < 8; i++) MMA_BF16(sacc[grp*8+i], Ql[ks], Bh[i]);
            }
        }

        const bool diag = (kc == qt);
        float mx0 = -INFINITY, mx1 = -INFINITY;
#pragma unroll
        for (int j = 0; j < 16; j++) {
            const int col = kc * 128 + 8 * j + 2 * t;
            float s0 = sacc[j][0] * 0.125f;
            float s1 = sacc[j][1] * 0.125f;
            float s2 = sacc[j][2] * 0.125f;
            float s3 = sacc[j][3] * 0.125f;
            if (diag) {
                if (col     > row0) s0 = NEGF;
                if (col + 1 > row0) s1 = NEGF;
                if (col     > row1) s2 = NEGF;
                if (col + 1 > row1) s3 = NEGF;
            }
            sacc[j][0] = s0; sacc[j][1] = s1; sacc[j][2] = s2; sacc[j][3] = s3;
            mx0 = fmaxf(mx0, fmaxf(s0, s1));
            mx1 = fmaxf(mx1, fmaxf(s2, s3));
        }
        mx0 = fmaxf(mx0, __shfl_xor_sync(~0u, mx0, 1));
        mx0 = fmaxf(mx0, __shfl_xor_sync(~0u, mx0, 2));
        mx1 = fmaxf(mx1, __shfl_xor_sync(~0u, mx1, 1));
        mx1 = fmaxf(mx1, __shfl_xor_sync(~0u, mx1, 2));
        const float mn0 = fmaxf(m0, mx0), mn1 = fmaxf(m1, mx1);
        const float f0 = __expf(m0 - mn0), f1 = __expf(m1 - mn1);
        float rs0 = 0.f, rs1 = 0.f;
#pragma unroll
        for (int j = 0; j < 16; j++) {
            float p0 = __expf(sacc[j][0] - mn0);
            float p1 = __expf(sacc[j][1] - mn0);
            float p2 = __expf(sacc[j][2] - mn1);
            float p3 = __expf(sacc[j][3] - mn1);
            sacc[j][0] = p0; sacc[j][1] = p1; sacc[j][2] = p2; sacc[j][3] = p3;
            rs0 += p0 + p1; rs1 += p2 + p3;
        }
        rs0 += __shfl_xor_sync(~0u, rs0, 1);
        rs0 += __shfl_xor_sync(~0u, rs0, 2);
        rs1 += __shfl_xor_sync(~0u, rs1, 1);
        rs1 += __shfl_xor_sync(~0u, rs1, 2);
        l0 = l0 * f0 + rs0;
        l1 = l1 * f1 + rs1;
        m0 = mn0; m1 = mn1;
#pragma unroll
        for (int ni = 0; ni < 8; ni++) {
            o[ni][0] *= f0; o[ni][1] *= f0; o[ni][2] *= f1; o[ni][3] *= f1;
        }

#pragma unroll
        for (int kf = 0; kf < 8; kf++) {
            const int j0 = 2 * kf, j1 = 2 * kf + 1;
            uint32_t Pfh[4], Pfl[4];
            {
                __nv_bfloat16 a0 = __float2bfloat16(sacc[j0][0]);
                __nv_bfloat16 a1 = __float2bfloat16(sacc[j0][1]);
                __nv_bfloat16 a2 = __float2bfloat16(sacc[j0][2]);
                __nv_bfloat16 a3 = __float2bfloat16(sacc[j0][3]);
                __nv_bfloat16 a4 = __float2bfloat16(sacc[j1][0]);
                __nv_bfloat16 a5 = __float2bfloat16(sacc[j1][1]);
                __nv_bfloat16 a6 = __float2bfloat16(sacc[j1][2]);
                __nv_bfloat16 a7 = __float2bfloat16(sacc[j1][3]);
                Pfh[0] = pack2(a0, a1); Pfh[1] = pack2(a2, a3);
                Pfh[2] = pack2(a4, a5); Pfh[3] = pack2(a6, a7);
                Pfl[0] = pack2(__float2bfloat16(sacc[j0][0] - __bfloat162float(a0)),
                               __float2bfloat16(sacc[j0][1] - __bfloat162float(a1)));
                Pfl[1] = pack2(__float2bfloat16(sacc[j0][2] - __bfloat162float(a2)),
                               __float2bfloat16(sacc[j0][3] - __bfloat162float(a3)));
                Pfl[2] = pack2(__float2bfloat16(sacc[j1][0] - __bfloat162float(a4)),
                               __float2bfloat16(sacc[j1][1] - __bfloat162float(a5)));
                Pfl[3] = pack2(__float2bfloat16(sacc[j1][2] - __bfloat162float(a6)),
                               __float2bfloat16(sacc[j1][3] - __bfloat162float(a7)));
            }
            uint32_t Vh[8][2], Vl[8][2];
#pragma unroll
            for (int i = 0; i < 4; i++) {
                LDMX4(Vh[2*i][0], Vh[2*i][1], Vh[2*i+1][0], Vh[2*i+1][1],
                      smem_u32(sVh + (i * 16 + lb_r) * FA_LDPV + kf * 16 + lb_c));
                LDMX4(Vl[2*i][0], Vl[2*i][1], Vl[2*i+1][0], Vl[2*i+1][1],
                      smem_u32(sVl + (i * 16 + lb_r) * FA_LDPV + kf * 16 + lb_c));
            }
#pragma unroll
            for (int ni = 0; ni < 8; ni++) MMA_BF16(o[ni], Pfh, Vh[ni]);
#pragma unroll
            for (int ni = 0; ni < 8; ni++) MMA_BF16(o[ni], Pfh, Vl[ni]);
#pragma unroll
            for (int ni = 0; ni < 8; ni++) MMA_BF16(o[ni], Pfl, Vh[ni]);
        }
    }

    const float inv0 = 1.f / l0, inv1 = 1.f / l1;
#pragma unroll
    for (int ni = 0; ni < 8; ni++) {
        const int d = h * HD + 8 * ni + 2 * t;
        const size_t off0 = (size_t)(b * SEQ + row0) * DMODEL + d;
        const size_t off1 = (size_t)(b * SEQ + row1) * DMODEL + d;
        float v00 = o[ni][0] * inv0, v01 = o[ni][1] * inv0;
        float v10 = o[ni][2] * inv1, v11 = o[ni][3] * inv1;
        __nv_bfloat16 h00 = __float2bfloat16(v00), h01 = __float2bfloat16(v01);
        __nv_bfloat16 h10 = __float2bfloat16(v10), h11 = __float2bfloat16(v11);
        *(uint32_t*)(Oh + off0) = pack2(h00, h01);
        *(uint32_t*)(Oh + off1) = pack2(h10, h11);
        *(uint32_t*)(Ol + off0) = pack2(__float2bfloat16(v00 - __bfloat162float(h00)),
                                        __float2bfloat16(v01 - __bfloat162float(h01)));
        *(uint32_t*)(Ol + off1) = pack2(__float2bfloat16(v10 - __bfloat162float(h10)),
                                        __float2bfloat16(v11 - __bfloat162float(h11)));
    }
}

// ============ keys softmax -> hi/lo ===========================================
__global__ __launch_bounds__(256, 1)
void softmax_keys_kernel(const float* __restrict__ src,
                         __nv_bfloat16* __restrict__ Kh, __nv_bfloat16* __restrict__ Kl)
{
    const int row = blockIdx.x;
    const int tid = threadIdx.x, warp = tid >> 5, lane = tid & 31;
    const float* p = src + (size_t)row * DMODEL;
    float v[2];
    float m = -INFINITY;
#pragma unroll
    for (int i = 0; i < 2; i++) { v[i] = p[tid + i * 256]; m = fmaxf(m, v[i]); }
#pragma unroll
    for (int o = 16; o > 0; o >>= 1) m = fmaxf(m, __shfl_xor_sync(~0u, m, o));
    __shared__ float smax[8], ssum[8];
    if (lane == 0) smax[warp] = m;
    __syncthreads();
    m = smax[0];
#pragma unroll
    for (int w = 1; w < 8; w++) m = fmaxf(m, smax[w]);
    float sum = 0.f;
#pragma unroll
    for (int i = 0; i < 2; i++) { v[i] = __expf(v[i] - m); sum += v[i]; }
#pragma unroll
    for (int o = 16; o > 0; o >>= 1) sum += __shfl_xor_sync(~0u, sum, o);
    if (lane == 0) ssum[warp] = sum;
    __syncthreads();
    sum = ssum[0];
#pragma unroll
    for (int w = 1; w < 8; w++) sum += ssum[w];
    const float inv = 1.f / sum;
#pragma unroll
    for (int i = 0; i < 2; i++) {
        float pv = v[i] * inv;
        __nv_bfloat16 h = __float2bfloat16(pv);
        Kh[(size_t)row * DMODEL + tid + i * 256] = h;
        Kl[(size_t)row * DMODEL + tid + i * 256] = __float2bfloat16(pv - __bfloat162float(h));
    }
}

// ============ V^T from bf16 hi/lo =============================================
__global__ void vt_convert_bf(const __nv_bfloat16* __restrict__ Vh,
                              const __nv_bfloat16* __restrict__ Vl, int ld,
                              __nv_bfloat16* __restrict__ Hi, __nv_bfloat16* __restrict__ Lo)
{
    __shared__ __nv_bfloat16 th[32][33], tl[32][33];
    const int k0 = blockIdx.x * 32, d0 = blockIdx.y * 32, bh = blockIdx.z;
    const int b = bh >> 3, h = bh & 7;
    const int tx = threadIdx.x & 31, ty = threadIdx.x >> 5;
#pragma unroll
    for (int j = 0; j < 32; j += 8) {
        const size_t src = (size_t)(b * SEQ + k0 + ty + j) * ld + h * HD + d0 + tx;
        th[ty + j][tx] = Vh[src];
        tl[ty + j][tx] = Vl[src];
    }
    __syncthreads();
#pragma unroll
    for (int j = 0; j < 32; j += 8) {
        const size_t o = ((size_t)bh * HD + d0 + ty + j) * SEQ + k0 + tx;
        Hi[o] = th[tx][ty + j];
        Lo[o] = tl[tx][ty + j];
    }
}

// ============ batched weight transpose + split (all input-only weights) =======
#define NSEG 17
struct TSegs {
    const float* src[NSEG];
    unsigned int dst[NSEG];     // element offset into wbank
    int K[NSEG], N[NSEG];
    int bstart[NSEG];           // first block of segment
};
__global__ void transpose_all_kernel(TSegs segs,
                                     __nv_bfloat16* __restrict__ Hi,
                                     __nv_bfloat16* __restrict__ Lo)
{
    __shared__ float t[32][33];
    const int blk = blockIdx.x;
    int si = 0;
#pragma unroll
    for (int i = 1; i < NSEG; i++)
        if (segs.bstart[i] <= blk) si = i;
    const float* W = segs.src[si];
    const int K = segs.K[si], N = segs.N[si];
    const int lb = blk - segs.bstart[si];
    const int nbN = N >> 5;
    const int k0 = (lb / nbN) * 32, n0 = (lb % nbN) * 32;
    __nv_bfloat16* Hd = Hi + segs.dst[si];
    __nv_bfloat16* Ld = Lo + segs.dst[si];

    const int tx = threadIdx.x & 31, ty = threadIdx.x >> 5;
#pragma unroll
    for (int j = 0; j < 32; j += 8)
        t[ty + j][tx] = W[(size_t)(k0 + ty + j) * N + n0 + tx];
    __syncthreads();
#pragma unroll
    for (int j = 0; j < 32; j += 8) {
        float v = t[tx][ty + j];
        __nv_bfloat16 h = __float2bfloat16(v);
        Hd[(size_t)(n0 + ty + j) * K + k0 + tx] = h;
        Ld[(size_t)(n0 + ty + j) * K + k0 + tx] = __float2bfloat16(v - __bfloat162float(h));
    }
}

// ============ single weight transpose (xbt, data-dependent) ===================
__global__ void transpose_convert_kernel(const float* __restrict__ W,
                                         __nv_bfloat16* __restrict__ Hi,
                                         __nv_bfloat16* __restrict__ Lo, int K, int N)
{
    __shared__ float t[32][33];
    const int k0 = blockIdx.y * 32, n0 = blockIdx.x * 32;
    const int tx = threadIdx.x & 31, ty = threadIdx.x >> 5;
#pragma unroll
    for (int j = 0; j < 32; j += 8)
        t[ty + j][tx] = W[(size_t)(k0 + ty + j) * N + n0 + tx];
    __syncthreads();
#pragma unroll
    for (int j = 0; j < 32; j += 8) {
        float v = t[tx][ty + j];
        __nv_bfloat16 h = __float2bfloat16(v);
        Hi[(size_t)(n0 + ty + j) * K + k0 + tx] = h;
        Lo[(size_t)(n0 + ty + j) * K + k0 + tx] = __float2bfloat16(v - __bfloat162float(h));
    }
}

// ============ elementwise split ===============================================
__global__ void split_kernel(const float* __restrict__ in,
                             __nv_bfloat16* __restrict__ hi, __nv_bfloat16* __restrict__ lo)
{
    const int i = blockIdx.x * 256 + threadIdx.x;
    float4 v = ((const float4*)in)[i];
    uint2 h, l;
    split4(v, h, l);
    ((uint2*)hi)[i] = h;
    ((uint2*)lo)[i] = l;
}

__global__ void split_copy_kernel(const float* __restrict__ in, float* __restrict__ outf,
                                  __nv_bfloat16* __restrict__ hi, __nv_bfloat16* __restrict__ lo)
{
    const int i = blockIdx.x * 256 + threadIdx.x;
    float4 v = ((const float4*)in)[i];
    ((float4*)outf)[i] = v;
    uint2 h, l;
    split4(v, h, l);
    ((uint2*)hi)[i] = h;
    ((uint2*)lo)[i] = l;
}

// ============ combined-bias assembly ==========================================
__global__ void bias_concat_kernel(const float* __restrict__ b_ss,
                                   const float* __restrict__ b_vs,
                                   float* __restrict__ bcomb)
{
    const int i = blockIdx.x * 256 + threadIdx.x;
    if (i < NSLOTS) bcomb[i] = b_ss[i];
    if (i < NSLOTS * OUTD) bcomb[NSLOTS + i] = b_vs[i];
}

// ============ residual + LayerNorm ============================================
__global__ void ln_kernel(const float* __restrict__ xin, const float* __restrict__ res,
                          int res_ld,
                          const float* __restrict__ scale, const float* __restrict__ bias,
                          float* __restrict__ outf,
                          __nv_bfloat16* __restrict__ outh, __nv_bfloat16* __restrict__ outl)
{
    const int row = blockIdx.x;
    const int tid = threadIdx.x;
    float4 v = ((const float4*)(xin + (size_t)row * DMODEL))[tid];
    if (res) {
        float4 r = ((const float4*)(res + (size_t)row * res_ld))[tid];
        v.x += r.x; v.y += r.y; v.z += r.z; v.w += r.w;
    }
    float s  = v.x + v.y + v.z + v.w;
    float sq = v.x * v.x + v.y * v.y + v.z * v.z + v.w * v.w;
#pragma unroll
    for (int o = 16; o > 0; o >>= 1) {
        s  += __shfl_xor_sync(~0u, s,  o);
        sq += __shfl_xor_sync(~0u, sq, o);
    }
    __shared__ float ss[4], sqs[4];
    const int warp = tid >> 5, lane = tid & 31;
    if (lane == 0) { ss[warp] = s; sqs[warp] = sq; }
    __syncthreads();
    float S  = ss[0]  + ss[1]  + ss[2]  + ss[3];
    float SQ = sqs[0] + sqs[1] + sqs[2] + sqs[3];
    float mean = S * (1.f / DMODEL);
    float var  = SQ * (1.f / DMODEL) - mean * mean;
    float rs   = rsqrtf(var + 1e-6f);
    float4 sc4 = ((const float4*)scale)[tid];
    float4 bi4 = ((const float4*)bias)[tid];
    float4 o;
    o.x = (v.x - mean) * rs * sc4.x + bi4.x;
    o.y = (v.y - mean) * rs * sc4.y + bi4.y;
    o.z = (v.z - mean) * rs * sc4.z + bi4.z;
    o.w = (v.w - mean) * rs * sc4.w + bi4.w;
    if (outf) ((float4*)(outf + (size_t)row * DMODEL))[tid] = o;
    uint2 h, l;
    split4(o, h, l);
    ((uint2*)(outh + (size_t)row * DMODEL))[tid] = h;
    ((uint2*)(outl + (size_t)row * DMODEL))[tid] = l;
}

// ============ fused double LayerNorm: LN2(LN1(x + a) + c) =====================
__global__ void ln2x_kernel(const float* __restrict__ xin, const float* __restrict__ add1,
                            const float* __restrict__ ctx, int ctx_ld,
                            const float* __restrict__ s1, const float* __restrict__ b1,
                            const float* __restrict__ s2, const float* __restrict__ b2,
                            float* __restrict__ outf,
                            __nv_bfloat16* __restrict__ outh, __nv_bfloat16* __restrict__ outl)
{
    const int row = blockIdx.x;
    const int tid = threadIdx.x;
    const int warp = tid >> 5, lane = tid & 31;
    __shared__ float ss[4], sqs[4];

    float4 v = ((const float4*)(xin + (size_t)row * DMODEL))[tid];
    float4 a = ((const float4*)(add1 + (size_t)row * DMODEL))[tid];
    v.x += a.x; v.y += a.y; v.z += a.z; v.w += a.w;

    {
        float s  = v.x + v.y + v.z + v.w;
        float sq = v.x * v.x + v.y * v.y + v.z * v.z + v.w * v.w;
#pragma unroll
        for (int o = 16; o > 0; o >>= 1) {
            s  += __shfl_xor_sync(~0u, s,  o);
            sq += __shfl_xor_sync(~0u, sq, o);
        }
        if (lane == 0) { ss[warp] = s; sqs[warp] = sq; }
        __syncthreads();
        float S  = ss[0]  + ss[1]  + ss[2]  + ss[3];
        float SQ = sqs[0] + sqs[1] + sqs[2] + sqs[3];
        float mean = S * (1.f / DMODEL);
        float var  = SQ * (1.f / DMODEL) - mean * mean;
        float rs   = rsqrtf(var + 1e-6f);
        float4 sc4 = ((const float4*)s1)[tid];
        float4 bi4 = ((const float4*)b1)[tid];
        v.x = (v.x - mean) * rs * sc4.x + bi4.x;
        v.y = (v.y - mean) * rs * sc4.y + bi4.y;
        v.z = (v.z - mean) * rs * sc4.z + bi4.z;
        v.w = (v.w - mean) * rs * sc4.w + bi4.w;
        __syncthreads();
    }
    {
        float4 c = ((const float4*)(ctx + (size_t)row * ctx_ld))[tid];
        v.x += c.x; v.y += c.y; v.z += c.z; v.w += c.w;
        float s  = v.x + v.y + v.z + v.w;
        float sq = v.x * v.x + v.y * v.y + v.z * v.z + v.w * v.w;
#pragma unroll
        for (int o = 16; o > 0; o >>= 1) {
            s  += __shfl_xor_sync(~0u, s,  o);
            sq += __shfl_xor_sync(~0u, sq, o);
        }
        if (lane == 0) { ss[warp] = s; sqs[warp] = sq; }
        __syncthreads();
        float S  = ss[0]  + ss[1]  + ss[2]  + ss[3];
        float SQ = sqs[0] + sqs[1] + sqs[2] + sqs[3];
        float mean = S * (1.f / DMODEL);
        float var  = SQ * (1.f / DMODEL) - mean * mean;
        float rs   = rsqrtf(var + 1e-6f);
        float4 sc4 = ((const float4*)s2)[tid];
        float4 bi4 = ((const float4*)b2)[tid];
        v.x = (v.x - mean) * rs * sc4.x + bi4.x;
        v.y = (v.y - mean) * rs * sc4.y + bi4.y;
        v.z = (v.z - mean) * rs * sc4.z + bi4.z;
        v.w = (v.w - mean) * rs * sc4.w + bi4.w;
    }
    ((float4*)(outf + (size_t)row * DMODEL))[tid] = v;
    uint2 h, l;
    split4(v, h, l);
    ((uint2*)(outh + (size_t)row * DMODEL))[tid] = h;
    ((uint2*)(outl + (size_t)row * DMODEL))[tid] = l;
}

// ============ winner gather ===================================================
__global__ void gather_kernel(const unsigned long long* __restrict__ best,
                              const float* __restrict__ vs, const float* __restrict__ ss,
                              float* __restrict__ vout, float* __restrict__ sout)
{
    const int n = blockIdx.x;
    const int lane = threadIdx.x;
    const unsigned long long key = best[n];
    const int idx = (int)(~(unsigned int)(key & 0xFFFFFFFFull));
    vout[(size_t)n * OUTD + lane] = vs[(size_t)n * (NSLOTS * OUTD) + (size_t)idx * OUTD + lane];
    if (lane == 0) sout[n] = ss[(size_t)n * NSLOTS + idx];
}

extern "C" void kernel_launch(void* const* d_in, const int* in_sizes, int n_in,
                              void* d_out, int out_size)
{
    const float* s_in  = (const float*)d_in[0];
    const float* x_in  = (const float*)d_in[1];
    const float* t_in  = (const float*)d_in[2];
    const float* Wq    = (const float*)d_in[3];
    const float* Wk    = (const float*)d_in[4];
    const float* Wv    = (const float*)d_in[5];
    const float* Wo    = (const float*)d_in[6];
    const float* cWv   = (const float*)d_in[9];
    const float* cWo   = (const float*)d_in[10];
    const float* ln1_s = (const float*)d_in[11];
    const float* ln1_b = (const float*)d_in[12];
    const float* ln2_s = (const float*)d_in[13];
    const float* ln2_b = (const float*)d_in[14];
    const float* ln3_s = (const float*)d_in[15];
    const float* ln3_b = (const float*)d_in[16];
    const float* W1    = (const float*)d_in[17];
    const float* b1    = (const float*)d_in[18];
    const float* W2    = (const float*)d_in[19];
    const float* b2    = (const float*)d_in[20];
    const float* lnf_s = (const float*)d_in[21];
    const float* lnf_b = (const float*)d_in[22];
    const float* Wout  = (const float*)d_in[23];
    const float* bout  = (const float*)d_in[24];
    const float* W_vs  = (const float*)d_in[25];
    const float* b_vs  = (const float*)d_in[26];
    const float* W_ss  = (const float*)d_in[27];
    const float* b_ss  = (const float*)d_in[28];
    float* out = (float*)d_out;

    float *dec, *tmp2, *ctx, *vs, *bcomb;
    unsigned long long* best;
    __nv_bfloat16 *dech, *decl, *qkvh, *qkvl, *obh, *obl, *th, *tl;
    __nv_bfloat16 *ffh, *ffl, *keysh, *keysl, *vthi, *vtlo;
    __nv_bfloat16 *wbh, *wbl, *xbth, *xbtl, *cvh, *cvl;
    cudaGetSymbolAddress((void**)&dec,  g_dec);
    cudaGetSymbolAddress((void**)&tmp2, g_tmp2);
    cudaGetSymbolAddress((void**)&ctx,  g_ctx);
    cudaGetSymbolAddress((void**)&vs,   g_vs);
    cudaGetSymbolAddress((void**)&bcomb,g_bcomb);
    cudaGetSymbolAddress((void**)&best, g_best);
    cudaGetSymbolAddress((void**)&dech, g_dech);
    cudaGetSymbolAddress((void**)&decl, g_decl);
    cudaGetSymbolAddress((void**)&qkvh, g_qkvh);
    cudaGetSymbolAddress((void**)&qkvl, g_qkvl);
    cudaGetSymbolAddress((void**)&obh,  g_obh);
    cudaGetSymbolAddress((void**)&obl,  g_obl);
    cudaGetSymbolAddress((void**)&th,   g_th);
    cudaGetSymbolAddress((void**)&tl,   g_tl);
    cudaGetSymbolAddress((void**)&ffh,  g_ffh);
    cudaGetSymbolAddress((void**)&ffl,  g_ffl);
    cudaGetSymbolAddress((void**)&keysh,g_keysh);
    cudaGetSymbolAddress((void**)&keysl,g_keysl);
    cudaGetSymbolAddress((void**)&vthi, g_vthi);
    cudaGetSymbolAddress((void**)&vtlo, g_vtlo);
    cudaGetSymbolAddress((void**)&wbh,  g_wbh);
    cudaGetSymbolAddress((void**)&wbl,  g_wbl);
    cudaGetSymbolAddress((void**)&xbth, g_xbth);
    cudaGetSymbolAddress((void**)&xbtl, g_xbtl);
    cudaGetSymbolAddress((void**)&cvh,  g_cvh);
    cudaGetSymbolAddress((void**)&cvl,  g_cvl);

    cudaFuncSetAttribute(gemm_bb_kernel, cudaFuncAttributeMaxDynamicSharedMemorySize, GEMM_SMEM);
    cudaFuncSetAttribute(flash_attn,     cudaFuncAttributeMaxDynamicSharedMemorySize, FA_SMEM);

    cudaMemsetAsync(best, 0, NTOK * sizeof(unsigned long long));
    split_copy_kernel<<<NTOK * DMODEL / 1024, 256>>>(s_in, dec, dech, decl);
    split_kernel<<<NTOK * DMODEL / 1024, 256>>>(t_in, th, tl);
    split_kernel<<<2 * DMODEL * DMODEL / 1024, 256>>>(cWv, cvh, cvl);
    bias_concat_kernel<<<(NSLOTS * OUTD + 255) / 256, 256>>>(b_ss, b_vs, bcomb);

    // ---- one batched transpose for all input-only weights ----
    {
        TSegs sg;
        const size_t D2 = (size_t)DMODEL * DMODEL;
        int bs = 0, i = 0;
        auto add = [&](const float* src, unsigned int dst, int K, int N) {
            sg.src[i] = src; sg.dst[i] = dst; sg.K[i] = K; sg.N[i] = N;
            sg.bstart[i] = bs; bs += (K / 32) * (N / 32); i++;
        };
        add(Wq,        OFF_QKV0,               DMODEL, DMODEL);
        add(Wk,        OFF_QKV0 + 512 * 512,   DMODEL, DMODEL);
        add(Wv,        OFF_QKV0 + 1024 * 512,  DMODEL, DMODEL);
        add(Wq + D2,   OFF_QKV1,               DMODEL, DMODEL);
        add(Wk + D2,   OFF_QKV1 + 512 * 512,   DMODEL, DMODEL);
        add(Wv + D2,   OFF_QKV1 + 1024 * 512,  DMODEL, DMODEL);
        add(Wo,        OFF_WO0,                DMODEL, DMODEL);
        add(Wo + D2,   OFF_WO1,                DMODEL, DMODEL);
        add(W1,        OFF_W1_0,               DMODEL, FFDIM);
        add(W1 + (size_t)DMODEL * FFDIM, OFF_W1_1, DMODEL, FFDIM);
        add(W2,        OFF_W2_0,               FFDIM, DMODEL);
        add(W2 + (size_t)FFDIM * DMODEL, OFF_W2_1, FFDIM, DMODEL);
        add(Wout,      OFF_WOUT,               DMODEL, DMODEL);
        add(W_ss,      OFF_HEAD,               DMODEL, NSLOTS);
        add(W_vs,      OFF_HEAD + (unsigned)NSLOTS * DMODEL, DMODEL, NSLOTS * OUTD);
        add(cWo,       OFF_CWO0,               DMODEL, DMODEL);
        add(cWo + D2,  OFF_CWO1,               DMODEL, DMODEL);
        transpose_all_kernel<<<bs, 256>>>(sg, wbh, wbl);
    }

    // ---- hoisted cross-attention: ctx = t @ [Mx0 | Mx1] ----
    for (int l = 0; l < 2; l++) {
        const unsigned int cwo = l ? OFF_CWO1 : OFF_CWO0;
        const size_t wo = (size_t)l * DMODEL * DMODEL;
        gemm_bb_kernel<<<dim3(DMODEL / 256, DMODEL / 128), 512, GEMM_SMEM>>>(
            cvh + wo, cvl + wo, wbh + cwo, wbl + cwo, nullptr,
            tmp2, nullptr, nullptr, DMODEL, DMODEL, DMODEL, 0,
            nullptr, nullptr, nullptr, 0);
        transpose_convert_kernel<<<dim3(16, 16), 256>>>(
            tmp2, xbth + wo, xbtl + wo, DMODEL, DMODEL);
    }
    gemm_bb_kernel<<<dim3(1024 / 256, NTOK / 128), 512, GEMM_SMEM>>>(
        th, tl, xbth, xbtl, nullptr, ctx, nullptr, nullptr,
        NTOK, 1024, DMODEL, 0, nullptr, nullptr, nullptr, 0);

    for (int l = 0; l < 2; l++) {
        const unsigned int qkvo = l ? OFF_QKV1 : OFF_QKV0;
        const unsigned int woo  = l ? OFF_WO1  : OFF_WO0;
        const unsigned int w1o  = l ? OFF_W1_1 : OFF_W1_0;
        const unsigned int w2o  = l ? OFF_W2_1 : OFF_W2_0;
        // ---- fused QKV projection (N=1536) ----
        gemm_bb_kernel<<<dim3(QKVN / 256, NTOK / 128), 512, GEMM_SMEM>>>(
            dech, decl, wbh + qkvo, wbl + qkvo, nullptr, nullptr, qkvh, qkvl,
            NTOK, QKVN, DMODEL, 0, nullptr, nullptr, nullptr, 0);
        // ---- fused flash attention ----
        vt_convert_bf<<<dim3(32, 2, 64), 256>>>(qkvh + 1024, qkvl + 1024, QKVN, vthi, vtlo);
        flash_attn<<<dim3(8, 64), 256, FA_SMEM>>>(
            qkvh, qkvl, qkvh + 512, qkvl + 512, QKVN, vthi, vtlo, obh, obl);
        gemm_bb_kernel<<<dim3(DMODEL / 256, NTOK / 128), 512, GEMM_SMEM>>>(
            obh, obl, wbh + woo, wbl + woo, nullptr, tmp2, nullptr, nullptr,
            NTOK, DMODEL, DMODEL, 0, nullptr, nullptr, nullptr, 0);
        // ---- fused ln1 + cross-residual + ln2 ----
        ln2x_kernel<<<NTOK, 128>>>(dec, tmp2, ctx + (size_t)l * 512, 1024,
                                   ln1_s + l * DMODEL, ln1_b + l * DMODEL,
                                   ln2_s + l * DMODEL, ln2_b + l * DMODEL,
                                   dec, dech, decl);
        // ---- FFN ----
        gemm_bb_kernel<<<dim3(FFDIM / 256, NTOK / 128), 512, GEMM_SMEM>>>(
            dech, decl, wbh + w1o, wbl + w1o, b1 + (size_t)l * FFDIM,
            nullptr, ffh, ffl, NTOK, FFDIM, DMODEL, 1, nullptr, nullptr, nullptr, 0);
        gemm_bb_kernel<<<dim3(DMODEL / 256, NTOK / 128), 512, GEMM_SMEM>>>(
            ffh, ffl, wbh + w2o, wbl + w2o, b2 + (size_t)l * DMODEL,
            tmp2, nullptr, nullptr, NTOK, DMODEL, FFDIM, 0, nullptr, nullptr, nullptr, 0);
        ln_kernel<<<NTOK, 128>>>(dec, tmp2, DMODEL,
                                 ln3_s + l * DMODEL, ln3_b + l * DMODEL, dec, dech, decl);
    }

    // ---- final head ----
    ln_kernel<<<NTOK, 128>>>(dec, nullptr, 0, lnf_s, lnf_b, nullptr, obh, obl);
    gemm_bb_kernel<<<dim3(DMODEL / 256, NTOK / 128), 512, GEMM_SMEM>>>(
        obh, obl, wbh + OFF_WOUT, wbl + OFF_WOUT, bout, tmp2, nullptr, nullptr,
        NTOK, DMODEL, DMODEL, 0, nullptr, nullptr, nullptr, 0);
    softmax_keys_kernel<<<NTOK, 256>>>(tmp2, keysh, keysl);

    float* out_v  = out;
    float* out_s  = out + 262144;
    float* out_ss = out + 262144 + 8192;

    // ---- merged scoring head: [W_ss | W_vs], N = 16896, split epilogue ----
    gemm_bb_kernel<<<dim3(HEADN / 256, NTOK / 128), 512, GEMM_SMEM>>>(
        keysh, keysl, wbh + OFF_HEAD, wbl + OFF_HEAD, bcomb, vs, nullptr, nullptr,
        NTOK, HEADN, DMODEL, 0, x_in, best, out_ss, NSLOTS);
    gather_kernel<<<NTOK, 32>>>(best, vs, out_ss, out_v, out_s);
}